// round 11
// baseline (speedup 1.0000x reference)
#include <cuda_runtime.h>
#include <cstdint>

// ---------------- problem constants ----------------
#define B_    64
#define N_    482
#define DIM_  512
#define H_    8
#define D_    64
#define QKV_  1536
#define BH_   (B_*H_)          // 512
#define BN_   (B_*N_)          // 30848
#define SZ_BND (BN_*DIM_)      // 15794176
#define NHW_  256
#define NB_   225
#define TAIL0_ 257
#define SCALE_ 0.125f

// RNA-to-tf32 via integer add (HMMA truncates low 13 bits; +0x1000 = round-to-nearest).
#define RNA_ 0x1000u

// ---------------- device scratch ----------------
__device__ float g_qkv [(size_t)BN_*QKV_];
__device__ float g_qkvm[(size_t)BN_*QKV_];
__device__ float g_qq  [(size_t)BH_*N_*D_];   // biased bits
__device__ float g_kk  [(size_t)BH_*N_*D_];   // biased bits
__device__ float g_vv  [(size_t)BH_*N_*D_];   // biased bits
__device__ float g_vm  [(size_t)BH_*N_*D_];   // biased bits
__device__ float g_out [SZ_BND];
__device__ float g_m   [SZ_BND];
__device__ float g_out2[SZ_BND];              // biased bits
__device__ float g_m2  [SZ_BND];              // biased bits
__device__ float g_max [B_*H_*3*D_];
__device__ float g_upd [BN_];
__device__ float g_mm  [B_*(N_-1)];
// pre-biased input copies
__device__ float g_xb   [SZ_BND];
__device__ float g_mkb  [SZ_BND];
__device__ float g_wq_b [QKV_*DIM_];
__device__ float g_wq_ab[QKV_*DIM_];
__device__ float g_wo_b [DIM_*DIM_];
__device__ float g_wo_ab[DIM_*DIM_];

// ---------------- helpers ----------------
__device__ __forceinline__ void mma_tf32(float* c, const uint32_t* a, const uint32_t* b) {
    asm volatile("mma.sync.aligned.m16n8k8.row.col.f32.tf32.tf32.f32 "
        "{%0,%1,%2,%3}, {%4,%5,%6,%7}, {%8,%9}, {%0,%1,%2,%3};"
        : "+f"(c[0]), "+f"(c[1]), "+f"(c[2]), "+f"(c[3])
        : "r"(a[0]), "r"(a[1]), "r"(a[2]), "r"(a[3]), "r"(b[0]), "r"(b[1]));
}
__device__ __forceinline__ uint32_t smem_u32(const void* p) {
    return (uint32_t)__cvta_generic_to_shared(p);
}
__device__ __forceinline__ void cp16(uint32_t dst, const void* src, int sz) {
    asm volatile("cp.async.cg.shared.global [%0], [%1], 16, %2;" :: "r"(dst), "l"(src), "r"(sz));
}
#define CP_COMMIT() asm volatile("cp.async.commit_group;")
#define CP_WAIT(n)  asm volatile("cp.async.wait_group %0;" :: "n"(n))
__device__ __forceinline__ float biasf(float v) { return __uint_as_float(__float_as_uint(v) + RNA_); }

extern __shared__ uint32_t s_dyn[];

// ---------------- prep: biased (optionally abs) copy ----------------
template<bool ABS>
__global__ void bias_copy(const uint4* __restrict__ src, uint4* __restrict__ dst, int n4)
{
    int i = blockIdx.x * blockDim.x + threadIdx.x;
    if (i >= n4) return;
    uint4 v = src[i];
    if (ABS) { v.x &= 0x7fffffffu; v.y &= 0x7fffffffu; v.z &= 0x7fffffffu; v.w &= 0x7fffffffu; }
    v.x += RNA_; v.y += RNA_; v.z += RNA_; v.w += RNA_;
    dst[i] = v;
}

// ================= cp.async-pipelined tf32 NT GEMM, 128x128 tile =================
// Inputs are PRE-BIASED; inner loop is pure LDS + MMA.
#define GEMM_BUF (128*36)
template<bool BIAS>
__global__ void __launch_bounds__(256) mma_gemm(const float* __restrict__ A,
                                                const float* __restrict__ Bm,
                                                const float* __restrict__ bias,
                                                float* __restrict__ C,
                                                int K, int lda, int ldb, int ldc)
{
    float* AsB = (float*)s_dyn;
    float* BsB = (float*)s_dyn + 2 * GEMM_BUF;
    const int tid = threadIdx.x;
    const int bm = blockIdx.y * 128, bn = blockIdx.x * 128;
    const int lane = tid & 31, wid = tid >> 5;
    const int gr = lane >> 2, gc = lane & 3;
    const int wm = (wid & 1) * 64, wn = (wid >> 1) * 32;
    const int lr = tid >> 3, lc = (tid & 7) * 4;
    const float* Ap = A  + (size_t)(bm + lr) * lda + lc;
    const float* Bp = Bm + (size_t)(bn + lr) * ldb + lc;

    float acc[4][4][4];
    #pragma unroll
    for (int i = 0; i < 4; i++)
        #pragma unroll
        for (int j = 0; j < 4; j++)
            #pragma unroll
            for (int e = 0; e < 4; e++) acc[i][j][e] = 0.f;

    const int nslab = K >> 5;
    {
        float* As = AsB; float* Bs = BsB;
        #pragma unroll
        for (int r = 0; r < 4; r++) {
            cp16(smem_u32(&As[(lr + r*32) * 36 + lc]), Ap + (size_t)(r*32) * lda, 16);
            cp16(smem_u32(&Bs[(lr + r*32) * 36 + lc]), Bp + (size_t)(r*32) * ldb, 16);
        }
        CP_COMMIT();
    }

    for (int s = 0; s < nslab; s++) {
        if (s + 1 < nslab) {
            float* As = AsB + ((s+1) & 1) * GEMM_BUF;
            float* Bs = BsB + ((s+1) & 1) * GEMM_BUF;
            int kt = (s + 1) * 32;
            #pragma unroll
            for (int r = 0; r < 4; r++) {
                cp16(smem_u32(&As[(lr + r*32) * 36 + lc]), Ap + (size_t)(r*32) * lda + kt, 16);
                cp16(smem_u32(&Bs[(lr + r*32) * 36 + lc]), Bp + (size_t)(r*32) * ldb + kt, 16);
            }
            CP_COMMIT();
            CP_WAIT(1);
        } else {
            CP_WAIT(0);
        }
        __syncthreads();

        const uint32_t* As = (const uint32_t*)(AsB + (s & 1) * GEMM_BUF);
        const uint32_t* Bs = (const uint32_t*)(BsB + (s & 1) * GEMM_BUF);
        #pragma unroll
        for (int ks = 0; ks < 4; ks++) {
            const int k0 = ks * 8;
            uint32_t ah[4][4], bh[4][2];
            #pragma unroll
            for (int mt = 0; mt < 4; mt++) {
                int r0 = wm + mt * 16 + gr;
                ah[mt][0] = As[(r0    ) * 36 + k0 + gc    ];
                ah[mt][1] = As[(r0 + 8) * 36 + k0 + gc    ];
                ah[mt][2] = As[(r0    ) * 36 + k0 + gc + 4];
                ah[mt][3] = As[(r0 + 8) * 36 + k0 + gc + 4];
            }
            #pragma unroll
            for (int nt = 0; nt < 4; nt++) {
                int c0 = wn + nt * 8 + gr;
                bh[nt][0] = Bs[c0 * 36 + k0 + gc    ];
                bh[nt][1] = Bs[c0 * 36 + k0 + gc + 4];
            }
            #pragma unroll
            for (int mt = 0; mt < 4; mt++)
                #pragma unroll
                for (int nt = 0; nt < 4; nt++)
                    mma_tf32(acc[mt][nt], ah[mt], bh[nt]);
        }
        __syncthreads();
    }
    #pragma unroll
    for (int mt = 0; mt < 4; mt++)
        #pragma unroll
        for (int nt = 0; nt < 4; nt++) {
            int m0 = bm + wm + mt * 16 + gr;
            int n0 = bn + wn + nt * 8 + gc * 2;
            float bx = 0.f, by = 0.f;
            if (BIAS) { bx = bias[n0]; by = bias[n0 + 1]; }
            *(float2*)&C[(size_t)m0 * ldc + n0] = make_float2(acc[mt][nt][0] + bx, acc[mt][nt][1] + by);
            *(float2*)&C[(size_t)(m0 + 8) * ldc + n0] = make_float2(acc[mt][nt][2] + bx, acc[mt][nt][3] + by);
        }
}

// ================= cp.async-pipelined flash attention (pre-biased inputs) =========
#define KT_SZ   (64*68)
#define V_SZ    (64*72)
#define V1_BASE (2*KT_SZ)
#define V2_BASE (V1_BASE + 2*V_SZ)
#define PQ_OFF  (V2_BASE + 2*V_SZ)
#define FA_SMEM_WORDS (PQ_OFF + 128*68)

__global__ void __launch_bounds__(256, 1) flash_attn()
{
    const int bh = blockIdx.y;
    const int b = bh >> 3, h = bh & 7;
    const int i0 = blockIdx.x * 128;
    const float* Q  = g_qq + (size_t)bh * N_ * D_;
    const float* Kp = g_kk + (size_t)bh * N_ * D_;
    const float* Vv = g_vv + (size_t)bh * N_ * D_;
    const float* Vm = g_vm + (size_t)bh * N_ * D_;
    uint32_t* PQ = s_dyn + PQ_OFF;

    const int tid = threadIdx.x;
    const int lane = tid & 31, wid = tid >> 5;
    const int gr = lane >> 2, gc = lane & 3;
    const int rbase = wid * 16;
    const int lc4 = (tid & 15) * 4, lrr = tid >> 4;

    {   // stage Q (bit-preserving copy of biased data)
        uint32_t* Qst = PQ;
        #pragma unroll
        for (int e = 0; e < 8; e++) {
            int row = lrr + e * 16, gi = i0 + row;
            uint4 q = make_uint4(0u,0u,0u,0u);
            if (gi < N_) q = *(const uint4*)(Q + (size_t)gi * D_ + lc4);
            *(uint4*)&Qst[row * 68 + lc4] = q;
        }
    }
    __syncthreads();
    uint32_t qf[8][4];
    #pragma unroll
    for (int kc = 0; kc < 8; kc++) {
        qf[kc][0] = PQ[(rbase + gr    ) * 68 + kc*8 + gc    ];
        qf[kc][1] = PQ[(rbase + gr + 8) * 68 + kc*8 + gc    ];
        qf[kc][2] = PQ[(rbase + gr    ) * 68 + kc*8 + gc + 4];
        qf[kc][3] = PQ[(rbase + gr + 8) * 68 + kc*8 + gc + 4];
    }
    __syncthreads();

    float acc1[8][4], acc2[8][4];
    #pragma unroll
    for (int nt = 0; nt < 8; nt++)
        #pragma unroll
        for (int e = 0; e < 4; e++) { acc1[nt][e] = 0.f; acc2[nt][e] = 0.f; }
    float rmax0 = -1e30f, rmax1 = -1e30f, rsum0 = 0.f, rsum1 = 0.f;

    const int ntiles = (N_ + 63) / 64;
    {
        uint32_t* Kt = s_dyn;
        uint32_t* V1 = s_dyn + V1_BASE;
        uint32_t* V2 = s_dyn + V2_BASE;
        #pragma unroll
        for (int e = 0; e < 4; e++) {
            int row = lrr + e * 16, j = row;
            int ok = (j < N_);
            size_t off = (size_t)(ok ? j : 0) * D_ + lc4;
            int sz = ok ? 16 : 0;
            cp16(smem_u32(&Kt[row * 68 + lc4]), Kp + off, sz);
            cp16(smem_u32(&V1[row * 72 + lc4]), Vv + off, sz);
            cp16(smem_u32(&V2[row * 72 + lc4]), Vm + off, sz);
        }
        CP_COMMIT();
    }

    for (int t = 0; t < ntiles; t++) {
        const int j0 = t * 64;
        if (t + 1 < ntiles) {
            uint32_t* Kt = s_dyn + ((t+1) & 1) * KT_SZ;
            uint32_t* V1 = s_dyn + V1_BASE + ((t+1) & 1) * V_SZ;
            uint32_t* V2 = s_dyn + V2_BASE + ((t+1) & 1) * V_SZ;
            int j0n = j0 + 64;
            #pragma unroll
            for (int e = 0; e < 4; e++) {
                int row = lrr + e * 16, j = j0n + row;
                int ok = (j < N_);
                size_t off = (size_t)(ok ? j : 0) * D_ + lc4;
                int sz = ok ? 16 : 0;
                cp16(smem_u32(&Kt[row * 68 + lc4]), Kp + off, sz);
                cp16(smem_u32(&V1[row * 72 + lc4]), Vv + off, sz);
                cp16(smem_u32(&V2[row * 72 + lc4]), Vm + off, sz);
            }
            CP_COMMIT();
            CP_WAIT(1);
        } else {
            CP_WAIT(0);
        }
        __syncthreads();

        const uint32_t* Kt = s_dyn + (t & 1) * KT_SZ;
        const uint32_t* V1 = s_dyn + V1_BASE + (t & 1) * V_SZ;
        const uint32_t* V2 = s_dyn + V2_BASE + (t & 1) * V_SZ;

        float sacc[8][4];
        #pragma unroll
        for (int nt = 0; nt < 8; nt++)
            #pragma unroll
            for (int e = 0; e < 4; e++) sacc[nt][e] = 0.f;
        #pragma unroll
        for (int nt = 0; nt < 8; nt++) {
            #pragma unroll
            for (int kc = 0; kc < 8; kc++) {
                uint32_t bf[2];
                bf[0] = Kt[(nt*8 + gr) * 68 + kc*8 + gc    ];
                bf[1] = Kt[(nt*8 + gr) * 68 + kc*8 + gc + 4];
                mma_tf32(sacc[nt], qf[kc], bf);
            }
        }
        if (j0 + 64 > N_) {
            #pragma unroll
            for (int nt = 0; nt < 8; nt++) {
                int cc = j0 + nt*8 + gc*2;
                if (cc     >= N_) { sacc[nt][0] = -1e30f; sacc[nt][2] = -1e30f; }
                if (cc + 1 >= N_) { sacc[nt][1] = -1e30f; sacc[nt][3] = -1e30f; }
            }
        }
        float tm0 = -1e30f, tm1 = -1e30f;
        #pragma unroll
        for (int nt = 0; nt < 8; nt++) {
            tm0 = fmaxf(tm0, fmaxf(sacc[nt][0], sacc[nt][1]));
            tm1 = fmaxf(tm1, fmaxf(sacc[nt][2], sacc[nt][3]));
        }
        tm0 = fmaxf(tm0, __shfl_xor_sync(0xffffffffu, tm0, 1));
        tm0 = fmaxf(tm0, __shfl_xor_sync(0xffffffffu, tm0, 2));
        tm1 = fmaxf(tm1, __shfl_xor_sync(0xffffffffu, tm1, 1));
        tm1 = fmaxf(tm1, __shfl_xor_sync(0xffffffffu, tm1, 2));
        float nm0 = fmaxf(rmax0, tm0), nm1 = fmaxf(rmax1, tm1);
        float sc0 = __expf(rmax0 - nm0), sc1 = __expf(rmax1 - nm1);
        rmax0 = nm0; rmax1 = nm1;
        float ps0 = 0.f, ps1 = 0.f;
        #pragma unroll
        for (int nt = 0; nt < 8; nt++) {
            float p00 = __expf(sacc[nt][0] - nm0);
            float p01 = __expf(sacc[nt][1] - nm0);
            float p10 = __expf(sacc[nt][2] - nm1);
            float p11 = __expf(sacc[nt][3] - nm1);
            ps0 += p00 + p01; ps1 += p10 + p11;
            // store PRE-BIASED p-values
            *(uint2*)&PQ[(rbase + gr    ) * 68 + nt*8 + gc*2] =
                make_uint2(__float_as_uint(p00) + RNA_, __float_as_uint(p01) + RNA_);
            *(uint2*)&PQ[(rbase + gr + 8) * 68 + nt*8 + gc*2] =
                make_uint2(__float_as_uint(p10) + RNA_, __float_as_uint(p11) + RNA_);
            acc1[nt][0] *= sc0; acc1[nt][1] *= sc0; acc1[nt][2] *= sc1; acc1[nt][3] *= sc1;
            acc2[nt][0] *= sc0; acc2[nt][1] *= sc0; acc2[nt][2] *= sc1; acc2[nt][3] *= sc1;
        }
        ps0 += __shfl_xor_sync(0xffffffffu, ps0, 1);
        ps0 += __shfl_xor_sync(0xffffffffu, ps0, 2);
        ps1 += __shfl_xor_sync(0xffffffffu, ps1, 1);
        ps1 += __shfl_xor_sync(0xffffffffu, ps1, 2);
        rsum0 = rsum0 * sc0 + ps0;
        rsum1 = rsum1 * sc1 + ps1;
        __syncwarp();

        #pragma unroll
        for (int kc = 0; kc < 8; kc++) {
            uint32_t af[4];
            af[0] = PQ[(rbase + gr    ) * 68 + kc*8 + gc    ];
            af[1] = PQ[(rbase + gr + 8) * 68 + kc*8 + gc    ];
            af[2] = PQ[(rbase + gr    ) * 68 + kc*8 + gc + 4];
            af[3] = PQ[(rbase + gr + 8) * 68 + kc*8 + gc + 4];
            #pragma unroll
            for (int nt = 0; nt < 8; nt++) {
                uint32_t bv1[2], bv2[2];
                bv1[0] = V1[(kc*8 + gc    ) * 72 + nt*8 + gr];
                bv1[1] = V1[(kc*8 + gc + 4) * 72 + nt*8 + gr];
                bv2[0] = V2[(kc*8 + gc    ) * 72 + nt*8 + gr];
                bv2[1] = V2[(kc*8 + gc + 4) * 72 + nt*8 + gr];
                mma_tf32(acc1[nt], af, bv1);
                mma_tf32(acc2[nt], af, bv2);
            }
        }
        __syncthreads();
    }

    float inv0 = 1.0f / rsum0, inv1 = 1.0f / rsum1;
    int gi0 = i0 + rbase + gr, gi1 = gi0 + 8;
    if (gi0 < N_) {
        float f = inv0 * g_upd[b * N_ + gi0];
        size_t base = (size_t)(b * N_ + gi0) * DIM_ + h * 64;
        #pragma unroll
        for (int nt = 0; nt < 8; nt++) {
            int d = nt*8 + gc*2;
            *(float2*)&g_out[base + d] = make_float2(acc1[nt][0]*f, acc1[nt][1]*f);
            *(float2*)&g_m  [base + d] = make_float2(acc2[nt][0]*f, acc2[nt][1]*f);
        }
    }
    if (gi1 < N_) {
        float f = inv1 * g_upd[b * N_ + gi1];
        size_t base = (size_t)(b * N_ + gi1) * DIM_ + h * 64;
        #pragma unroll
        for (int nt = 0; nt < 8; nt++) {
            int d = nt*8 + gc*2;
            *(float2*)&g_out[base + d] = make_float2(acc1[nt][2]*f, acc1[nt][3]*f);
            *(float2*)&g_m  [base + d] = make_float2(acc2[nt][2]*f, acc2[nt][3]*f);
        }
    }
}

// ---------------- updated[b,i] ----------------
__global__ void updated_k(const float* __restrict__ mask)
{
    int row = blockIdx.x * (blockDim.x >> 5) + (threadIdx.x >> 5);
    if (row >= BN_) return;
    int ln = threadIdx.x & 31;
    const float* p = mask + (size_t)row * DIM_;
    float s = 0.f;
    #pragma unroll
    for (int e = ln; e < DIM_; e += 32) s += p[e];
    #pragma unroll
    for (int o = 16; o > 0; o >>= 1) s += __shfl_xor_sync(0xffffffffu, s, o);
    if (ln == 0) {
        int i = row % N_;
        g_upd[row] = (i == 0) ? 1.0f : (s > 0.0f ? 1.0f : 0.0f);
    }
}

// ---------------- per-(b,h,w,d) max over sequence ----------------
__global__ void reduce_max_k()
{
    int o = blockIdx.x * blockDim.x + threadIdx.x;
    if (o >= B_*H_*3*D_) return;
    int d = o & 63;
    int w = (o >> 6) % 3;
    int h = ((o >> 6) / 3) % H_;
    int b = (o >> 6) / 24;
    const float* p = g_qkvm + (size_t)b * N_ * QKV_ + w * DIM_ + h * 64 + d;
    float mx = -1e30f;
    for (int i = 0; i < N_; i++) mx = fmaxf(mx, p[(size_t)i * QKV_]);
    g_max[o] = mx;
}

// ---------------- modulated q,k,v (writes PRE-BIASED bits) ----------------
__global__ void modulate_k()
{
    int idx = blockIdx.x * blockDim.x + threadIdx.x;
    if (idx >= SZ_BND) return;
    int hd = idx % DIM_;
    int i  = (idx / DIM_) % N_;
    int b  = idx / (DIM_ * N_);
    int h = hd >> 6, d = hd & 63;
    size_t base = (size_t)(b * N_ + i) * QKV_;
    float q  = g_qkv [base + hd];
    float k  = g_qkv [base + DIM_ + hd];
    float v  = g_qkv [base + 2*DIM_ + hd];
    float qm = g_qkvm[base + hd];
    float km = g_qkvm[base + DIM_ + hd];
    float vm = g_qkvm[base + 2*DIM_ + hd];
    int mb = ((b * H_ + h) * 3) * 64 + d;
    float qmn = qm / (1e-6f + g_max[mb]);
    float kmn = km / (1e-6f + g_max[mb + 64]);
    float vmn = vm / (1e-6f + g_max[mb + 128]);
    size_t o = ((size_t)(b * H_ + h) * N_ + i) * D_ + d;
    g_qq[o] = biasf(q * qmn * SCALE_);
    g_kk[o] = biasf(k * kmn);
    g_vv[o] = biasf(v * vmn);
    g_vm[o] = biasf(vmn);
}

// ---------------- fused blend + channel-mean; writes PRE-BIASED out2/m2 ----------
__global__ void __launch_bounds__(128) blend_mm_k()
{
    const int row = blockIdx.x;           // b*N_ + i
    const int b = row / N_, i = row % N_;
    const int tid = threadIdx.x;
    const int c = tid * 4;
    size_t idx = (size_t)row * DIM_ + c;
    float4 o  = *(const float4*)&g_out[idx];
    float4 mv = *(const float4*)&g_m[idx];

    if (i >= 1 && i <= NHW_) {
        int p = i - 1, y = p >> 4, x = p & 15;
        float inv = 0.25f * (1.0f - g_upd[row]);
        float4 s1 = make_float4(0,0,0,0), s2 = make_float4(0,0,0,0);
        #pragma unroll
        for (int dy = -1; dy <= 0; dy++)
            #pragma unroll
            for (int dx = -1; dx <= 0; dx++) {
                int r = y + dy, cc = x + dx;
                if (r >= 0 && r < 15 && cc >= 0 && cc < 15) {
                    size_t src = ((size_t)(b * N_ + TAIL0_ + r * 15 + cc)) * DIM_ + c;
                    float4 a = *(const float4*)&g_out[src];
                    float4 e = *(const float4*)&g_m[src];
                    s1.x += a.x; s1.y += a.y; s1.z += a.z; s1.w += a.w;
                    s2.x += e.x; s2.y += e.y; s2.z += e.z; s2.w += e.w;
                }
            }
        o.x += s1.x*inv; o.y += s1.y*inv; o.z += s1.z*inv; o.w += s1.w*inv;
        mv.x += s2.x*inv; mv.y += s2.y*inv; mv.z += s2.z*inv; mv.w += s2.w*inv;
    } else if (i >= TAIL0_) {
        int p = i - TAIL0_, r = p / 15, cc = p % 15;
        float inv = 0.25f * (1.0f - g_upd[row]);
        float4 s1 = make_float4(0,0,0,0), s2 = make_float4(0,0,0,0);
        #pragma unroll
        for (int dy = 0; dy <= 1; dy++)
            #pragma unroll
            for (int dx = 0; dx <= 1; dx++) {
                size_t src = ((size_t)(b * N_ + 1 + (r + dy) * 16 + (cc + dx))) * DIM_ + c;
                float4 a = *(const float4*)&g_out[src];
                float4 e = *(const float4*)&g_m[src];
                s1.x += a.x; s1.y += a.y; s1.z += a.z; s1.w += a.w;
                s2.x += e.x; s2.y += e.y; s2.z += e.z; s2.w += e.w;
            }
        o.x += s1.x*inv; o.y += s1.y*inv; o.z += s1.z*inv; o.w += s1.w*inv;
        mv.x += s2.x*inv; mv.y += s2.y*inv; mv.z += s2.z*inv; mv.w += s2.w*inv;
    }

    // channel-sum of true mv for mm (before biasing)
    float s = mv.x + mv.y + mv.z + mv.w;
    #pragma unroll
    for (int off = 16; off > 0; off >>= 1) s += __shfl_xor_sync(0xffffffffu, s, off);
    __shared__ float ssum[4];
    if ((tid & 31) == 0) ssum[tid >> 5] = s;
    __syncthreads();
    if (tid == 0 && i >= 1)
        g_mm[b * (N_ - 1) + i - 1] = (ssum[0] + ssum[1] + ssum[2] + ssum[3]) * (1.0f / DIM_);

    // write biased bits for the final tf32 GEMMs
    uint4 ob, mb;
    ob.x = __float_as_uint(o.x)+RNA_; ob.y = __float_as_uint(o.y)+RNA_;
    ob.z = __float_as_uint(o.z)+RNA_; ob.w = __float_as_uint(o.w)+RNA_;
    mb.x = __float_as_uint(mv.x)+RNA_; mb.y = __float_as_uint(mv.y)+RNA_;
    mb.z = __float_as_uint(mv.z)+RNA_; mb.w = __float_as_uint(mv.w)+RNA_;
    *(uint4*)&g_out2[idx] = ob;
    *(uint4*)&g_m2[idx]   = mb;
}

// ---------------- inter ----------------
__global__ void inter_k(float* __restrict__ outp)
{
    int idx = blockIdx.x * blockDim.x + threadIdx.x;
    if (idx >= B_ * 256 * 256) return;
    int x = idx & 255, y = (idx >> 8) & 255, b = idx >> 16;
    float v = g_mm[b * (N_ - 1) + (y >> 4) * 16 + (x >> 4)];
    if (y >= 8 && y < 248 && x >= 8 && x < 248) {
        float sh = g_mm[b * (N_ - 1) + 256 + ((y - 8) >> 4) * 15 + ((x - 8) >> 4)];
        v = 0.5f * (v + sh);
    }
    outp[idx] = v;
}

// ---------------- launch ----------------
extern "C" void kernel_launch(void* const* d_in, const int* in_sizes, int n_in,
                              void* d_out, int out_size)
{
    const float* x    = (const float*)d_in[0];
    const float* mask = (const float*)d_in[1];
    const float* Wqkv = (const float*)d_in[2];
    const float* Wout = (const float*)d_in[3];
    const float* bout = (const float*)d_in[4];
    float* out = (float*)d_out;

    float *p_qkv, *p_qkvm, *p_out2, *p_m2, *p_xb, *p_mkb, *p_wqb, *p_wqab, *p_wob, *p_woab;
    cudaGetSymbolAddress((void**)&p_qkv,  g_qkv);
    cudaGetSymbolAddress((void**)&p_qkvm, g_qkvm);
    cudaGetSymbolAddress((void**)&p_out2, g_out2);
    cudaGetSymbolAddress((void**)&p_m2,   g_m2);
    cudaGetSymbolAddress((void**)&p_xb,   g_xb);
    cudaGetSymbolAddress((void**)&p_mkb,  g_mkb);
    cudaGetSymbolAddress((void**)&p_wqb,  g_wq_b);
    cudaGetSymbolAddress((void**)&p_wqab, g_wq_ab);
    cudaGetSymbolAddress((void**)&p_wob,  g_wo_b);
    cudaGetSymbolAddress((void**)&p_woab, g_wo_ab);

    const int gemm_smem = 2 * 2 * GEMM_BUF * 4;   // 73728 B
    cudaFuncSetAttribute(mma_gemm<false>, cudaFuncAttributeMaxDynamicSharedMemorySize, gemm_smem);
    cudaFuncSetAttribute(mma_gemm<true >, cudaFuncAttributeMaxDynamicSharedMemorySize, gemm_smem);
    cudaFuncSetAttribute(flash_attn, cudaFuncAttributeMaxDynamicSharedMemorySize, FA_SMEM_WORDS * 4);

    // 0. biased copies (inputs -> scratch)
    bias_copy<false><<<(SZ_BND/4 + 255)/256, 256>>>((const uint4*)x,    (uint4*)p_xb,   SZ_BND/4);
    bias_copy<false><<<(SZ_BND/4 + 255)/256, 256>>>((const uint4*)mask, (uint4*)p_mkb,  SZ_BND/4);
    bias_copy<false><<<(QKV_*DIM_/4 + 255)/256, 256>>>((const uint4*)Wqkv, (uint4*)p_wqb,  QKV_*DIM_/4);
    bias_copy<true ><<<(QKV_*DIM_/4 + 255)/256, 256>>>((const uint4*)Wqkv, (uint4*)p_wqab, QKV_*DIM_/4);
    bias_copy<false><<<(DIM_*DIM_/4 + 255)/256, 256>>>((const uint4*)Wout, (uint4*)p_wob,  DIM_*DIM_/4);
    bias_copy<true ><<<(DIM_*DIM_/4 + 255)/256, 256>>>((const uint4*)Wout, (uint4*)p_woab, DIM_*DIM_/4);

    // 1-2. qkv / qkv_m projections (pre-biased operands)
    mma_gemm<false><<<dim3(QKV_/128, BN_/128), 256, gemm_smem>>>(p_xb,  p_wqb,  nullptr, p_qkv,  DIM_, DIM_, DIM_, QKV_);
    mma_gemm<false><<<dim3(QKV_/128, BN_/128), 256, gemm_smem>>>(p_mkb, p_wqab, nullptr, p_qkvm, DIM_, DIM_, DIM_, QKV_);
    // 3. updated flags
    updated_k<<<(BN_ + 7) / 8, 256>>>(mask);
    // 4. maxima
    reduce_max_k<<<(B_*H_*3*D_ + 255) / 256, 256>>>();
    // 5. modulate (emits biased bits)
    modulate_k<<<(SZ_BND + 255) / 256, 256>>>();
    // 6-8. fused attention
    flash_attn<<<dim3(4, BH_), 256, FA_SMEM_WORDS * 4>>>();
    // 9-10. fused blend + channel means (emits biased out2/m2)
    blend_mm_k<<<BN_, 128>>>();
    // 11. inter
    inter_k<<<(B_ * 65536 + 255) / 256, 256>>>(out + 2 * (size_t)SZ_BND);
    // 12-13. final projections
    mma_gemm<true ><<<dim3(DIM_/128, BN_/128), 256, gemm_smem>>>(p_out2, p_wob,  bout,    out,                  DIM_, DIM_, DIM_, DIM_);
    mma_gemm<false><<<dim3(DIM_/128, BN_/128), 256, gemm_smem>>>(p_m2,   p_woab, nullptr, out + (size_t)SZ_BND, DIM_, DIM_, DIM_, DIM_);
}

// round 13
// speedup vs baseline: 2.0542x; 2.0542x over previous
#include <cuda_runtime.h>
#include <cuda_fp16.h>
#include <cstdint>

// ---------------- problem constants ----------------
#define B_    64
#define N_    482
#define DIM_  512
#define H_    8
#define D_    64
#define QKV_  1536
#define BH_   (B_*H_)          // 512
#define BN_   (B_*N_)          // 30848
#define SZ_BND (BN_*DIM_)      // 15794176
#define NHW_  256
#define NB_   225
#define TAIL0_ 257
#define SCALE_ 0.125f

// ---------------- device scratch ----------------
__device__ float  g_qkv [(size_t)BN_*QKV_];
__device__ float  g_qkvm[(size_t)BN_*QKV_];
__device__ float  g_out [SZ_BND];
__device__ float  g_m   [SZ_BND];
__device__ float  g_m2  [SZ_BND];
__device__ float  g_max [B_*H_*3*D_];
__device__ float  g_upd [BN_];
__device__ float  g_mm  [B_*(N_-1)];
// fp16 operands
__device__ __half g_xh  [SZ_BND];
__device__ __half g_mkh [SZ_BND];
__device__ __half g_wqh [QKV_*DIM_];
__device__ __half g_wqah[QKV_*DIM_];
__device__ __half g_woh [DIM_*DIM_];
__device__ __half g_woah[DIM_*DIM_];
__device__ __half g_qh  [(size_t)BH_*N_*D_];
__device__ __half g_kh  [(size_t)BH_*N_*D_];
__device__ __half g_vvT [(size_t)BH_*64*512];   // [bh][d][j], zero-padded cols
__device__ __half g_vmT [(size_t)BH_*64*512];
__device__ __half g_o2h [SZ_BND];
__device__ __half g_m2h [SZ_BND];

// ---------------- helpers ----------------
__device__ __forceinline__ void mma_f16(float* c, const uint32_t* a, const uint32_t* b) {
    asm volatile("mma.sync.aligned.m16n8k16.row.col.f32.f16.f16.f32 "
        "{%0,%1,%2,%3}, {%4,%5,%6,%7}, {%8,%9}, {%0,%1,%2,%3};"
        : "+f"(c[0]), "+f"(c[1]), "+f"(c[2]), "+f"(c[3])
        : "r"(a[0]), "r"(a[1]), "r"(a[2]), "r"(a[3]), "r"(b[0]), "r"(b[1]));
}
__device__ __forceinline__ uint32_t smem_u32(const void* p) {
    return (uint32_t)__cvta_generic_to_shared(p);
}
__device__ __forceinline__ void cp16(uint32_t dst, const void* src, int sz) {
    asm volatile("cp.async.cg.shared.global [%0], [%1], 16, %2;" :: "r"(dst), "l"(src), "r"(sz));
}
#define CP_COMMIT() asm volatile("cp.async.commit_group;")
#define CP_WAIT(n)  asm volatile("cp.async.wait_group %0;" :: "n"(n))

extern __shared__ uint32_t s_dyn[];

// ---------------- prep: f32 -> f16 copy (optionally |.|) ----------------
template<bool ABS>
__global__ void half_copy(const float4* __restrict__ src, uint2* __restrict__ dst, int n4)
{
    int i = blockIdx.x * blockDim.x + threadIdx.x;
    if (i >= n4) return;
    float4 v = src[i];
    if (ABS) { v.x = fabsf(v.x); v.y = fabsf(v.y); v.z = fabsf(v.z); v.w = fabsf(v.w); }
    __half2 lo = __floats2half2_rn(v.x, v.y);
    __half2 hi = __floats2half2_rn(v.z, v.w);
    uint2 r;
    r.x = *(uint32_t*)&lo; r.y = *(uint32_t*)&hi;
    dst[i] = r;
}

// ================= fp16 NT GEMM (m16n8k16), 128x128 tile, cp.async pipelined =====
// C[m,n] = sum_k A[m*lda+k]*B[n*ldb+k] (+bias[n]); M,N mult of 128, K of 32.
#define GBUF_W 2560   // words per tile buffer: 128 rows * 20 words (40 halfs)
template<bool BIAS>
__global__ void __launch_bounds__(256) hgemm(const __half* __restrict__ A,
                                             const __half* __restrict__ Bm,
                                             const float* __restrict__ bias,
                                             float* __restrict__ C,
                                             int K, int lda, int ldb, int ldc)
{
    uint32_t* AsB = s_dyn;               // [2][2560]
    uint32_t* BsB = s_dyn + 2 * GBUF_W;  // [2][2560]
    const int tid = threadIdx.x;
    const int bm = blockIdx.y * 128, bn = blockIdx.x * 128;
    const int lane = tid & 31, wid = tid >> 5;
    const int gr = lane >> 2, gc = lane & 3;
    const int wm = (wid & 1) * 64, wn = (wid >> 1) * 32;

    float acc[4][4][4];
    #pragma unroll
    for (int i = 0; i < 4; i++)
        #pragma unroll
        for (int j = 0; j < 4; j++)
            #pragma unroll
            for (int e = 0; e < 4; e++) acc[i][j][e] = 0.f;

    const int nslab = K >> 5;
    // slab staging: 128 rows * 32 halfs(64B) = 512 chunks of 16B per matrix; 2/thread
    const int r0s = tid >> 2, s0s = tid & 3;
    const int r1s = 64 + (tid >> 2), s1s = tid & 3;
    {
        cp16(smem_u32(&AsB[r0s*20 + s0s*4]), A + (size_t)(bm + r0s) * lda + s0s*8, 16);
        cp16(smem_u32(&AsB[r1s*20 + s1s*4]), A + (size_t)(bm + r1s) * lda + s1s*8, 16);
        cp16(smem_u32(&BsB[r0s*20 + s0s*4]), Bm + (size_t)(bn + r0s) * ldb + s0s*8, 16);
        cp16(smem_u32(&BsB[r1s*20 + s1s*4]), Bm + (size_t)(bn + r1s) * ldb + s1s*8, 16);
        CP_COMMIT();
    }
    for (int s = 0; s < nslab; s++) {
        if (s + 1 < nslab) {
            uint32_t* As = AsB + ((s+1) & 1) * GBUF_W;
            uint32_t* Bs = BsB + ((s+1) & 1) * GBUF_W;
            int kt = (s + 1) * 32;
            cp16(smem_u32(&As[r0s*20 + s0s*4]), A + (size_t)(bm + r0s) * lda + kt + s0s*8, 16);
            cp16(smem_u32(&As[r1s*20 + s1s*4]), A + (size_t)(bm + r1s) * lda + kt + s1s*8, 16);
            cp16(smem_u32(&Bs[r0s*20 + s0s*4]), Bm + (size_t)(bn + r0s) * ldb + kt + s0s*8, 16);
            cp16(smem_u32(&Bs[r1s*20 + s1s*4]), Bm + (size_t)(bn + r1s) * ldb + kt + s1s*8, 16);
            CP_COMMIT();
            CP_WAIT(1);
        } else {
            CP_WAIT(0);
        }
        __syncthreads();

        const uint32_t* As = AsB + (s & 1) * GBUF_W;
        const uint32_t* Bs = BsB + (s & 1) * GBUF_W;
        #pragma unroll
        for (int ks = 0; ks < 2; ks++) {          // two k16 steps per 32-k slab
            const int kw = ks * 8;
            uint32_t ah[4][4], bh[4][2];
            #pragma unroll
            for (int mt = 0; mt < 4; mt++) {
                int r0 = wm + mt * 16 + gr;
                ah[mt][0] = As[(r0    ) * 20 + kw + gc    ];
                ah[mt][1] = As[(r0 + 8) * 20 + kw + gc    ];
                ah[mt][2] = As[(r0    ) * 20 + kw + gc + 4];
                ah[mt][3] = As[(r0 + 8) * 20 + kw + gc + 4];
            }
            #pragma unroll
            for (int nt = 0; nt < 4; nt++) {
                int c0 = wn + nt * 8 + gr;
                bh[nt][0] = Bs[c0 * 20 + kw + gc    ];
                bh[nt][1] = Bs[c0 * 20 + kw + gc + 4];
            }
            #pragma unroll
            for (int mt = 0; mt < 4; mt++)
                #pragma unroll
                for (int nt = 0; nt < 4; nt++)
                    mma_f16(acc[mt][nt], ah[mt], bh[nt]);
        }
        __syncthreads();
    }
    #pragma unroll
    for (int mt = 0; mt < 4; mt++)
        #pragma unroll
        for (int nt = 0; nt < 4; nt++) {
            int m0 = bm + wm + mt * 16 + gr;
            int n0 = bn + wn + nt * 8 + gc * 2;
            float bx = 0.f, by = 0.f;
            if (BIAS) { bx = bias[n0]; by = bias[n0 + 1]; }
            *(float2*)&C[(size_t)m0 * ldc + n0] = make_float2(acc[mt][nt][0] + bx, acc[mt][nt][1] + by);
            *(float2*)&C[(size_t)(m0 + 8) * ldc + n0] = make_float2(acc[mt][nt][2] + bx, acc[mt][nt][3] + by);
        }
}

// ================= fp16 flash attention =================
// smem (words): Kt[2][2304] | V1t[2][2304] | V2t[2][2304] | PQ[128*36]
#define KT_W    2304     // 64 rows * 36 words (72 halfs)
#define V1_OFF  (2*KT_W)
#define V2_OFF  (4*KT_W)
#define PQ_OFF  (6*KT_W)
#define FA_SMEM_WORDS (PQ_OFF + 128*36)

__global__ void __launch_bounds__(256, 1) flash_attn()
{
    const int bh = blockIdx.y;
    const int b = bh >> 3, h = bh & 7;
    const int i0 = blockIdx.x * 128;
    const __half* Q   = g_qh  + (size_t)bh * N_ * D_;
    const __half* Kp  = g_kh  + (size_t)bh * N_ * D_;
    const __half* V1g = g_vvT + (size_t)bh * 64 * 512;
    const __half* V2g = g_vmT + (size_t)bh * 64 * 512;
    uint32_t* PQ = s_dyn + PQ_OFF;

    const int tid = threadIdx.x;
    const int lane = tid & 31, wid = tid >> 5;
    const int gr = lane >> 2, gc = lane & 3;
    const int rbase = wid * 16;

    // ---- stage Q into PQ (fp16): 128 rows * 64 halfs = 1024 chunks of 16B ----
    {
        #pragma unroll
        for (int e = 0; e < 4; e++) {
            int chunk = tid + e * 256;
            int row = chunk >> 3, seg = chunk & 7;
            int gi = i0 + row;
            uint4 q = make_uint4(0u,0u,0u,0u);
            if (gi < N_) q = *(const uint4*)(Q + (size_t)gi * D_ + seg * 8);
            *(uint4*)&PQ[row * 36 + seg * 4] = q;
        }
    }
    __syncthreads();
    uint32_t qf[4][4];
    #pragma unroll
    for (int ks = 0; ks < 4; ks++) {
        qf[ks][0] = PQ[(rbase + gr    ) * 36 + ks*8 + gc    ];
        qf[ks][1] = PQ[(rbase + gr + 8) * 36 + ks*8 + gc    ];
        qf[ks][2] = PQ[(rbase + gr    ) * 36 + ks*8 + gc + 4];
        qf[ks][3] = PQ[(rbase + gr + 8) * 36 + ks*8 + gc + 4];
    }
    __syncthreads();

    float acc1[8][4], acc2[8][4];
    #pragma unroll
    for (int nt = 0; nt < 8; nt++)
        #pragma unroll
        for (int e = 0; e < 4; e++) { acc1[nt][e] = 0.f; acc2[nt][e] = 0.f; }
    float rmax0 = -1e30f, rmax1 = -1e30f, rsum0 = 0.f, rsum1 = 0.f;

    const int ntiles = (N_ + 63) / 64;   // 8
    // tile staging: 64 rows * 64 halfs = 512 chunks of 16B per tensor; 2/thread
    {
        #pragma unroll
        for (int e = 0; e < 2; e++) {
            int chunk = tid + e * 256;
            int row = chunk >> 3, seg = chunk & 7;
            int j = row;
            int sz = (j < N_) ? 16 : 0;
            cp16(smem_u32(&s_dyn[row*36 + seg*4]), Kp + (size_t)(sz ? j : 0) * D_ + seg*8, sz);
            cp16(smem_u32(&s_dyn[V1_OFF + row*36 + seg*4]), V1g + (size_t)row * 512 + seg*8, 16);
            cp16(smem_u32(&s_dyn[V2_OFF + row*36 + seg*4]), V2g + (size_t)row * 512 + seg*8, 16);
        }
        CP_COMMIT();
    }

    for (int t = 0; t < ntiles; t++) {
        const int j0 = t * 64;
        if (t + 1 < ntiles) {
            int buf = (t + 1) & 1;
            int jb = j0 + 64;
            #pragma unroll
            for (int e = 0; e < 2; e++) {
                int chunk = tid + e * 256;
                int row = chunk >> 3, seg = chunk & 7;
                int j = jb + row;
                int sz = (j < N_) ? 16 : 0;
                cp16(smem_u32(&s_dyn[buf*KT_W + row*36 + seg*4]), Kp + (size_t)(sz ? j : 0) * D_ + seg*8, sz);
                cp16(smem_u32(&s_dyn[V1_OFF + buf*KT_W + row*36 + seg*4]), V1g + (size_t)row * 512 + jb + seg*8, 16);
                cp16(smem_u32(&s_dyn[V2_OFF + buf*KT_W + row*36 + seg*4]), V2g + (size_t)row * 512 + jb + seg*8, 16);
            }
            CP_COMMIT();
            CP_WAIT(1);
        } else {
            CP_WAIT(0);
        }
        __syncthreads();

        const uint32_t* Kt = s_dyn + (t & 1) * KT_W;
        const uint32_t* V1 = s_dyn + V1_OFF + (t & 1) * KT_W;
        const uint32_t* V2 = s_dyn + V2_OFF + (t & 1) * KT_W;

        // ---- S = Q @ K^T ----
        float sacc[8][4];
        #pragma unroll
        for (int nt = 0; nt < 8; nt++)
            #pragma unroll
            for (int e = 0; e < 4; e++) sacc[nt][e] = 0.f;
        #pragma unroll
        for (int nt = 0; nt < 8; nt++) {
            #pragma unroll
            for (int ks = 0; ks < 4; ks++) {
                uint32_t bf[2];
                bf[0] = Kt[(nt*8 + gr) * 36 + ks*8 + gc    ];
                bf[1] = Kt[(nt*8 + gr) * 36 + ks*8 + gc + 4];
                mma_f16(sacc[nt], qf[ks], bf);
            }
        }
        if (j0 + 64 > N_) {
            #pragma unroll
            for (int nt = 0; nt < 8; nt++) {
                int cc = j0 + nt*8 + gc*2;
                if (cc     >= N_) { sacc[nt][0] = -1e30f; sacc[nt][2] = -1e30f; }
                if (cc + 1 >= N_) { sacc[nt][1] = -1e30f; sacc[nt][3] = -1e30f; }
            }
        }
        // ---- online softmax ----
        float tm0 = -1e30f, tm1 = -1e30f;
        #pragma unroll
        for (int nt = 0; nt < 8; nt++) {
            tm0 = fmaxf(tm0, fmaxf(sacc[nt][0], sacc[nt][1]));
            tm1 = fmaxf(tm1, fmaxf(sacc[nt][2], sacc[nt][3]));
        }
        tm0 = fmaxf(tm0, __shfl_xor_sync(0xffffffffu, tm0, 1));
        tm0 = fmaxf(tm0, __shfl_xor_sync(0xffffffffu, tm0, 2));
        tm1 = fmaxf(tm1, __shfl_xor_sync(0xffffffffu, tm1, 1));
        tm1 = fmaxf(tm1, __shfl_xor_sync(0xffffffffu, tm1, 2));
        float nm0 = fmaxf(rmax0, tm0), nm1 = fmaxf(rmax1, tm1);
        float sc0 = __expf(rmax0 - nm0), sc1 = __expf(rmax1 - nm1);
        rmax0 = nm0; rmax1 = nm1;
        float ps0 = 0.f, ps1 = 0.f;
        __half2* PQh = (__half2*)PQ;
        #pragma unroll
        for (int nt = 0; nt < 8; nt++) {
            float p00 = __expf(sacc[nt][0] - nm0);
            float p01 = __expf(sacc[nt][1] - nm0);
            float p10 = __expf(sacc[nt][2] - nm1);
            float p11 = __expf(sacc[nt][3] - nm1);
            ps0 += p00 + p01; ps1 += p10 + p11;
            PQh[(rbase + gr    ) * 36 + nt*4 + gc] = __floats2half2_rn(p00, p01);
            PQh[(rbase + gr + 8) * 36 + nt*4 + gc] = __floats2half2_rn(p10, p11);
            acc1[nt][0] *= sc0; acc1[nt][1] *= sc0; acc1[nt][2] *= sc1; acc1[nt][3] *= sc1;
            acc2[nt][0] *= sc0; acc2[nt][1] *= sc0; acc2[nt][2] *= sc1; acc2[nt][3] *= sc1;
        }
        ps0 += __shfl_xor_sync(0xffffffffu, ps0, 1);
        ps0 += __shfl_xor_sync(0xffffffffu, ps0, 2);
        ps1 += __shfl_xor_sync(0xffffffffu, ps1, 1);
        ps1 += __shfl_xor_sync(0xffffffffu, ps1, 2);
        rsum0 = rsum0 * sc0 + ps0;
        rsum1 = rsum1 * sc1 + ps1;
        __syncwarp();   // warp-private PQ rows

        // ---- PV: acc1 += P@V1, acc2 += P@V2 (V stored [d][j]) ----
        #pragma unroll
        for (int ks = 0; ks < 4; ks++) {
            uint32_t af[4];
            af[0] = PQ[(rbase + gr    ) * 36 + ks*8 + gc    ];
            af[1] = PQ[(rbase + gr + 8) * 36 + ks*8 + gc    ];
            af[2] = PQ[(rbase + gr    ) * 36 + ks*8 + gc + 4];
            af[3] = PQ[(rbase + gr + 8) * 36 + ks*8 + gc + 4];
            #pragma unroll
            for (int nt = 0; nt < 8; nt++) {
                uint32_t bv1[2], bv2[2];
                bv1[0] = V1[(nt*8 + gr) * 36 + ks*8 + gc    ];
                bv1[1] = V1[(nt*8 + gr) * 36 + ks*8 + gc + 4];
                bv2[0] = V2[(nt*8 + gr) * 36 + ks*8 + gc    ];
                bv2[1] = V2[(nt*8 + gr) * 36 + ks*8 + gc + 4];
                mma_f16(acc1[nt], af, bv1);
                mma_f16(acc2[nt], af, bv2);
            }
        }
        __syncthreads();
    }

    // ---- epilogue ----
    float inv0 = 1.0f / rsum0, inv1 = 1.0f / rsum1;
    int gi0 = i0 + rbase + gr, gi1 = gi0 + 8;
    if (gi0 < N_) {
        float f = inv0 * g_upd[b * N_ + gi0];
        size_t base = (size_t)(b * N_ + gi0) * DIM_ + h * 64;
        #pragma unroll
        for (int nt = 0; nt < 8; nt++) {
            int d = nt*8 + gc*2;
            *(float2*)&g_out[base + d] = make_float2(acc1[nt][0]*f, acc1[nt][1]*f);
            *(float2*)&g_m  [base + d] = make_float2(acc2[nt][0]*f, acc2[nt][1]*f);
        }
    }
    if (gi1 < N_) {
        float f = inv1 * g_upd[b * N_ + gi1];
        size_t base = (size_t)(b * N_ + gi1) * DIM_ + h * 64;
        #pragma unroll
        for (int nt = 0; nt < 8; nt++) {
            int d = nt*8 + gc*2;
            *(float2*)&g_out[base + d] = make_float2(acc1[nt][2]*f, acc1[nt][3]*f);
            *(float2*)&g_m  [base + d] = make_float2(acc2[nt][2]*f, acc2[nt][3]*f);
        }
    }
}

// ---------------- updated[b,i] ----------------
__global__ void updated_k(const float* __restrict__ mask)
{
    int row = blockIdx.x * (blockDim.x >> 5) + (threadIdx.x >> 5);
    if (row >= BN_) return;
    int ln = threadIdx.x & 31;
    const float* p = mask + (size_t)row * DIM_;
    float s = 0.f;
    #pragma unroll
    for (int e = ln; e < DIM_; e += 32) s += p[e];
    #pragma unroll
    for (int o = 16; o > 0; o >>= 1) s += __shfl_xor_sync(0xffffffffu, s, o);
    if (ln == 0) {
        int i = row % N_;
        g_upd[row] = (i == 0) ? 1.0f : (s > 0.0f ? 1.0f : 0.0f);
    }
}

// ---------------- per-(bh,w,d) max over sequence ----------------
__global__ void reduce_max_k()
{
    int o = blockIdx.x * blockDim.x + threadIdx.x;
    if (o >= B_*H_*3*D_) return;
    int d = o & 63;
    int w = (o >> 6) % 3;
    int h = ((o >> 6) / 3) % H_;
    int b = (o >> 6) / 24;
    const float* p = g_qkvm + (size_t)b * N_ * QKV_ + w * DIM_ + h * 64 + d;
    float mx = -1e30f;
    for (int i = 0; i < N_; i++) mx = fmaxf(mx, p[(size_t)i * QKV_]);
    g_max[((b * H_ + h) * 3 + w) * 64 + d] = mx;
}

// ---------------- modulate: fp16 q/k (row-major) + transposed v/vm ----------------
__global__ void __launch_bounds__(256) modulate_k()
{
    __shared__ __half sv1[64][72];
    __shared__ __half sv2[64][72];
    __shared__ float smax[192];
    const int bh = blockIdx.y, b = bh >> 3, h = bh & 7;
    const int i0 = blockIdx.x * 64;
    const int t = threadIdx.x;
    if (t < 192) smax[t] = g_max[bh * 192 + t];
    __syncthreads();

    const int r = t >> 2, d0 = (t & 3) * 16;
    const int i = i0 + r;

    union H16 { __half h[16]; uint4 u[2]; };
    H16 qo, ko;

    if (i < N_) {
        size_t base = (size_t)(b * N_ + i) * QKV_ + h * 64 + d0;
        #pragma unroll
        for (int e = 0; e < 4; e++) {
            float4 q  = *(const float4*)&g_qkv [base + e*4];
            float4 k  = *(const float4*)&g_qkv [base + 512 + e*4];
            float4 v  = *(const float4*)&g_qkv [base + 1024 + e*4];
            float4 qm = *(const float4*)&g_qkvm[base + e*4];
            float4 km = *(const float4*)&g_qkvm[base + 512 + e*4];
            float4 vm = *(const float4*)&g_qkvm[base + 1024 + e*4];
            float qa[4] = {q.x,q.y,q.z,q.w}, ka[4] = {k.x,k.y,k.z,k.w}, va[4] = {v.x,v.y,v.z,v.w};
            float qma[4] = {qm.x,qm.y,qm.z,qm.w}, kma[4] = {km.x,km.y,km.z,km.w}, vma[4] = {vm.x,vm.y,vm.z,vm.w};
            #pragma unroll
            for (int j = 0; j < 4; j++) {
                int d = d0 + e*4 + j;
                float qmn = qma[j] / (1e-6f + smax[d]);
                float kmn = kma[j] / (1e-6f + smax[64 + d]);
                float vmn = vma[j] / (1e-6f + smax[128 + d]);
                qo.h[e*4+j] = __float2half_rn(qa[j] * qmn * SCALE_);
                ko.h[e*4+j] = __float2half_rn(ka[j] * kmn);
                sv1[r][d] = __float2half_rn(va[j] * vmn);
                sv2[r][d] = __float2half_rn(vmn);
            }
        }
        size_t ob = (size_t)bh * N_ * 64 + (size_t)i * 64 + d0;
        *(uint4*)&g_qh[ob] = qo.u[0];
        *(uint4*)&g_qh[ob + 8] = qo.u[1];
        *(uint4*)&g_kh[ob] = ko.u[0];
        *(uint4*)&g_kh[ob + 8] = ko.u[1];
    } else {
        #pragma unroll
        for (int e = 0; e < 16; e++) {
            sv1[r][d0 + e] = __float2half_rn(0.f);
            sv2[r][d0 + e] = __float2half_rn(0.f);
        }
    }
    __syncthreads();

    // transpose out: thread -> d-row, 16 i's
    const int drow = t >> 2, is0 = (t & 3) * 16;
    H16 o1, o2;
    #pragma unroll
    for (int e = 0; e < 16; e++) {
        o1.h[e] = sv1[is0 + e][drow];
        o2.h[e] = sv2[is0 + e][drow];
    }
    size_t ob = (size_t)bh * 64 * 512 + (size_t)drow * 512 + i0 + is0;
    *(uint4*)&g_vvT[ob] = o1.u[0];
    *(uint4*)&g_vvT[ob + 8] = o1.u[1];
    *(uint4*)&g_vmT[ob] = o2.u[0];
    *(uint4*)&g_vmT[ob + 8] = o2.u[1];
}

// ---------------- overlap blending; emits fp16 out2/m2 + f32 m2 ----------------
__global__ void blend_k()
{
    int idx4 = blockIdx.x * blockDim.x + threadIdx.x;
    if (idx4 >= SZ_BND / 4) return;
    size_t idx = (size_t)idx4 * 4;
    int c = idx % DIM_;
    int i = (idx / DIM_) % N_;
    int b = idx / (DIM_ * (size_t)N_);
    float4 o  = *(const float4*)&g_out[idx];
    float4 mv = *(const float4*)&g_m[idx];

    if (i >= 1 && i <= NHW_) {
        int p = i - 1, y = p >> 4, x = p & 15;
        float inv = 0.25f * (1.0f - g_upd[b * N_ + i]);
        float4 s1 = make_float4(0,0,0,0), s2 = make_float4(0,0,0,0);
        #pragma unroll
        for (int dy = -1; dy <= 0; dy++)
            #pragma unroll
            for (int dx = -1; dx <= 0; dx++) {
                int rr = y + dy, cc = x + dx;
                if (rr >= 0 && rr < 15 && cc >= 0 && cc < 15) {
                    size_t src = ((size_t)(b * N_ + TAIL0_ + rr * 15 + cc)) * DIM_ + c;
                    float4 a = *(const float4*)&g_out[src];
                    float4 e = *(const float4*)&g_m[src];
                    s1.x += a.x; s1.y += a.y; s1.z += a.z; s1.w += a.w;
                    s2.x += e.x; s2.y += e.y; s2.z += e.z; s2.w += e.w;
                }
            }
        o.x += s1.x*inv; o.y += s1.y*inv; o.z += s1.z*inv; o.w += s1.w*inv;
        mv.x += s2.x*inv; mv.y += s2.y*inv; mv.z += s2.z*inv; mv.w += s2.w*inv;
    } else if (i >= TAIL0_) {
        int p = i - TAIL0_, rr = p / 15, cc = p % 15;
        float inv = 0.25f * (1.0f - g_upd[b * N_ + i]);
        float4 s1 = make_float4(0,0,0,0), s2 = make_float4(0,0,0,0);
        #pragma unroll
        for (int dy = 0; dy <= 1; dy++)
            #pragma unroll
            for (int dx = 0; dx <= 1; dx++) {
                size_t src = ((size_t)(b * N_ + 1 + (rr + dy) * 16 + (cc + dx))) * DIM_ + c;
                float4 a = *(const float4*)&g_out[src];
                float4 e = *(const float4*)&g_m[src];
                s1.x += a.x; s1.y += a.y; s1.z += a.z; s1.w += a.w;
                s2.x += e.x; s2.y += e.y; s2.z += e.z; s2.w += e.w;
            }
        o.x += s1.x*inv; o.y += s1.y*inv; o.z += s1.z*inv; o.w += s1.w*inv;
        mv.x += s2.x*inv; mv.y += s2.y*inv; mv.z += s2.z*inv; mv.w += s2.w*inv;
    }
    *(float4*)&g_m2[idx] = mv;
    __half2 ol = __floats2half2_rn(o.x, o.y),  oh = __floats2half2_rn(o.z, o.w);
    __half2 ml = __floats2half2_rn(mv.x, mv.y), mh = __floats2half2_rn(mv.z, mv.w);
    uint2 ou, mu;
    ou.x = *(uint32_t*)&ol; ou.y = *(uint32_t*)&oh;
    mu.x = *(uint32_t*)&ml; mu.y = *(uint32_t*)&mh;
    *(uint2*)&g_o2h[idx] = ou;
    *(uint2*)&g_m2h[idx] = mu;
}

// ---------------- channel means ----------------
__global__ void mm_k()
{
    int row = blockIdx.x * (blockDim.x >> 5) + (threadIdx.x >> 5);
    if (row >= B_ * (N_ - 1)) return;
    int b = row / (N_ - 1), j = row % (N_ - 1);
    int ln = threadIdx.x & 31;
    const float* p = g_m2 + (size_t)(b * N_ + j + 1) * DIM_;
    float s = 0.f;
    #pragma unroll
    for (int e = ln; e < DIM_; e += 32) s += p[e];
    #pragma unroll
    for (int o = 16; o > 0; o >>= 1) s += __shfl_xor_sync(0xffffffffu, s, o);
    if (ln == 0) g_mm[row] = s * (1.0f / DIM_);
}

// ---------------- inter ----------------
__global__ void inter_k(float* __restrict__ outp)
{
    int idx = blockIdx.x * blockDim.x + threadIdx.x;
    if (idx >= B_ * 256 * 256) return;
    int x = idx & 255, y = (idx >> 8) & 255, b = idx >> 16;
    float v = g_mm[b * (N_ - 1) + (y >> 4) * 16 + (x >> 4)];
    if (y >= 8 && y < 248 && x >= 8 && x < 248) {
        float sh = g_mm[b * (N_ - 1) + 256 + ((y - 8) >> 4) * 15 + ((x - 8) >> 4)];
        v = 0.5f * (v + sh);
    }
    outp[idx] = v;
}

// ---------------- launch ----------------
extern "C" void kernel_launch(void* const* d_in, const int* in_sizes, int n_in,
                              void* d_out, int out_size)
{
    const float* x    = (const float*)d_in[0];
    const float* mask = (const float*)d_in[1];
    const float* Wqkv = (const float*)d_in[2];
    const float* Wout = (const float*)d_in[3];
    const float* bout = (const float*)d_in[4];
    float* out = (float*)d_out;

    float *p_qkv, *p_qkvm;
    __half *p_xh, *p_mkh, *p_wqh, *p_wqah, *p_woh, *p_woah, *p_o2h, *p_m2h;
    cudaGetSymbolAddress((void**)&p_qkv,  g_qkv);
    cudaGetSymbolAddress((void**)&p_qkvm, g_qkvm);
    cudaGetSymbolAddress((void**)&p_xh,   g_xh);
    cudaGetSymbolAddress((void**)&p_mkh,  g_mkh);
    cudaGetSymbolAddress((void**)&p_wqh,  g_wqh);
    cudaGetSymbolAddress((void**)&p_wqah, g_wqah);
    cudaGetSymbolAddress((void**)&p_woh,  g_woh);
    cudaGetSymbolAddress((void**)&p_woah, g_woah);
    cudaGetSymbolAddress((void**)&p_o2h,  g_o2h);
    cudaGetSymbolAddress((void**)&p_m2h,  g_m2h);

    const int gemm_smem = 4 * GBUF_W * 4;          // 40960 B
    cudaFuncSetAttribute(hgemm<false>, cudaFuncAttributeMaxDynamicSharedMemorySize, gemm_smem);
    cudaFuncSetAttribute(hgemm<true >, cudaFuncAttributeMaxDynamicSharedMemorySize, gemm_smem);
    cudaFuncSetAttribute(flash_attn, cudaFuncAttributeMaxDynamicSharedMemorySize, FA_SMEM_WORDS * 4);

    // 0. fp16 copies
    half_copy<false><<<(SZ_BND/4 + 255)/256, 256>>>((const float4*)x,    (uint2*)p_xh,   SZ_BND/4);
    half_copy<false><<<(SZ_BND/4 + 255)/256, 256>>>((const float4*)mask, (uint2*)p_mkh,  SZ_BND/4);
    half_copy<false><<<(QKV_*DIM_/4 + 255)/256, 256>>>((const float4*)Wqkv, (uint2*)p_wqh,  QKV_*DIM_/4);
    half_copy<true ><<<(QKV_*DIM_/4 + 255)/256, 256>>>((const float4*)Wqkv, (uint2*)p_wqah, QKV_*DIM_/4);
    half_copy<false><<<(DIM_*DIM_/4 + 255)/256, 256>>>((const float4*)Wout, (uint2*)p_woh,  DIM_*DIM_/4);
    half_copy<true ><<<(DIM_*DIM_/4 + 255)/256, 256>>>((const float4*)Wout, (uint2*)p_woah, DIM_*DIM_/4);

    // 1-2. qkv projections (fp16 MMA, f32 out)
    hgemm<false><<<dim3(QKV_/128, BN_/128), 256, gemm_smem>>>(p_xh,  p_wqh,  nullptr, p_qkv,  DIM_, DIM_, DIM_, QKV_);
    hgemm<false><<<dim3(QKV_/128, BN_/128), 256, gemm_smem>>>(p_mkh, p_wqah, nullptr, p_qkvm, DIM_, DIM_, DIM_, QKV_);
    // 3. updated flags
    updated_k<<<(BN_ + 7) / 8, 256>>>(mask);
    // 4. maxima
    reduce_max_k<<<(B_*H_*3*D_ + 255) / 256, 256>>>();
    // 5. modulate (fp16 q/k + transposed v/vm)
    modulate_k<<<dim3(8, BH_), 256>>>();
    // 6-8. fused attention
    flash_attn<<<dim3(4, BH_), 256, FA_SMEM_WORDS * 4>>>();
    // 9. blending (emits fp16 o2/m2 + f32 m2)
    blend_k<<<(SZ_BND/4 + 255)/256, 256>>>();
    // 10. channel means
    mm_k<<<(B_ * (N_ - 1) + 7) / 8, 256>>>();
    // 11. inter
    inter_k<<<(B_ * 65536 + 255) / 256, 256>>>(out + 2 * (size_t)SZ_BND);
    // 12-13. final projections
    hgemm<true ><<<dim3(DIM_/128, BN_/128), 256, gemm_smem>>>(p_o2h, p_woh,  bout,    out,                  DIM_, DIM_, DIM_, DIM_);
    hgemm<false><<<dim3(DIM_/128, BN_/128), 256, gemm_smem>>>(p_m2h, p_woah, nullptr, out + (size_t)SZ_BND, DIM_, DIM_, DIM_, DIM_);
}

// round 14
// speedup vs baseline: 2.2571x; 1.0988x over previous
#include <cuda_runtime.h>
#include <cuda_fp16.h>
#include <cstdint>

// ---------------- problem constants ----------------
#define B_    64
#define N_    482
#define DIM_  512
#define H_    8
#define D_    64
#define QKV_  1536
#define BH_   (B_*H_)          // 512
#define BN_   (B_*N_)          // 30848
#define SZ_BND (BN_*DIM_)      // 15794176
#define NHW_  256
#define NB_   225
#define TAIL0_ 257
#define SCALE_ 0.125f

// ---------------- device scratch ----------------
__device__ float  g_out [SZ_BND];
__device__ float  g_m   [SZ_BND];
__device__ float  g_m2  [SZ_BND];
__device__ float  g_max [B_*H_*3*D_];
__device__ float  g_upd [BN_];
__device__ float  g_mm  [B_*(N_-1)];
// fp16 tensors
__device__ __half g_xh  [SZ_BND];
__device__ __half g_mkh [SZ_BND];
__device__ __half g_wqh [QKV_*DIM_];
__device__ __half g_wqah[QKV_*DIM_];
__device__ __half g_woh [DIM_*DIM_];
__device__ __half g_woah[DIM_*DIM_];
__device__ __half g_qkvh [(size_t)BN_*QKV_];
__device__ __half g_qkvmh[(size_t)BN_*QKV_];
__device__ __half g_qh  [(size_t)BH_*N_*D_];
__device__ __half g_kh  [(size_t)BH_*N_*D_];
__device__ __half g_vvT [(size_t)BH_*64*512];   // [bh][d][j], zero-padded cols
__device__ __half g_vmT [(size_t)BH_*64*512];
__device__ __half g_o2h [SZ_BND];
__device__ __half g_m2h [SZ_BND];

// ---------------- helpers ----------------
__device__ __forceinline__ void mma_f16(float* c, const uint32_t* a, const uint32_t* b) {
    asm volatile("mma.sync.aligned.m16n8k16.row.col.f32.f16.f16.f32 "
        "{%0,%1,%2,%3}, {%4,%5,%6,%7}, {%8,%9}, {%0,%1,%2,%3};"
        : "+f"(c[0]), "+f"(c[1]), "+f"(c[2]), "+f"(c[3])
        : "r"(a[0]), "r"(a[1]), "r"(a[2]), "r"(a[3]), "r"(b[0]), "r"(b[1]));
}
__device__ __forceinline__ void ldm4(uint32_t* r, uint32_t addr) {
    asm volatile("ldmatrix.sync.aligned.m8n8.x4.shared.b16 {%0,%1,%2,%3}, [%4];"
        : "=r"(r[0]), "=r"(r[1]), "=r"(r[2]), "=r"(r[3]) : "r"(addr));
}
__device__ __forceinline__ uint32_t smem_u32(const void* p) {
    return (uint32_t)__cvta_generic_to_shared(p);
}
__device__ __forceinline__ void cp16(uint32_t dst, const void* src, int sz) {
    asm volatile("cp.async.cg.shared.global [%0], [%1], 16, %2;" :: "r"(dst), "l"(src), "r"(sz));
}
#define CP_COMMIT() asm volatile("cp.async.commit_group;")
#define CP_WAIT(n)  asm volatile("cp.async.wait_group %0;" :: "n"(n))

extern __shared__ uint32_t s_dyn[];

// ---------------- prep kernels ----------------
__global__ void half_copy1(const float4* __restrict__ src, uint2* __restrict__ dst, int n4)
{
    int i = blockIdx.x * blockDim.x + threadIdx.x;
    if (i >= n4) return;
    float4 v = src[i];
    __half2 lo = __floats2half2_rn(v.x, v.y);
    __half2 hi = __floats2half2_rn(v.z, v.w);
    uint2 r; r.x = *(uint32_t*)&lo; r.y = *(uint32_t*)&hi;
    dst[i] = r;
}
__global__ void half_copy2(const float4* __restrict__ src, uint2* __restrict__ dstp,
                           uint2* __restrict__ dsta, int n4)
{
    int i = blockIdx.x * blockDim.x + threadIdx.x;
    if (i >= n4) return;
    float4 v = src[i];
    __half2 lo = __floats2half2_rn(v.x, v.y);
    __half2 hi = __floats2half2_rn(v.z, v.w);
    uint2 r; r.x = *(uint32_t*)&lo; r.y = *(uint32_t*)&hi;
    dstp[i] = r;
    r.x &= 0x7fff7fffu; r.y &= 0x7fff7fffu;
    dsta[i] = r;
}

// ================= fp16 NT GEMM (m16n8k16, ldmatrix), 128x128 tile =================
// C[m,n] = sum_k A[m*lda+k]*B[n*ldb+k] (+bias[n]); M,N mult of 128, K of 32.
#define GBUF_W 2560   // words per tile buffer: 128 rows * 20 words (40 halfs)
template<bool BIAS, bool HOUT>
__global__ void __launch_bounds__(256) hgemm(const __half* __restrict__ A,
                                             const __half* __restrict__ Bm,
                                             const float* __restrict__ bias,
                                             void* __restrict__ Cv,
                                             int K, int lda, int ldb, int ldc)
{
    uint32_t* AsB = s_dyn;               // [2][2560]
    uint32_t* BsB = s_dyn + 2 * GBUF_W;  // [2][2560]
    const int tid = threadIdx.x;
    const int bm = blockIdx.y * 128, bn = blockIdx.x * 128;
    const int lane = tid & 31, wid = tid >> 5;
    const int gr = lane >> 2, gc = lane & 3;
    const int wm = (wid & 1) * 64, wn = (wid >> 1) * 32;
    // ldmatrix lane roles
    const int a_row = (lane & 7) + ((lane >> 3) & 1) * 8;
    const int a_col = (lane >> 4) * 4;
    const int b_row = (lane & 7) + ((lane >> 4) & 1) * 8;
    const int b_col = ((lane >> 3) & 1) * 4;

    float acc[4][4][4];
    #pragma unroll
    for (int i = 0; i < 4; i++)
        #pragma unroll
        for (int j = 0; j < 4; j++)
            #pragma unroll
            for (int e = 0; e < 4; e++) acc[i][j][e] = 0.f;

    const int nslab = K >> 5;
    const int r0s = tid >> 2, s0s = tid & 3;
    const int r1s = 64 + (tid >> 2);
    {
        cp16(smem_u32(&AsB[r0s*20 + s0s*4]), A + (size_t)(bm + r0s) * lda + s0s*8, 16);
        cp16(smem_u32(&AsB[r1s*20 + s0s*4]), A + (size_t)(bm + r1s) * lda + s0s*8, 16);
        cp16(smem_u32(&BsB[r0s*20 + s0s*4]), Bm + (size_t)(bn + r0s) * ldb + s0s*8, 16);
        cp16(smem_u32(&BsB[r1s*20 + s0s*4]), Bm + (size_t)(bn + r1s) * ldb + s0s*8, 16);
        CP_COMMIT();
    }
    for (int s = 0; s < nslab; s++) {
        if (s + 1 < nslab) {
            uint32_t* As = AsB + ((s+1) & 1) * GBUF_W;
            uint32_t* Bs = BsB + ((s+1) & 1) * GBUF_W;
            int kt = (s + 1) * 32;
            cp16(smem_u32(&As[r0s*20 + s0s*4]), A + (size_t)(bm + r0s) * lda + kt + s0s*8, 16);
            cp16(smem_u32(&As[r1s*20 + s0s*4]), A + (size_t)(bm + r1s) * lda + kt + s0s*8, 16);
            cp16(smem_u32(&Bs[r0s*20 + s0s*4]), Bm + (size_t)(bn + r0s) * ldb + kt + s0s*8, 16);
            cp16(smem_u32(&Bs[r1s*20 + s0s*4]), Bm + (size_t)(bn + r1s) * ldb + kt + s0s*8, 16);
            CP_COMMIT();
            CP_WAIT(1);
        } else {
            CP_WAIT(0);
        }
        __syncthreads();

        const uint32_t* As = AsB + (s & 1) * GBUF_W;
        const uint32_t* Bs = BsB + (s & 1) * GBUF_W;
        #pragma unroll
        for (int ks = 0; ks < 2; ks++) {
            const int kw = ks * 8;
            uint32_t ah[4][4];
            #pragma unroll
            for (int mt = 0; mt < 4; mt++)
                ldm4(ah[mt], smem_u32(&As[(wm + mt*16 + a_row) * 20 + kw + a_col]));
            #pragma unroll
            for (int p = 0; p < 2; p++) {
                uint32_t t[4];
                ldm4(t, smem_u32(&Bs[(wn + p*16 + b_row) * 20 + kw + b_col]));
                #pragma unroll
                for (int mt = 0; mt < 4; mt++) {
                    mma_f16(acc[mt][2*p    ], ah[mt], t);
                    mma_f16(acc[mt][2*p + 1], ah[mt], t + 2);
                }
            }
        }
        __syncthreads();
    }
    #pragma unroll
    for (int mt = 0; mt < 4; mt++)
        #pragma unroll
        for (int nt = 0; nt < 4; nt++) {
            int m0 = bm + wm + mt * 16 + gr;
            int n0 = bn + wn + nt * 8 + gc * 2;
            float bx = 0.f, by = 0.f;
            if (BIAS) { bx = bias[n0]; by = bias[n0 + 1]; }
            if (HOUT) {
                __half* C = (__half*)Cv;
                __half2 v0 = __floats2half2_rn(acc[mt][nt][0], acc[mt][nt][1]);
                __half2 v1 = __floats2half2_rn(acc[mt][nt][2], acc[mt][nt][3]);
                *(uint32_t*)&C[(size_t)m0 * ldc + n0]       = *(uint32_t*)&v0;
                *(uint32_t*)&C[(size_t)(m0 + 8) * ldc + n0] = *(uint32_t*)&v1;
            } else {
                float* C = (float*)Cv;
                *(float2*)&C[(size_t)m0 * ldc + n0] = make_float2(acc[mt][nt][0] + bx, acc[mt][nt][1] + by);
                *(float2*)&C[(size_t)(m0 + 8) * ldc + n0] = make_float2(acc[mt][nt][2] + bx, acc[mt][nt][3] + by);
            }
        }
}

// ================= fp16 flash attention (ldmatrix) =================
#define KT_W    2304     // 64 rows * 36 words (72 halfs)
#define V1_OFF  (2*KT_W)
#define V2_OFF  (4*KT_W)
#define PQ_OFF  (6*KT_W)
#define FA_SMEM_WORDS (PQ_OFF + 128*36)

__global__ void __launch_bounds__(256, 1) flash_attn()
{
    const int bh = blockIdx.y;
    const int b = bh >> 3, h = bh & 7;
    const int i0 = blockIdx.x * 128;
    const __half* Q   = g_qh  + (size_t)bh * N_ * D_;
    const __half* Kp  = g_kh  + (size_t)bh * N_ * D_;
    const __half* V1g = g_vvT + (size_t)bh * 64 * 512;
    const __half* V2g = g_vmT + (size_t)bh * 64 * 512;
    uint32_t* PQ = s_dyn + PQ_OFF;

    const int tid = threadIdx.x;
    const int lane = tid & 31, wid = tid >> 5;
    const int gr = lane >> 2, gc = lane & 3;
    const int rbase = wid * 16;
    const int a_row = (lane & 7) + ((lane >> 3) & 1) * 8;
    const int a_col = (lane >> 4) * 4;
    const int b_row = (lane & 7) + ((lane >> 4) & 1) * 8;
    const int b_col = ((lane >> 3) & 1) * 4;

    // ---- stage Q into PQ (fp16): 128 rows * 64 halfs = 1024 chunks of 16B ----
    {
        #pragma unroll
        for (int e = 0; e < 4; e++) {
            int chunk = tid + e * 256;
            int row = chunk >> 3, seg = chunk & 7;
            int gi = i0 + row;
            uint4 q = make_uint4(0u,0u,0u,0u);
            if (gi < N_) q = *(const uint4*)(Q + (size_t)gi * D_ + seg * 8);
            *(uint4*)&PQ[row * 36 + seg * 4] = q;
        }
    }
    __syncthreads();
    uint32_t qf[4][4];
    #pragma unroll
    for (int ks = 0; ks < 4; ks++)
        ldm4(qf[ks], smem_u32(&PQ[(rbase + a_row) * 36 + ks*8 + a_col]));
    __syncthreads();

    float acc1[8][4], acc2[8][4];
    #pragma unroll
    for (int nt = 0; nt < 8; nt++)
        #pragma unroll
        for (int e = 0; e < 4; e++) { acc1[nt][e] = 0.f; acc2[nt][e] = 0.f; }
    float rmax0 = -1e30f, rmax1 = -1e30f, rsum0 = 0.f, rsum1 = 0.f;

    const int ntiles = (N_ + 63) / 64;   // 8
    {
        #pragma unroll
        for (int e = 0; e < 2; e++) {
            int chunk = tid + e * 256;
            int row = chunk >> 3, seg = chunk & 7;
            int j = row;
            int sz = (j < N_) ? 16 : 0;
            cp16(smem_u32(&s_dyn[row*36 + seg*4]), Kp + (size_t)(sz ? j : 0) * D_ + seg*8, sz);
            cp16(smem_u32(&s_dyn[V1_OFF + row*36 + seg*4]), V1g + (size_t)row * 512 + seg*8, 16);
            cp16(smem_u32(&s_dyn[V2_OFF + row*36 + seg*4]), V2g + (size_t)row * 512 + seg*8, 16);
        }
        CP_COMMIT();
    }

    for (int t = 0; t < ntiles; t++) {
        const int j0 = t * 64;
        if (t + 1 < ntiles) {
            int buf = (t + 1) & 1;
            int jb = j0 + 64;
            #pragma unroll
            for (int e = 0; e < 2; e++) {
                int chunk = tid + e * 256;
                int row = chunk >> 3, seg = chunk & 7;
                int j = jb + row;
                int sz = (j < N_) ? 16 : 0;
                cp16(smem_u32(&s_dyn[buf*KT_W + row*36 + seg*4]), Kp + (size_t)(sz ? j : 0) * D_ + seg*8, sz);
                cp16(smem_u32(&s_dyn[V1_OFF + buf*KT_W + row*36 + seg*4]), V1g + (size_t)row * 512 + jb + seg*8, 16);
                cp16(smem_u32(&s_dyn[V2_OFF + buf*KT_W + row*36 + seg*4]), V2g + (size_t)row * 512 + jb + seg*8, 16);
            }
            CP_COMMIT();
            CP_WAIT(1);
        } else {
            CP_WAIT(0);
        }
        __syncthreads();

        const uint32_t* Kt = s_dyn + (t & 1) * KT_W;
        const uint32_t* V1 = s_dyn + V1_OFF + (t & 1) * KT_W;
        const uint32_t* V2 = s_dyn + V2_OFF + (t & 1) * KT_W;

        // ---- S = Q @ K^T (ldmatrix B-frags) ----
        float sacc[8][4];
        #pragma unroll
        for (int nt = 0; nt < 8; nt++)
            #pragma unroll
            for (int e = 0; e < 4; e++) sacc[nt][e] = 0.f;
        #pragma unroll
        for (int ks = 0; ks < 4; ks++) {
            #pragma unroll
            for (int p = 0; p < 4; p++) {
                uint32_t tkt[4];
                ldm4(tkt, smem_u32(&Kt[(p*16 + b_row) * 36 + ks*8 + b_col]));
                mma_f16(sacc[2*p    ], qf[ks], tkt);
                mma_f16(sacc[2*p + 1], qf[ks], tkt + 2);
            }
        }
        if (j0 + 64 > N_) {
            #pragma unroll
            for (int nt = 0; nt < 8; nt++) {
                int cc = j0 + nt*8 + gc*2;
                if (cc     >= N_) { sacc[nt][0] = -1e30f; sacc[nt][2] = -1e30f; }
                if (cc + 1 >= N_) { sacc[nt][1] = -1e30f; sacc[nt][3] = -1e30f; }
            }
        }
        // ---- online softmax ----
        float tm0 = -1e30f, tm1 = -1e30f;
        #pragma unroll
        for (int nt = 0; nt < 8; nt++) {
            tm0 = fmaxf(tm0, fmaxf(sacc[nt][0], sacc[nt][1]));
            tm1 = fmaxf(tm1, fmaxf(sacc[nt][2], sacc[nt][3]));
        }
        tm0 = fmaxf(tm0, __shfl_xor_sync(0xffffffffu, tm0, 1));
        tm0 = fmaxf(tm0, __shfl_xor_sync(0xffffffffu, tm0, 2));
        tm1 = fmaxf(tm1, __shfl_xor_sync(0xffffffffu, tm1, 1));
        tm1 = fmaxf(tm1, __shfl_xor_sync(0xffffffffu, tm1, 2));
        float nm0 = fmaxf(rmax0, tm0), nm1 = fmaxf(rmax1, tm1);
        float sc0 = __expf(rmax0 - nm0), sc1 = __expf(rmax1 - nm1);
        rmax0 = nm0; rmax1 = nm1;
        float ps0 = 0.f, ps1 = 0.f;
        __half2* PQh = (__half2*)PQ;
        #pragma unroll
        for (int nt = 0; nt < 8; nt++) {
            float p00 = __expf(sacc[nt][0] - nm0);
            float p01 = __expf(sacc[nt][1] - nm0);
            float p10 = __expf(sacc[nt][2] - nm1);
            float p11 = __expf(sacc[nt][3] - nm1);
            ps0 += p00 + p01; ps1 += p10 + p11;
            PQh[(rbase + gr    ) * 36 + nt*4 + gc] = __floats2half2_rn(p00, p01);
            PQh[(rbase + gr + 8) * 36 + nt*4 + gc] = __floats2half2_rn(p10, p11);
            acc1[nt][0] *= sc0; acc1[nt][1] *= sc0; acc1[nt][2] *= sc1; acc1[nt][3] *= sc1;
            acc2[nt][0] *= sc0; acc2[nt][1] *= sc0; acc2[nt][2] *= sc1; acc2[nt][3] *= sc1;
        }
        ps0 += __shfl_xor_sync(0xffffffffu, ps0, 1);
        ps0 += __shfl_xor_sync(0xffffffffu, ps0, 2);
        ps1 += __shfl_xor_sync(0xffffffffu, ps1, 1);
        ps1 += __shfl_xor_sync(0xffffffffu, ps1, 2);
        rsum0 = rsum0 * sc0 + ps0;
        rsum1 = rsum1 * sc1 + ps1;
        __syncwarp();   // warp-private PQ rows

        // ---- PV: acc1 += P@V1, acc2 += P@V2 (V stored [d][j]) ----
        #pragma unroll
        for (int ks = 0; ks < 4; ks++) {
            uint32_t af[4];
            ldm4(af, smem_u32(&PQ[(rbase + a_row) * 36 + ks*8 + a_col]));
            #pragma unroll
            for (int p = 0; p < 4; p++) {
                uint32_t t1[4], t2[4];
                ldm4(t1, smem_u32(&V1[(p*16 + b_row) * 36 + ks*8 + b_col]));
                ldm4(t2, smem_u32(&V2[(p*16 + b_row) * 36 + ks*8 + b_col]));
                mma_f16(acc1[2*p    ], af, t1);
                mma_f16(acc1[2*p + 1], af, t1 + 2);
                mma_f16(acc2[2*p    ], af, t2);
                mma_f16(acc2[2*p + 1], af, t2 + 2);
            }
        }
        __syncthreads();
    }

    // ---- epilogue ----
    float inv0 = 1.0f / rsum0, inv1 = 1.0f / rsum1;
    int gi0 = i0 + rbase + gr, gi1 = gi0 + 8;
    if (gi0 < N_) {
        float f = inv0 * g_upd[b * N_ + gi0];
        size_t base = (size_t)(b * N_ + gi0) * DIM_ + h * 64;
        #pragma unroll
        for (int nt = 0; nt < 8; nt++) {
            int d = nt*8 + gc*2;
            *(float2*)&g_out[base + d] = make_float2(acc1[nt][0]*f, acc1[nt][1]*f);
            *(float2*)&g_m  [base + d] = make_float2(acc2[nt][0]*f, acc2[nt][1]*f);
        }
    }
    if (gi1 < N_) {
        float f = inv1 * g_upd[b * N_ + gi1];
        size_t base = (size_t)(b * N_ + gi1) * DIM_ + h * 64;
        #pragma unroll
        for (int nt = 0; nt < 8; nt++) {
            int d = nt*8 + gc*2;
            *(float2*)&g_out[base + d] = make_float2(acc1[nt][2]*f, acc1[nt][3]*f);
            *(float2*)&g_m  [base + d] = make_float2(acc2[nt][2]*f, acc2[nt][3]*f);
        }
    }
}

// ---------------- updated[b,i] ----------------
__global__ void updated_k(const float* __restrict__ mask)
{
    int row = blockIdx.x * (blockDim.x >> 5) + (threadIdx.x >> 5);
    if (row >= BN_) return;
    int ln = threadIdx.x & 31;
    const float* p = mask + (size_t)row * DIM_;
    float s = 0.f;
    #pragma unroll
    for (int e = ln; e < DIM_; e += 32) s += p[e];
    #pragma unroll
    for (int o = 16; o > 0; o >>= 1) s += __shfl_xor_sync(0xffffffffu, s, o);
    if (ln == 0) {
        int i = row % N_;
        g_upd[row] = (i == 0) ? 1.0f : (s > 0.0f ? 1.0f : 0.0f);
    }
}

// ---------------- per-(bh,w,d) max over sequence (fp16 input) ----------------
__global__ void reduce_max_k()
{
    int o = blockIdx.x * blockDim.x + threadIdx.x;
    if (o >= B_*H_*3*D_) return;
    int d = o & 63;
    int w = (o >> 6) % 3;
    int h = ((o >> 6) / 3) % H_;
    int b = (o >> 6) / 24;
    const __half* p = g_qkvmh + (size_t)b * N_ * QKV_ + w * DIM_ + h * 64 + d;
    float mx = -1e30f;
    for (int i = 0; i < N_; i++) mx = fmaxf(mx, __half2float(p[(size_t)i * QKV_]));
    g_max[((b * H_ + h) * 3 + w) * 64 + d] = mx;
}

// ---------------- modulate: fp16 in, fp16 q/k + transposed v/vm out ----------------
__global__ void __launch_bounds__(256) modulate_k()
{
    __shared__ __half sv1[64][72];
    __shared__ __half sv2[64][72];
    __shared__ float smax[192];
    const int bh = blockIdx.y, b = bh >> 3, h = bh & 7;
    const int i0 = blockIdx.x * 64;
    const int t = threadIdx.x;
    if (t < 192) smax[t] = g_max[bh * 192 + t];
    __syncthreads();

    const int r = t >> 2, d0 = (t & 3) * 16;
    const int i = i0 + r;

    union H16 { __half h[16]; uint4 u[2]; };
    H16 qo, ko;

    if (i < N_) {
        size_t base = (size_t)(b * N_ + i) * QKV_ + h * 64 + d0;
        H16 qi, ki, vi, qmi, kmi, vmi;
        qi.u[0]  = *(const uint4*)&g_qkvh [base];        qi.u[1]  = *(const uint4*)&g_qkvh [base + 8];
        ki.u[0]  = *(const uint4*)&g_qkvh [base + 512];  ki.u[1]  = *(const uint4*)&g_qkvh [base + 520];
        vi.u[0]  = *(const uint4*)&g_qkvh [base + 1024]; vi.u[1]  = *(const uint4*)&g_qkvh [base + 1032];
        qmi.u[0] = *(const uint4*)&g_qkvmh[base];        qmi.u[1] = *(const uint4*)&g_qkvmh[base + 8];
        kmi.u[0] = *(const uint4*)&g_qkvmh[base + 512];  kmi.u[1] = *(const uint4*)&g_qkvmh[base + 520];
        vmi.u[0] = *(const uint4*)&g_qkvmh[base + 1024]; vmi.u[1] = *(const uint4*)&g_qkvmh[base + 1032];
        #pragma unroll
        for (int j = 0; j < 16; j++) {
            int d = d0 + j;
            float qmn = __half2float(qmi.h[j]) / (1e-6f + smax[d]);
            float kmn = __half2float(kmi.h[j]) / (1e-6f + smax[64 + d]);
            float vmn = __half2float(vmi.h[j]) / (1e-6f + smax[128 + d]);
            qo.h[j] = __float2half_rn(__half2float(qi.h[j]) * qmn * SCALE_);
            ko.h[j] = __float2half_rn(__half2float(ki.h[j]) * kmn);
            sv1[r][d] = __float2half_rn(__half2float(vi.h[j]) * vmn);
            sv2[r][d] = __float2half_rn(vmn);
        }
        size_t ob = (size_t)bh * N_ * 64 + (size_t)i * 64 + d0;
        *(uint4*)&g_qh[ob] = qo.u[0];
        *(uint4*)&g_qh[ob + 8] = qo.u[1];
        *(uint4*)&g_kh[ob] = ko.u[0];
        *(uint4*)&g_kh[ob + 8] = ko.u[1];
    } else {
        #pragma unroll
        for (int e = 0; e < 16; e++) {
            sv1[r][d0 + e] = __float2half_rn(0.f);
            sv2[r][d0 + e] = __float2half_rn(0.f);
        }
    }
    __syncthreads();

    const int drow = t >> 2, is0 = (t & 3) * 16;
    H16 o1, o2;
    #pragma unroll
    for (int e = 0; e < 16; e++) {
        o1.h[e] = sv1[is0 + e][drow];
        o2.h[e] = sv2[is0 + e][drow];
    }
    size_t ob = (size_t)bh * 64 * 512 + (size_t)drow * 512 + i0 + is0;
    *(uint4*)&g_vvT[ob] = o1.u[0];
    *(uint4*)&g_vvT[ob + 8] = o1.u[1];
    *(uint4*)&g_vmT[ob] = o2.u[0];
    *(uint4*)&g_vmT[ob + 8] = o2.u[1];
}

// ---------------- overlap blending; emits fp16 out2/m2 + f32 m2 ----------------
__global__ void blend_k()
{
    int idx4 = blockIdx.x * blockDim.x + threadIdx.x;
    if (idx4 >= SZ_BND / 4) return;
    size_t idx = (size_t)idx4 * 4;
    int c = idx % DIM_;
    int i = (idx / DIM_) % N_;
    int b = idx / (DIM_ * (size_t)N_);
    float4 o  = *(const float4*)&g_out[idx];
    float4 mv = *(const float4*)&g_m[idx];

    if (i >= 1 && i <= NHW_) {
        int p = i - 1, y = p >> 4, x = p & 15;
        float inv = 0.25f * (1.0f - g_upd[b * N_ + i]);
        float4 s1 = make_float4(0,0,0,0), s2 = make_float4(0,0,0,0);
        #pragma unroll
        for (int dy = -1; dy <= 0; dy++)
            #pragma unroll
            for (int dx = -1; dx <= 0; dx++) {
                int rr = y + dy, cc = x + dx;
                if (rr >= 0 && rr < 15 && cc >= 0 && cc < 15) {
                    size_t src = ((size_t)(b * N_ + TAIL0_ + rr * 15 + cc)) * DIM_ + c;
                    float4 a = *(const float4*)&g_out[src];
                    float4 e = *(const float4*)&g_m[src];
                    s1.x += a.x; s1.y += a.y; s1.z += a.z; s1.w += a.w;
                    s2.x += e.x; s2.y += e.y; s2.z += e.z; s2.w += e.w;
                }
            }
        o.x += s1.x*inv; o.y += s1.y*inv; o.z += s1.z*inv; o.w += s1.w*inv;
        mv.x += s2.x*inv; mv.y += s2.y*inv; mv.z += s2.z*inv; mv.w += s2.w*inv;
    } else if (i >= TAIL0_) {
        int p = i - TAIL0_, rr = p / 15, cc = p % 15;
        float inv = 0.25f * (1.0f - g_upd[b * N_ + i]);
        float4 s1 = make_float4(0,0,0,0), s2 = make_float4(0,0,0,0);
        #pragma unroll
        for (int dy = 0; dy <= 1; dy++)
            #pragma unroll
            for (int dx = 0; dx <= 1; dx++) {
                size_t src = ((size_t)(b * N_ + 1 + (rr + dy) * 16 + (cc + dx))) * DIM_ + c;
                float4 a = *(const float4*)&g_out[src];
                float4 e = *(const float4*)&g_m[src];
                s1.x += a.x; s1.y += a.y; s1.z += a.z; s1.w += a.w;
                s2.x += e.x; s2.y += e.y; s2.z += e.z; s2.w += e.w;
            }
        o.x += s1.x*inv; o.y += s1.y*inv; o.z += s1.z*inv; o.w += s1.w*inv;
        mv.x += s2.x*inv; mv.y += s2.y*inv; mv.z += s2.z*inv; mv.w += s2.w*inv;
    }
    *(float4*)&g_m2[idx] = mv;
    __half2 ol = __floats2half2_rn(o.x, o.y),  oh = __floats2half2_rn(o.z, o.w);
    __half2 ml = __floats2half2_rn(mv.x, mv.y), mh = __floats2half2_rn(mv.z, mv.w);
    uint2 ou, mu;
    ou.x = *(uint32_t*)&ol; ou.y = *(uint32_t*)&oh;
    mu.x = *(uint32_t*)&ml; mu.y = *(uint32_t*)&mh;
    *(uint2*)&g_o2h[idx] = ou;
    *(uint2*)&g_m2h[idx] = mu;
}

// ---------------- channel means ----------------
__global__ void mm_k()
{
    int row = blockIdx.x * (blockDim.x >> 5) + (threadIdx.x >> 5);
    if (row >= B_ * (N_ - 1)) return;
    int b = row / (N_ - 1), j = row % (N_ - 1);
    int ln = threadIdx.x & 31;
    const float* p = g_m2 + (size_t)(b * N_ + j + 1) * DIM_;
    float s = 0.f;
    #pragma unroll
    for (int e = ln; e < DIM_; e += 32) s += p[e];
    #pragma unroll
    for (int o = 16; o > 0; o >>= 1) s += __shfl_xor_sync(0xffffffffu, s, o);
    if (ln == 0) g_mm[row] = s * (1.0f / DIM_);
}

// ---------------- inter ----------------
__global__ void inter_k(float* __restrict__ outp)
{
    int idx = blockIdx.x * blockDim.x + threadIdx.x;
    if (idx >= B_ * 256 * 256) return;
    int x = idx & 255, y = (idx >> 8) & 255, b = idx >> 16;
    float v = g_mm[b * (N_ - 1) + (y >> 4) * 16 + (x >> 4)];
    if (y >= 8 && y < 248 && x >= 8 && x < 248) {
        float sh = g_mm[b * (N_ - 1) + 256 + ((y - 8) >> 4) * 15 + ((x - 8) >> 4)];
        v = 0.5f * (v + sh);
    }
    outp[idx] = v;
}

// ---------------- launch ----------------
extern "C" void kernel_launch(void* const* d_in, const int* in_sizes, int n_in,
                              void* d_out, int out_size)
{
    const float* x    = (const float*)d_in[0];
    const float* mask = (const float*)d_in[1];
    const float* Wqkv = (const float*)d_in[2];
    const float* Wout = (const float*)d_in[3];
    const float* bout = (const float*)d_in[4];
    float* out = (float*)d_out;

    __half *p_xh, *p_mkh, *p_wqh, *p_wqah, *p_woh, *p_woah, *p_o2h, *p_m2h, *p_qkvh, *p_qkvmh;
    cudaGetSymbolAddress((void**)&p_xh,    g_xh);
    cudaGetSymbolAddress((void**)&p_mkh,   g_mkh);
    cudaGetSymbolAddress((void**)&p_wqh,   g_wqh);
    cudaGetSymbolAddress((void**)&p_wqah,  g_wqah);
    cudaGetSymbolAddress((void**)&p_woh,   g_woh);
    cudaGetSymbolAddress((void**)&p_woah,  g_woah);
    cudaGetSymbolAddress((void**)&p_o2h,   g_o2h);
    cudaGetSymbolAddress((void**)&p_m2h,   g_m2h);
    cudaGetSymbolAddress((void**)&p_qkvh,  g_qkvh);
    cudaGetSymbolAddress((void**)&p_qkvmh, g_qkvmh);

    const int gemm_smem = 4 * GBUF_W * 4;          // 40960 B
    cudaFuncSetAttribute(hgemm<false,true >, cudaFuncAttributeMaxDynamicSharedMemorySize, gemm_smem);
    cudaFuncSetAttribute(hgemm<false,false>, cudaFuncAttributeMaxDynamicSharedMemorySize, gemm_smem);
    cudaFuncSetAttribute(hgemm<true ,false>, cudaFuncAttributeMaxDynamicSharedMemorySize, gemm_smem);
    cudaFuncSetAttribute(flash_attn, cudaFuncAttributeMaxDynamicSharedMemorySize, FA_SMEM_WORDS * 4);

    // 0. fp16 copies
    half_copy1<<<(SZ_BND/4 + 255)/256, 256>>>((const float4*)x,    (uint2*)p_xh,  SZ_BND/4);
    half_copy1<<<(SZ_BND/4 + 255)/256, 256>>>((const float4*)mask, (uint2*)p_mkh, SZ_BND/4);
    half_copy2<<<(QKV_*DIM_/4 + 255)/256, 256>>>((const float4*)Wqkv, (uint2*)p_wqh, (uint2*)p_wqah, QKV_*DIM_/4);
    half_copy2<<<(DIM_*DIM_/4 + 255)/256, 256>>>((const float4*)Wout, (uint2*)p_woh, (uint2*)p_woah, DIM_*DIM_/4);

    // 1-2. qkv projections (fp16 MMA, fp16 out)
    hgemm<false,true><<<dim3(QKV_/128, BN_/128), 256, gemm_smem>>>(p_xh,  p_wqh,  nullptr, p_qkvh,  DIM_, DIM_, DIM_, QKV_);
    hgemm<false,true><<<dim3(QKV_/128, BN_/128), 256, gemm_smem>>>(p_mkh, p_wqah, nullptr, p_qkvmh, DIM_, DIM_, DIM_, QKV_);
    // 3. updated flags
    updated_k<<<(BN_ + 7) / 8, 256>>>(mask);
    // 4. maxima
    reduce_max_k<<<(B_*H_*3*D_ + 255) / 256, 256>>>();
    // 5. modulate
    modulate_k<<<dim3(8, BH_), 256>>>();
    // 6-8. fused attention
    flash_attn<<<dim3(4, BH_), 256, FA_SMEM_WORDS * 4>>>();
    // 9. blending
    blend_k<<<(SZ_BND/4 + 255)/256, 256>>>();
    // 10. channel means
    mm_k<<<(B_ * (N_ - 1) + 7) / 8, 256>>>();
    // 11. inter
    inter_k<<<(B_ * 65536 + 255) / 256, 256>>>(out + 2 * (size_t)SZ_BND);
    // 12-13. final projections (f32 out into d_out)
    hgemm<true ,false><<<dim3(DIM_/128, BN_/128), 256, gemm_smem>>>(p_o2h, p_woh,  bout,    out,                  DIM_, DIM_, DIM_, DIM_);
    hgemm<false,false><<<dim3(DIM_/128, BN_/128), 256, gemm_smem>>>(p_m2h, p_woah, nullptr, out + (size_t)SZ_BND, DIM_, DIM_, DIM_, DIM_);
}

// round 15
// speedup vs baseline: 2.3530x; 1.0425x over previous
#include <cuda_runtime.h>
#include <cuda_fp16.h>
#include <cstdint>

// ---------------- problem constants ----------------
#define B_    64
#define N_    482
#define DIM_  512
#define H_    8
#define D_    64
#define QKV_  1536
#define BH_   (B_*H_)          // 512
#define BN_   (B_*N_)          // 30848
#define SZ_BND (BN_*DIM_)      // 15794176
#define NHW_  256
#define NB_   225
#define TAIL0_ 257
#define SCALE_ 0.125f

// ---------------- device scratch ----------------
__device__ float  g_max [B_*H_*3*D_];
__device__ float  g_upd [BN_];
__device__ float  g_mm  [B_*(N_-1)];
// fp16 tensors
__device__ __half g_xh  [SZ_BND];
__device__ __half g_mkh [SZ_BND];
__device__ __half g_wqh [QKV_*DIM_];
__device__ __half g_wqah[QKV_*DIM_];
__device__ __half g_woh [DIM_*DIM_];
__device__ __half g_woah[DIM_*DIM_];
__device__ __half g_qkvh [(size_t)BN_*QKV_];
__device__ __half g_qkvmh[(size_t)BN_*QKV_];
__device__ __half g_qh  [(size_t)BH_*N_*D_];
__device__ __half g_kh  [(size_t)BH_*N_*D_];
__device__ __half g_vvT [(size_t)BH_*64*512];   // [bh][d][j], zero-padded cols
__device__ __half g_vmT [(size_t)BH_*64*512];
__device__ __half g_outh[SZ_BND];
__device__ __half g_mh  [SZ_BND];
__device__ __half g_o2h [SZ_BND];
__device__ __half g_m2h [SZ_BND];

// ---------------- helpers ----------------
__device__ __forceinline__ void mma_f16(float* c, const uint32_t* a, const uint32_t* b) {
    asm volatile("mma.sync.aligned.m16n8k16.row.col.f32.f16.f16.f32 "
        "{%0,%1,%2,%3}, {%4,%5,%6,%7}, {%8,%9}, {%0,%1,%2,%3};"
        : "+f"(c[0]), "+f"(c[1]), "+f"(c[2]), "+f"(c[3])
        : "r"(a[0]), "r"(a[1]), "r"(a[2]), "r"(a[3]), "r"(b[0]), "r"(b[1]));
}
__device__ __forceinline__ void ldm4(uint32_t* r, uint32_t addr) {
    asm volatile("ldmatrix.sync.aligned.m8n8.x4.shared.b16 {%0,%1,%2,%3}, [%4];"
        : "=r"(r[0]), "=r"(r[1]), "=r"(r[2]), "=r"(r[3]) : "r"(addr));
}
__device__ __forceinline__ uint32_t smem_u32(const void* p) {
    return (uint32_t)__cvta_generic_to_shared(p);
}
__device__ __forceinline__ void cp16(uint32_t dst, const void* src, int sz) {
    asm volatile("cp.async.cg.shared.global [%0], [%1], 16, %2;" :: "r"(dst), "l"(src), "r"(sz));
}
#define CP_COMMIT() asm volatile("cp.async.commit_group;")
#define CP_WAIT(n)  asm volatile("cp.async.wait_group %0;" :: "n"(n))
__device__ __forceinline__ float4 ld_h4(const __half* p) {
    uint2 u = *(const uint2*)p;
    __half2 a = *(__half2*)&u.x, b = *(__half2*)&u.y;
    float2 fa = __half22float2(a), fb = __half22float2(b);
    return make_float4(fa.x, fa.y, fb.x, fb.y);
}

extern __shared__ uint32_t s_dyn[];

// ---------------- prep kernels ----------------
__global__ void half_copy1(const float4* __restrict__ src, uint2* __restrict__ dst, int n4)
{
    int i = blockIdx.x * blockDim.x + threadIdx.x;
    if (i >= n4) return;
    float4 v = src[i];
    __half2 lo = __floats2half2_rn(v.x, v.y);
    __half2 hi = __floats2half2_rn(v.z, v.w);
    uint2 r; r.x = *(uint32_t*)&lo; r.y = *(uint32_t*)&hi;
    dst[i] = r;
}
__global__ void half_copy2(const float4* __restrict__ src, uint2* __restrict__ dstp,
                           uint2* __restrict__ dsta, int n4)
{
    int i = blockIdx.x * blockDim.x + threadIdx.x;
    if (i >= n4) return;
    float4 v = src[i];
    __half2 lo = __floats2half2_rn(v.x, v.y);
    __half2 hi = __floats2half2_rn(v.z, v.w);
    uint2 r; r.x = *(uint32_t*)&lo; r.y = *(uint32_t*)&hi;
    dstp[i] = r;
    r.x &= 0x7fff7fffu; r.y &= 0x7fff7fffu;
    dsta[i] = r;
}
// fused: mask -> fp16 copy + updated flag (warp per row, mask read ONCE)
__global__ void mask_prep(const float* __restrict__ mask)
{
    int row = blockIdx.x * (blockDim.x >> 5) + (threadIdx.x >> 5);
    if (row >= BN_) return;
    int ln = threadIdx.x & 31;
    const float4* p = (const float4*)(mask + (size_t)row * DIM_);
    uint2* dst = (uint2*)(g_mkh + (size_t)row * DIM_);
    float s = 0.f;
    #pragma unroll
    for (int e = 0; e < 4; e++) {
        int c4 = ln + e * 32;
        float4 v = p[c4];
        s += v.x + v.y + v.z + v.w;
        __half2 lo = __floats2half2_rn(v.x, v.y);
        __half2 hi = __floats2half2_rn(v.z, v.w);
        uint2 r; r.x = *(uint32_t*)&lo; r.y = *(uint32_t*)&hi;
        dst[c4] = r;
    }
    #pragma unroll
    for (int o = 16; o > 0; o >>= 1) s += __shfl_xor_sync(0xffffffffu, s, o);
    if (ln == 0) {
        int i = row % N_;
        g_upd[row] = (i == 0) ? 1.0f : (s > 0.0f ? 1.0f : 0.0f);
    }
}

// ================= fp16 NT GEMM (m16n8k16, ldmatrix), 128x128 tile =================
#define GBUF_W 2560   // words per tile buffer: 128 rows * 20 words (40 halfs)
template<bool BIAS, bool HOUT>
__global__ void __launch_bounds__(256, 2) hgemm(const __half* __restrict__ A,
                                                const __half* __restrict__ Bm,
                                                const float* __restrict__ bias,
                                                void* __restrict__ Cv,
                                                int K, int lda, int ldb, int ldc)
{
    uint32_t* AsB = s_dyn;               // [2][2560]
    uint32_t* BsB = s_dyn + 2 * GBUF_W;  // [2][2560]
    const int tid = threadIdx.x;
    const int bm = blockIdx.y * 128, bn = blockIdx.x * 128;
    const int lane = tid & 31, wid = tid >> 5;
    const int gr = lane >> 2, gc = lane & 3;
    const int wm = (wid & 1) * 64, wn = (wid >> 1) * 32;
    const int a_row = (lane & 7) + ((lane >> 3) & 1) * 8;
    const int a_col = (lane >> 4) * 4;
    const int b_row = (lane & 7) + ((lane >> 4) & 1) * 8;
    const int b_col = ((lane >> 3) & 1) * 4;

    float acc[4][4][4];
    #pragma unroll
    for (int i = 0; i < 4; i++)
        #pragma unroll
        for (int j = 0; j < 4; j++)
            #pragma unroll
            for (int e = 0; e < 4; e++) acc[i][j][e] = 0.f;

    const int nslab = K >> 5;
    const int r0s = tid >> 2, s0s = tid & 3;
    const int r1s = 64 + (tid >> 2);
    {
        cp16(smem_u32(&AsB[r0s*20 + s0s*4]), A + (size_t)(bm + r0s) * lda + s0s*8, 16);
        cp16(smem_u32(&AsB[r1s*20 + s0s*4]), A + (size_t)(bm + r1s) * lda + s0s*8, 16);
        cp16(smem_u32(&BsB[r0s*20 + s0s*4]), Bm + (size_t)(bn + r0s) * ldb + s0s*8, 16);
        cp16(smem_u32(&BsB[r1s*20 + s0s*4]), Bm + (size_t)(bn + r1s) * ldb + s0s*8, 16);
        CP_COMMIT();
    }
    for (int s = 0; s < nslab; s++) {
        if (s + 1 < nslab) {
            uint32_t* As = AsB + ((s+1) & 1) * GBUF_W;
            uint32_t* Bs = BsB + ((s+1) & 1) * GBUF_W;
            int kt = (s + 1) * 32;
            cp16(smem_u32(&As[r0s*20 + s0s*4]), A + (size_t)(bm + r0s) * lda + kt + s0s*8, 16);
            cp16(smem_u32(&As[r1s*20 + s0s*4]), A + (size_t)(bm + r1s) * lda + kt + s0s*8, 16);
            cp16(smem_u32(&Bs[r0s*20 + s0s*4]), Bm + (size_t)(bn + r0s) * ldb + kt + s0s*8, 16);
            cp16(smem_u32(&Bs[r1s*20 + s0s*4]), Bm + (size_t)(bn + r1s) * ldb + kt + s0s*8, 16);
            CP_COMMIT();
            CP_WAIT(1);
        } else {
            CP_WAIT(0);
        }
        __syncthreads();

        const uint32_t* As = AsB + (s & 1) * GBUF_W;
        const uint32_t* Bs = BsB + (s & 1) * GBUF_W;
        #pragma unroll
        for (int ks = 0; ks < 2; ks++) {
            const int kw = ks * 8;
            uint32_t ah[4][4];
            #pragma unroll
            for (int mt = 0; mt < 4; mt++)
                ldm4(ah[mt], smem_u32(&As[(wm + mt*16 + a_row) * 20 + kw + a_col]));
            #pragma unroll
            for (int p = 0; p < 2; p++) {
                uint32_t t[4];
                ldm4(t, smem_u32(&Bs[(wn + p*16 + b_row) * 20 + kw + b_col]));
                #pragma unroll
                for (int mt = 0; mt < 4; mt++) {
                    mma_f16(acc[mt][2*p    ], ah[mt], t);
                    mma_f16(acc[mt][2*p + 1], ah[mt], t + 2);
                }
            }
        }
        __syncthreads();
    }
    #pragma unroll
    for (int mt = 0; mt < 4; mt++)
        #pragma unroll
        for (int nt = 0; nt < 4; nt++) {
            int m0 = bm + wm + mt * 16 + gr;
            int n0 = bn + wn + nt * 8 + gc * 2;
            float bx = 0.f, by = 0.f;
            if (BIAS) { bx = bias[n0]; by = bias[n0 + 1]; }
            if (HOUT) {
                __half* C = (__half*)Cv;
                __half2 v0 = __floats2half2_rn(acc[mt][nt][0], acc[mt][nt][1]);
                __half2 v1 = __floats2half2_rn(acc[mt][nt][2], acc[mt][nt][3]);
                *(uint32_t*)&C[(size_t)m0 * ldc + n0]       = *(uint32_t*)&v0;
                *(uint32_t*)&C[(size_t)(m0 + 8) * ldc + n0] = *(uint32_t*)&v1;
            } else {
                float* C = (float*)Cv;
                *(float2*)&C[(size_t)m0 * ldc + n0] = make_float2(acc[mt][nt][0] + bx, acc[mt][nt][1] + by);
                *(float2*)&C[(size_t)(m0 + 8) * ldc + n0] = make_float2(acc[mt][nt][2] + bx, acc[mt][nt][3] + by);
            }
        }
}

// ================= fp16 flash attention (ldmatrix) =================
#define KT_W    2304     // 64 rows * 36 words (72 halfs)
#define V1_OFF  (2*KT_W)
#define V2_OFF  (4*KT_W)
#define PQ_OFF  (6*KT_W)
#define FA_SMEM_WORDS (PQ_OFF + 128*36)

__global__ void __launch_bounds__(256, 1) flash_attn()
{
    const int bh = blockIdx.y;
    const int b = bh >> 3, h = bh & 7;
    const int i0 = blockIdx.x * 128;
    const __half* Q   = g_qh  + (size_t)bh * N_ * D_;
    const __half* Kp  = g_kh  + (size_t)bh * N_ * D_;
    const __half* V1g = g_vvT + (size_t)bh * 64 * 512;
    const __half* V2g = g_vmT + (size_t)bh * 64 * 512;
    uint32_t* PQ = s_dyn + PQ_OFF;

    const int tid = threadIdx.x;
    const int lane = tid & 31, wid = tid >> 5;
    const int gr = lane >> 2, gc = lane & 3;
    const int rbase = wid * 16;
    const int a_row = (lane & 7) + ((lane >> 3) & 1) * 8;
    const int a_col = (lane >> 4) * 4;
    const int b_row = (lane & 7) + ((lane >> 4) & 1) * 8;
    const int b_col = ((lane >> 3) & 1) * 4;

    {
        #pragma unroll
        for (int e = 0; e < 4; e++) {
            int chunk = tid + e * 256;
            int row = chunk >> 3, seg = chunk & 7;
            int gi = i0 + row;
            uint4 q = make_uint4(0u,0u,0u,0u);
            if (gi < N_) q = *(const uint4*)(Q + (size_t)gi * D_ + seg * 8);
            *(uint4*)&PQ[row * 36 + seg * 4] = q;
        }
    }
    __syncthreads();
    uint32_t qf[4][4];
    #pragma unroll
    for (int ks = 0; ks < 4; ks++)
        ldm4(qf[ks], smem_u32(&PQ[(rbase + a_row) * 36 + ks*8 + a_col]));
    __syncthreads();

    float acc1[8][4], acc2[8][4];
    #pragma unroll
    for (int nt = 0; nt < 8; nt++)
        #pragma unroll
        for (int e = 0; e < 4; e++) { acc1[nt][e] = 0.f; acc2[nt][e] = 0.f; }
    float rmax0 = -1e30f, rmax1 = -1e30f, rsum0 = 0.f, rsum1 = 0.f;

    const int ntiles = (N_ + 63) / 64;   // 8
    {
        #pragma unroll
        for (int e = 0; e < 2; e++) {
            int chunk = tid + e * 256;
            int row = chunk >> 3, seg = chunk & 7;
            int j = row;
            int sz = (j < N_) ? 16 : 0;
            cp16(smem_u32(&s_dyn[row*36 + seg*4]), Kp + (size_t)(sz ? j : 0) * D_ + seg*8, sz);
            cp16(smem_u32(&s_dyn[V1_OFF + row*36 + seg*4]), V1g + (size_t)row * 512 + seg*8, 16);
            cp16(smem_u32(&s_dyn[V2_OFF + row*36 + seg*4]), V2g + (size_t)row * 512 + seg*8, 16);
        }
        CP_COMMIT();
    }

    for (int t = 0; t < ntiles; t++) {
        const int j0 = t * 64;
        if (t + 1 < ntiles) {
            int buf = (t + 1) & 1;
            int jb = j0 + 64;
            #pragma unroll
            for (int e = 0; e < 2; e++) {
                int chunk = tid + e * 256;
                int row = chunk >> 3, seg = chunk & 7;
                int j = jb + row;
                int sz = (j < N_) ? 16 : 0;
                cp16(smem_u32(&s_dyn[buf*KT_W + row*36 + seg*4]), Kp + (size_t)(sz ? j : 0) * D_ + seg*8, sz);
                cp16(smem_u32(&s_dyn[V1_OFF + buf*KT_W + row*36 + seg*4]), V1g + (size_t)row * 512 + jb + seg*8, 16);
                cp16(smem_u32(&s_dyn[V2_OFF + buf*KT_W + row*36 + seg*4]), V2g + (size_t)row * 512 + jb + seg*8, 16);
            }
            CP_COMMIT();
            CP_WAIT(1);
        } else {
            CP_WAIT(0);
        }
        __syncthreads();

        const uint32_t* Kt = s_dyn + (t & 1) * KT_W;
        const uint32_t* V1 = s_dyn + V1_OFF + (t & 1) * KT_W;
        const uint32_t* V2 = s_dyn + V2_OFF + (t & 1) * KT_W;

        float sacc[8][4];
        #pragma unroll
        for (int nt = 0; nt < 8; nt++)
            #pragma unroll
            for (int e = 0; e < 4; e++) sacc[nt][e] = 0.f;
        #pragma unroll
        for (int ks = 0; ks < 4; ks++) {
            #pragma unroll
            for (int p = 0; p < 4; p++) {
                uint32_t tkt[4];
                ldm4(tkt, smem_u32(&Kt[(p*16 + b_row) * 36 + ks*8 + b_col]));
                mma_f16(sacc[2*p    ], qf[ks], tkt);
                mma_f16(sacc[2*p + 1], qf[ks], tkt + 2);
            }
        }
        if (j0 + 64 > N_) {
            #pragma unroll
            for (int nt = 0; nt < 8; nt++) {
                int cc = j0 + nt*8 + gc*2;
                if (cc     >= N_) { sacc[nt][0] = -1e30f; sacc[nt][2] = -1e30f; }
                if (cc + 1 >= N_) { sacc[nt][1] = -1e30f; sacc[nt][3] = -1e30f; }
            }
        }
        float tm0 = -1e30f, tm1 = -1e30f;
        #pragma unroll
        for (int nt = 0; nt < 8; nt++) {
            tm0 = fmaxf(tm0, fmaxf(sacc[nt][0], sacc[nt][1]));
            tm1 = fmaxf(tm1, fmaxf(sacc[nt][2], sacc[nt][3]));
        }
        tm0 = fmaxf(tm0, __shfl_xor_sync(0xffffffffu, tm0, 1));
        tm0 = fmaxf(tm0, __shfl_xor_sync(0xffffffffu, tm0, 2));
        tm1 = fmaxf(tm1, __shfl_xor_sync(0xffffffffu, tm1, 1));
        tm1 = fmaxf(tm1, __shfl_xor_sync(0xffffffffu, tm1, 2));
        float nm0 = fmaxf(rmax0, tm0), nm1 = fmaxf(rmax1, tm1);
        float sc0 = __expf(rmax0 - nm0), sc1 = __expf(rmax1 - nm1);
        rmax0 = nm0; rmax1 = nm1;
        float ps0 = 0.f, ps1 = 0.f;
        __half2* PQh = (__half2*)PQ;
        #pragma unroll
        for (int nt = 0; nt < 8; nt++) {
            float p00 = __expf(sacc[nt][0] - nm0);
            float p01 = __expf(sacc[nt][1] - nm0);
            float p10 = __expf(sacc[nt][2] - nm1);
            float p11 = __expf(sacc[nt][3] - nm1);
            ps0 += p00 + p01; ps1 += p10 + p11;
            PQh[(rbase + gr    ) * 36 + nt*4 + gc] = __floats2half2_rn(p00, p01);
            PQh[(rbase + gr + 8) * 36 + nt*4 + gc] = __floats2half2_rn(p10, p11);
            acc1[nt][0] *= sc0; acc1[nt][1] *= sc0; acc1[nt][2] *= sc1; acc1[nt][3] *= sc1;
            acc2[nt][0] *= sc0; acc2[nt][1] *= sc0; acc2[nt][2] *= sc1; acc2[nt][3] *= sc1;
        }
        ps0 += __shfl_xor_sync(0xffffffffu, ps0, 1);
        ps0 += __shfl_xor_sync(0xffffffffu, ps0, 2);
        ps1 += __shfl_xor_sync(0xffffffffu, ps1, 1);
        ps1 += __shfl_xor_sync(0xffffffffu, ps1, 2);
        rsum0 = rsum0 * sc0 + ps0;
        rsum1 = rsum1 * sc1 + ps1;
        __syncwarp();

        #pragma unroll
        for (int ks = 0; ks < 4; ks++) {
            uint32_t af[4];
            ldm4(af, smem_u32(&PQ[(rbase + a_row) * 36 + ks*8 + a_col]));
            #pragma unroll
            for (int p = 0; p < 4; p++) {
                uint32_t t1[4], t2[4];
                ldm4(t1, smem_u32(&V1[(p*16 + b_row) * 36 + ks*8 + b_col]));
                ldm4(t2, smem_u32(&V2[(p*16 + b_row) * 36 + ks*8 + b_col]));
                mma_f16(acc1[2*p    ], af, t1);
                mma_f16(acc1[2*p + 1], af, t1 + 2);
                mma_f16(acc2[2*p    ], af, t2);
                mma_f16(acc2[2*p + 1], af, t2 + 2);
            }
        }
        __syncthreads();
    }

    // ---- epilogue (fp16 out) ----
    float inv0 = 1.0f / rsum0, inv1 = 1.0f / rsum1;
    int gi0 = i0 + rbase + gr, gi1 = gi0 + 8;
    if (gi0 < N_) {
        float f = inv0 * g_upd[b * N_ + gi0];
        size_t base = (size_t)(b * N_ + gi0) * DIM_ + h * 64;
        #pragma unroll
        for (int nt = 0; nt < 8; nt++) {
            int d = nt*8 + gc*2;
            __half2 h1 = __floats2half2_rn(acc1[nt][0]*f, acc1[nt][1]*f);
            __half2 h2 = __floats2half2_rn(acc2[nt][0]*f, acc2[nt][1]*f);
            *(uint32_t*)&g_outh[base + d] = *(uint32_t*)&h1;
            *(uint32_t*)&g_mh  [base + d] = *(uint32_t*)&h2;
        }
    }
    if (gi1 < N_) {
        float f = inv1 * g_upd[b * N_ + gi1];
        size_t base = (size_t)(b * N_ + gi1) * DIM_ + h * 64;
        #pragma unroll
        for (int nt = 0; nt < 8; nt++) {
            int d = nt*8 + gc*2;
            __half2 h1 = __floats2half2_rn(acc1[nt][2]*f, acc1[nt][3]*f);
            __half2 h2 = __floats2half2_rn(acc2[nt][2]*f, acc2[nt][3]*f);
            *(uint32_t*)&g_outh[base + d] = *(uint32_t*)&h1;
            *(uint32_t*)&g_mh  [base + d] = *(uint32_t*)&h2;
        }
    }
}

// ---------------- per-(bh,w,d) max over sequence (fp16 input) ----------------
__global__ void reduce_max_k()
{
    int o = blockIdx.x * blockDim.x + threadIdx.x;
    if (o >= B_*H_*3*D_) return;
    int d = o & 63;
    int w = (o >> 6) % 3;
    int h = ((o >> 6) / 3) % H_;
    int b = (o >> 6) / 24;
    const __half* p = g_qkvmh + (size_t)b * N_ * QKV_ + w * DIM_ + h * 64 + d;
    float mx = -1e30f;
    for (int i = 0; i < N_; i++) mx = fmaxf(mx, __half2float(p[(size_t)i * QKV_]));
    g_max[((b * H_ + h) * 3 + w) * 64 + d] = mx;
}

// ---------------- modulate: fp16 in, fp16 q/k + transposed v/vm out ----------------
__global__ void __launch_bounds__(256) modulate_k()
{
    __shared__ __half sv1[64][72];
    __shared__ __half sv2[64][72];
    __shared__ float smax[192];
    const int bh = blockIdx.y, b = bh >> 3, h = bh & 7;
    const int i0 = blockIdx.x * 64;
    const int t = threadIdx.x;
    if (t < 192) smax[t] = g_max[bh * 192 + t];
    __syncthreads();

    const int r = t >> 2, d0 = (t & 3) * 16;
    const int i = i0 + r;

    union H16 { __half h[16]; uint4 u[2]; };
    H16 qo, ko;

    if (i < N_) {
        size_t base = (size_t)(b * N_ + i) * QKV_ + h * 64 + d0;
        H16 qi, ki, vi, qmi, kmi, vmi;
        qi.u[0]  = *(const uint4*)&g_qkvh [base];        qi.u[1]  = *(const uint4*)&g_qkvh [base + 8];
        ki.u[0]  = *(const uint4*)&g_qkvh [base + 512];  ki.u[1]  = *(const uint4*)&g_qkvh [base + 520];
        vi.u[0]  = *(const uint4*)&g_qkvh [base + 1024]; vi.u[1]  = *(const uint4*)&g_qkvh [base + 1032];
        qmi.u[0] = *(const uint4*)&g_qkvmh[base];        qmi.u[1] = *(const uint4*)&g_qkvmh[base + 8];
        kmi.u[0] = *(const uint4*)&g_qkvmh[base + 512];  kmi.u[1] = *(const uint4*)&g_qkvmh[base + 520];
        vmi.u[0] = *(const uint4*)&g_qkvmh[base + 1024]; vmi.u[1] = *(const uint4*)&g_qkvmh[base + 1032];
        #pragma unroll
        for (int j = 0; j < 16; j++) {
            int d = d0 + j;
            float qmn = __half2float(qmi.h[j]) / (1e-6f + smax[d]);
            float kmn = __half2float(kmi.h[j]) / (1e-6f + smax[64 + d]);
            float vmn = __half2float(vmi.h[j]) / (1e-6f + smax[128 + d]);
            qo.h[j] = __float2half_rn(__half2float(qi.h[j]) * qmn * SCALE_);
            ko.h[j] = __float2half_rn(__half2float(ki.h[j]) * kmn);
            sv1[r][d] = __float2half_rn(__half2float(vi.h[j]) * vmn);
            sv2[r][d] = __float2half_rn(vmn);
        }
        size_t ob = (size_t)bh * N_ * 64 + (size_t)i * 64 + d0;
        *(uint4*)&g_qh[ob] = qo.u[0];
        *(uint4*)&g_qh[ob + 8] = qo.u[1];
        *(uint4*)&g_kh[ob] = ko.u[0];
        *(uint4*)&g_kh[ob + 8] = ko.u[1];
    } else {
        #pragma unroll
        for (int e = 0; e < 16; e++) {
            sv1[r][d0 + e] = __float2half_rn(0.f);
            sv2[r][d0 + e] = __float2half_rn(0.f);
        }
    }
    __syncthreads();

    const int drow = t >> 2, is0 = (t & 3) * 16;
    H16 o1, o2;
    #pragma unroll
    for (int e = 0; e < 16; e++) {
        o1.h[e] = sv1[is0 + e][drow];
        o2.h[e] = sv2[is0 + e][drow];
    }
    size_t ob = (size_t)bh * 64 * 512 + (size_t)drow * 512 + i0 + is0;
    *(uint4*)&g_vvT[ob] = o1.u[0];
    *(uint4*)&g_vvT[ob + 8] = o1.u[1];
    *(uint4*)&g_vmT[ob] = o2.u[0];
    *(uint4*)&g_vmT[ob + 8] = o2.u[1];
}

// ---------------- overlap blending (fp16 in/out) ----------------
__global__ void blend_k()
{
    int idx4 = blockIdx.x * blockDim.x + threadIdx.x;
    if (idx4 >= SZ_BND / 4) return;
    size_t idx = (size_t)idx4 * 4;
    int c = idx % DIM_;
    int i = (idx / DIM_) % N_;
    int b = idx / (DIM_ * (size_t)N_);
    float4 o  = ld_h4(&g_outh[idx]);
    float4 mv = ld_h4(&g_mh[idx]);

    if (i >= 1 && i <= NHW_) {
        int p = i - 1, y = p >> 4, x = p & 15;
        float inv = 0.25f * (1.0f - g_upd[b * N_ + i]);
        float4 s1 = make_float4(0,0,0,0), s2 = make_float4(0,0,0,0);
        #pragma unroll
        for (int dy = -1; dy <= 0; dy++)
            #pragma unroll
            for (int dx = -1; dx <= 0; dx++) {
                int rr = y + dy, cc = x + dx;
                if (rr >= 0 && rr < 15 && cc >= 0 && cc < 15) {
                    size_t src = ((size_t)(b * N_ + TAIL0_ + rr * 15 + cc)) * DIM_ + c;
                    float4 a = ld_h4(&g_outh[src]);
                    float4 e = ld_h4(&g_mh[src]);
                    s1.x += a.x; s1.y += a.y; s1.z += a.z; s1.w += a.w;
                    s2.x += e.x; s2.y += e.y; s2.z += e.z; s2.w += e.w;
                }
            }
        o.x += s1.x*inv; o.y += s1.y*inv; o.z += s1.z*inv; o.w += s1.w*inv;
        mv.x += s2.x*inv; mv.y += s2.y*inv; mv.z += s2.z*inv; mv.w += s2.w*inv;
    } else if (i >= TAIL0_) {
        int p = i - TAIL0_, rr = p / 15, cc = p % 15;
        float inv = 0.25f * (1.0f - g_upd[b * N_ + i]);
        float4 s1 = make_float4(0,0,0,0), s2 = make_float4(0,0,0,0);
        #pragma unroll
        for (int dy = 0; dy <= 1; dy++)
            #pragma unroll
            for (int dx = 0; dx <= 1; dx++) {
                size_t src = ((size_t)(b * N_ + 1 + (rr + dy) * 16 + (cc + dx))) * DIM_ + c;
                float4 a = ld_h4(&g_outh[src]);
                float4 e = ld_h4(&g_mh[src]);
                s1.x += a.x; s1.y += a.y; s1.z += a.z; s1.w += a.w;
                s2.x += e.x; s2.y += e.y; s2.z += e.z; s2.w += e.w;
            }
        o.x += s1.x*inv; o.y += s1.y*inv; o.z += s1.z*inv; o.w += s1.w*inv;
        mv.x += s2.x*inv; mv.y += s2.y*inv; mv.z += s2.z*inv; mv.w += s2.w*inv;
    }
    __half2 ol = __floats2half2_rn(o.x, o.y),  oh = __floats2half2_rn(o.z, o.w);
    __half2 ml = __floats2half2_rn(mv.x, mv.y), mh = __floats2half2_rn(mv.z, mv.w);
    uint2 ou, mu;
    ou.x = *(uint32_t*)&ol; ou.y = *(uint32_t*)&oh;
    mu.x = *(uint32_t*)&ml; mu.y = *(uint32_t*)&mh;
    *(uint2*)&g_o2h[idx] = ou;
    *(uint2*)&g_m2h[idx] = mu;
}

// ---------------- channel means (fp16 input) ----------------
__global__ void mm_k()
{
    int row = blockIdx.x * (blockDim.x >> 5) + (threadIdx.x >> 5);
    if (row >= B_ * (N_ - 1)) return;
    int b = row / (N_ - 1), j = row % (N_ - 1);
    int ln = threadIdx.x & 31;
    const __half2* p = (const __half2*)(g_m2h + (size_t)(b * N_ + j + 1) * DIM_);
    float s = 0.f;
    #pragma unroll
    for (int e = 0; e < 8; e++) {
        float2 v = __half22float2(p[ln + e * 32]);
        s += v.x + v.y;
    }
    #pragma unroll
    for (int o = 16; o > 0; o >>= 1) s += __shfl_xor_sync(0xffffffffu, s, o);
    if (ln == 0) g_mm[row] = s * (1.0f / DIM_);
}

// ---------------- inter ----------------
__global__ void inter_k(float* __restrict__ outp)
{
    int idx = blockIdx.x * blockDim.x + threadIdx.x;
    if (idx >= B_ * 256 * 256) return;
    int x = idx & 255, y = (idx >> 8) & 255, b = idx >> 16;
    float v = g_mm[b * (N_ - 1) + (y >> 4) * 16 + (x >> 4)];
    if (y >= 8 && y < 248 && x >= 8 && x < 248) {
        float sh = g_mm[b * (N_ - 1) + 256 + ((y - 8) >> 4) * 15 + ((x - 8) >> 4)];
        v = 0.5f * (v + sh);
    }
    outp[idx] = v;
}

// ---------------- launch ----------------
extern "C" void kernel_launch(void* const* d_in, const int* in_sizes, int n_in,
                              void* d_out, int out_size)
{
    const float* x    = (const float*)d_in[0];
    const float* mask = (const float*)d_in[1];
    const float* Wqkv = (const float*)d_in[2];
    const float* Wout = (const float*)d_in[3];
    const float* bout = (const float*)d_in[4];
    float* out = (float*)d_out;

    __half *p_xh, *p_wqh, *p_wqah, *p_woh, *p_woah, *p_o2h, *p_m2h, *p_qkvh, *p_qkvmh, *p_mkh;
    cudaGetSymbolAddress((void**)&p_xh,    g_xh);
    cudaGetSymbolAddress((void**)&p_mkh,   g_mkh);
    cudaGetSymbolAddress((void**)&p_wqh,   g_wqh);
    cudaGetSymbolAddress((void**)&p_wqah,  g_wqah);
    cudaGetSymbolAddress((void**)&p_woh,   g_woh);
    cudaGetSymbolAddress((void**)&p_woah,  g_woah);
    cudaGetSymbolAddress((void**)&p_o2h,   g_o2h);
    cudaGetSymbolAddress((void**)&p_m2h,   g_m2h);
    cudaGetSymbolAddress((void**)&p_qkvh,  g_qkvh);
    cudaGetSymbolAddress((void**)&p_qkvmh, g_qkvmh);

    const int gemm_smem = 4 * GBUF_W * 4;          // 40960 B
    cudaFuncSetAttribute(hgemm<false,true >, cudaFuncAttributeMaxDynamicSharedMemorySize, gemm_smem);
    cudaFuncSetAttribute(hgemm<false,false>, cudaFuncAttributeMaxDynamicSharedMemorySize, gemm_smem);
    cudaFuncSetAttribute(hgemm<true ,false>, cudaFuncAttributeMaxDynamicSharedMemorySize, gemm_smem);
    cudaFuncSetAttribute(flash_attn, cudaFuncAttributeMaxDynamicSharedMemorySize, FA_SMEM_WORDS * 4);

    // 0. fp16 copies + fused mask prep
    half_copy1<<<(SZ_BND/4 + 255)/256, 256>>>((const float4*)x, (uint2*)p_xh, SZ_BND/4);
    mask_prep<<<(BN_ + 7) / 8, 256>>>(mask);
    half_copy2<<<(QKV_*DIM_/4 + 255)/256, 256>>>((const float4*)Wqkv, (uint2*)p_wqh, (uint2*)p_wqah, QKV_*DIM_/4);
    half_copy2<<<(DIM_*DIM_/4 + 255)/256, 256>>>((const float4*)Wout, (uint2*)p_woh, (uint2*)p_woah, DIM_*DIM_/4);

    // 1-2. qkv projections (fp16 MMA, fp16 out)
    hgemm<false,true><<<dim3(QKV_/128, BN_/128), 256, gemm_smem>>>(p_xh,  p_wqh,  nullptr, p_qkvh,  DIM_, DIM_, DIM_, QKV_);
    hgemm<false,true><<<dim3(QKV_/128, BN_/128), 256, gemm_smem>>>(p_mkh, p_wqah, nullptr, p_qkvmh, DIM_, DIM_, DIM_, QKV_);
    // 3. maxima
    reduce_max_k<<<(B_*H_*3*D_ + 255) / 256, 256>>>();
    // 4. modulate
    modulate_k<<<dim3(8, BH_), 256>>>();
    // 5-7. fused attention (fp16 out/m)
    flash_attn<<<dim3(4, BH_), 256, FA_SMEM_WORDS * 4>>>();
    // 8. blending (fp16 in, fp16 out)
    blend_k<<<(SZ_BND/4 + 255)/256, 256>>>();
    // 9. channel means (fp16 in)
    mm_k<<<(B_ * (N_ - 1) + 7) / 8, 256>>>();
    // 10. inter
    inter_k<<<(B_ * 65536 + 255) / 256, 256>>>(out + 2 * (size_t)SZ_BND);
    // 11-12. final projections (f32 out into d_out)
    hgemm<true ,false><<<dim3(DIM_/128, BN_/128), 256, gemm_smem>>>(p_o2h, p_woh,  bout,    out,                  DIM_, DIM_, DIM_, DIM_);
    hgemm<false,false><<<dim3(DIM_/128, BN_/128), 256, gemm_smem>>>(p_m2h, p_woah, nullptr, out + (size_t)SZ_BND, DIM_, DIM_, DIM_, DIM_);
}

// round 16
// speedup vs baseline: 2.5171x; 1.0697x over previous
#include <cuda_runtime.h>
#include <cuda_fp16.h>
#include <cstdint>

// ---------------- problem constants ----------------
#define B_    64
#define N_    482
#define DIM_  512
#define H_    8
#define D_    64
#define QKV_  1536
#define BH_   (B_*H_)          // 512
#define BN_   (B_*N_)          // 30848
#define SZ_BND (BN_*DIM_)      // 15794176
#define NHW_  256
#define NB_   225
#define TAIL0_ 257
#define SCALE_ 0.125f

// ---------------- device scratch ----------------
__device__ float  g_max [B_*H_*3*D_];
__device__ float  g_upd [BN_];
__device__ float  g_mm  [B_*(N_-1)];
// fp16 tensors
__device__ __half g_xh  [SZ_BND];
__device__ __half g_mkh [SZ_BND];
__device__ __half g_wqh [QKV_*DIM_];
__device__ __half g_wqah[QKV_*DIM_];
__device__ __half g_woh [DIM_*DIM_];
__device__ __half g_woah[DIM_*DIM_];
__device__ __half g_qkvh [(size_t)BN_*QKV_];
__device__ __half g_qkvmh[(size_t)BN_*QKV_];
__device__ __half g_qh  [(size_t)BH_*N_*D_];
__device__ __half g_kh  [(size_t)BH_*N_*D_];
__device__ __half g_vvT [(size_t)BH_*64*512];   // [bh][d][j], zero-padded cols
__device__ __half g_vmT [(size_t)BH_*64*512];
__device__ __half g_outh[SZ_BND];
__device__ __half g_mh  [SZ_BND];
__device__ __half g_o2h [SZ_BND];
__device__ __half g_m2h [SZ_BND];

// ---------------- helpers ----------------
__device__ __forceinline__ void mma_f16(float* c, const uint32_t* a, const uint32_t* b) {
    asm volatile("mma.sync.aligned.m16n8k16.row.col.f32.f16.f16.f32 "
        "{%0,%1,%2,%3}, {%4,%5,%6,%7}, {%8,%9}, {%0,%1,%2,%3};"
        : "+f"(c[0]), "+f"(c[1]), "+f"(c[2]), "+f"(c[3])
        : "r"(a[0]), "r"(a[1]), "r"(a[2]), "r"(a[3]), "r"(b[0]), "r"(b[1]));
}
__device__ __forceinline__ void ldm4(uint32_t* r, uint32_t addr) {
    asm volatile("ldmatrix.sync.aligned.m8n8.x4.shared.b16 {%0,%1,%2,%3}, [%4];"
        : "=r"(r[0]), "=r"(r[1]), "=r"(r[2]), "=r"(r[3]) : "r"(addr));
}
__device__ __forceinline__ uint32_t smem_u32(const void* p) {
    return (uint32_t)__cvta_generic_to_shared(p);
}
__device__ __forceinline__ void cp16(uint32_t dst, const void* src, int sz) {
    asm volatile("cp.async.cg.shared.global [%0], [%1], 16, %2;" :: "r"(dst), "l"(src), "r"(sz));
}
#define CP_COMMIT() asm volatile("cp.async.commit_group;")
#define CP_WAIT(n)  asm volatile("cp.async.wait_group %0;" :: "n"(n))
__device__ __forceinline__ float4 ld_h4(const __half* p) {
    uint2 u = *(const uint2*)p;
    __half2 a = *(__half2*)&u.x, b = *(__half2*)&u.y;
    float2 fa = __half22float2(a), fb = __half22float2(b);
    return make_float4(fa.x, fa.y, fb.x, fb.y);
}

extern __shared__ uint32_t s_dyn[];

// ---------------- prep kernels ----------------
__global__ void half_copy1(const float4* __restrict__ src, uint2* __restrict__ dst, int n4)
{
    int i = blockIdx.x * blockDim.x + threadIdx.x;
    if (i >= n4) return;
    float4 v = src[i];
    __half2 lo = __floats2half2_rn(v.x, v.y);
    __half2 hi = __floats2half2_rn(v.z, v.w);
    uint2 r; r.x = *(uint32_t*)&lo; r.y = *(uint32_t*)&hi;
    dst[i] = r;
}
__global__ void half_copy2(const float4* __restrict__ src, uint2* __restrict__ dstp,
                           uint2* __restrict__ dsta, int n4)
{
    int i = blockIdx.x * blockDim.x + threadIdx.x;
    if (i >= n4) return;
    float4 v = src[i];
    __half2 lo = __floats2half2_rn(v.x, v.y);
    __half2 hi = __floats2half2_rn(v.z, v.w);
    uint2 r; r.x = *(uint32_t*)&lo; r.y = *(uint32_t*)&hi;
    dstp[i] = r;
    r.x &= 0x7fff7fffu; r.y &= 0x7fff7fffu;
    dsta[i] = r;
}
// fused: mask -> fp16 copy + updated flag (warp per row, mask read ONCE)
__global__ void mask_prep(const float* __restrict__ mask)
{
    int row = blockIdx.x * (blockDim.x >> 5) + (threadIdx.x >> 5);
    if (row >= BN_) return;
    int ln = threadIdx.x & 31;
    const float4* p = (const float4*)(mask + (size_t)row * DIM_);
    uint2* dst = (uint2*)(g_mkh + (size_t)row * DIM_);
    float s = 0.f;
    #pragma unroll
    for (int e = 0; e < 4; e++) {
        int c4 = ln + e * 32;
        float4 v = p[c4];
        s += v.x + v.y + v.z + v.w;
        __half2 lo = __floats2half2_rn(v.x, v.y);
        __half2 hi = __floats2half2_rn(v.z, v.w);
        uint2 r; r.x = *(uint32_t*)&lo; r.y = *(uint32_t*)&hi;
        dst[c4] = r;
    }
    #pragma unroll
    for (int o = 16; o > 0; o >>= 1) s += __shfl_xor_sync(0xffffffffu, s, o);
    if (ln == 0) {
        int i = row % N_;
        g_upd[row] = (i == 0) ? 1.0f : (s > 0.0f ? 1.0f : 0.0f);
    }
}

// ================= fp16 NT GEMM pair (z-batched), 128x128 tile =================
#define GBUF_W 2560   // words per tile buffer: 128 rows * 20 words (40 halfs)
template<bool BIAS0, bool HOUT>
__global__ void __launch_bounds__(256, 2) hgemm2(const __half* __restrict__ A0,
                                                 const __half* __restrict__ A1,
                                                 const __half* __restrict__ B0,
                                                 const __half* __restrict__ B1,
                                                 const float* __restrict__ bias,
                                                 void* __restrict__ C0,
                                                 void* __restrict__ C1,
                                                 int K, int lda, int ldb, int ldc)
{
    const int z = blockIdx.z;
    const __half* A  = z ? A1 : A0;
    const __half* Bm = z ? B1 : B0;
    void* Cv = z ? C1 : C0;
    const bool use_bias = BIAS0 && (z == 0);

    uint32_t* AsB = s_dyn;               // [2][2560]
    uint32_t* BsB = s_dyn + 2 * GBUF_W;  // [2][2560]
    const int tid = threadIdx.x;
    const int bm = blockIdx.y * 128, bn = blockIdx.x * 128;
    const int lane = tid & 31, wid = tid >> 5;
    const int gr = lane >> 2, gc = lane & 3;
    const int wm = (wid & 1) * 64, wn = (wid >> 1) * 32;
    const int a_row = (lane & 7) + ((lane >> 3) & 1) * 8;
    const int a_col = (lane >> 4) * 4;
    const int b_row = (lane & 7) + ((lane >> 4) & 1) * 8;
    const int b_col = ((lane >> 3) & 1) * 4;

    float acc[4][4][4];
    #pragma unroll
    for (int i = 0; i < 4; i++)
        #pragma unroll
        for (int j = 0; j < 4; j++)
            #pragma unroll
            for (int e = 0; e < 4; e++) acc[i][j][e] = 0.f;

    const int nslab = K >> 5;
    const int r0s = tid >> 2, s0s = tid & 3;
    const int r1s = 64 + (tid >> 2);
    {
        cp16(smem_u32(&AsB[r0s*20 + s0s*4]), A + (size_t)(bm + r0s) * lda + s0s*8, 16);
        cp16(smem_u32(&AsB[r1s*20 + s0s*4]), A + (size_t)(bm + r1s) * lda + s0s*8, 16);
        cp16(smem_u32(&BsB[r0s*20 + s0s*4]), Bm + (size_t)(bn + r0s) * ldb + s0s*8, 16);
        cp16(smem_u32(&BsB[r1s*20 + s0s*4]), Bm + (size_t)(bn + r1s) * ldb + s0s*8, 16);
        CP_COMMIT();
    }
    for (int s = 0; s < nslab; s++) {
        if (s + 1 < nslab) {
            uint32_t* As = AsB + ((s+1) & 1) * GBUF_W;
            uint32_t* Bs = BsB + ((s+1) & 1) * GBUF_W;
            int kt = (s + 1) * 32;
            cp16(smem_u32(&As[r0s*20 + s0s*4]), A + (size_t)(bm + r0s) * lda + kt + s0s*8, 16);
            cp16(smem_u32(&As[r1s*20 + s0s*4]), A + (size_t)(bm + r1s) * lda + kt + s0s*8, 16);
            cp16(smem_u32(&Bs[r0s*20 + s0s*4]), Bm + (size_t)(bn + r0s) * ldb + kt + s0s*8, 16);
            cp16(smem_u32(&Bs[r1s*20 + s0s*4]), Bm + (size_t)(bn + r1s) * ldb + kt + s0s*8, 16);
            CP_COMMIT();
            CP_WAIT(1);
        } else {
            CP_WAIT(0);
        }
        __syncthreads();

        const uint32_t* As = AsB + (s & 1) * GBUF_W;
        const uint32_t* Bs = BsB + (s & 1) * GBUF_W;
        #pragma unroll
        for (int ks = 0; ks < 2; ks++) {
            const int kw = ks * 8;
            uint32_t ah[4][4];
            #pragma unroll
            for (int mt = 0; mt < 4; mt++)
                ldm4(ah[mt], smem_u32(&As[(wm + mt*16 + a_row) * 20 + kw + a_col]));
            #pragma unroll
            for (int p = 0; p < 2; p++) {
                uint32_t t[4];
                ldm4(t, smem_u32(&Bs[(wn + p*16 + b_row) * 20 + kw + b_col]));
                #pragma unroll
                for (int mt = 0; mt < 4; mt++) {
                    mma_f16(acc[mt][2*p    ], ah[mt], t);
                    mma_f16(acc[mt][2*p + 1], ah[mt], t + 2);
                }
            }
        }
        __syncthreads();
    }
    #pragma unroll
    for (int mt = 0; mt < 4; mt++)
        #pragma unroll
        for (int nt = 0; nt < 4; nt++) {
            int m0 = bm + wm + mt * 16 + gr;
            int n0 = bn + wn + nt * 8 + gc * 2;
            float bx = 0.f, by = 0.f;
            if (use_bias) { bx = bias[n0]; by = bias[n0 + 1]; }
            if (HOUT) {
                __half* C = (__half*)Cv;
                __half2 v0 = __floats2half2_rn(acc[mt][nt][0], acc[mt][nt][1]);
                __half2 v1 = __floats2half2_rn(acc[mt][nt][2], acc[mt][nt][3]);
                *(uint32_t*)&C[(size_t)m0 * ldc + n0]       = *(uint32_t*)&v0;
                *(uint32_t*)&C[(size_t)(m0 + 8) * ldc + n0] = *(uint32_t*)&v1;
            } else {
                float* C = (float*)Cv;
                *(float2*)&C[(size_t)m0 * ldc + n0] = make_float2(acc[mt][nt][0] + bx, acc[mt][nt][1] + by);
                *(float2*)&C[(size_t)(m0 + 8) * ldc + n0] = make_float2(acc[mt][nt][2] + bx, acc[mt][nt][3] + by);
            }
        }
}

// ================= fp16 flash attention (ldmatrix, 2 CTAs/SM) =================
#define KT_W    2304     // 64 rows * 36 words (72 halfs)
#define V1_OFF  (2*KT_W)
#define V2_OFF  (4*KT_W)
#define PQ_OFF  (6*KT_W)
#define FA_SMEM_WORDS (PQ_OFF + 128*36)

__global__ void __launch_bounds__(256, 2) flash_attn()
{
    const int bh = blockIdx.y;
    const int b = bh >> 3, h = bh & 7;
    const int i0 = blockIdx.x * 128;
    const __half* Q   = g_qh  + (size_t)bh * N_ * D_;
    const __half* Kp  = g_kh  + (size_t)bh * N_ * D_;
    const __half* V1g = g_vvT + (size_t)bh * 64 * 512;
    const __half* V2g = g_vmT + (size_t)bh * 64 * 512;
    uint32_t* PQ = s_dyn + PQ_OFF;

    const int tid = threadIdx.x;
    const int lane = tid & 31, wid = tid >> 5;
    const int gr = lane >> 2, gc = lane & 3;
    const int rbase = wid * 16;
    const int a_row = (lane & 7) + ((lane >> 3) & 1) * 8;
    const int a_col = (lane >> 4) * 4;
    const int b_row = (lane & 7) + ((lane >> 4) & 1) * 8;
    const int b_col = ((lane >> 3) & 1) * 4;

    {
        #pragma unroll
        for (int e = 0; e < 4; e++) {
            int chunk = tid + e * 256;
            int row = chunk >> 3, seg = chunk & 7;
            int gi = i0 + row;
            uint4 q = make_uint4(0u,0u,0u,0u);
            if (gi < N_) q = *(const uint4*)(Q + (size_t)gi * D_ + seg * 8);
            *(uint4*)&PQ[row * 36 + seg * 4] = q;
        }
    }
    __syncthreads();
    uint32_t qf[4][4];
    #pragma unroll
    for (int ks = 0; ks < 4; ks++)
        ldm4(qf[ks], smem_u32(&PQ[(rbase + a_row) * 36 + ks*8 + a_col]));
    __syncthreads();

    float acc1[8][4], acc2[8][4];
    #pragma unroll
    for (int nt = 0; nt < 8; nt++)
        #pragma unroll
        for (int e = 0; e < 4; e++) { acc1[nt][e] = 0.f; acc2[nt][e] = 0.f; }
    float rmax0 = -1e30f, rmax1 = -1e30f, rsum0 = 0.f, rsum1 = 0.f;

    const int ntiles = (N_ + 63) / 64;   // 8
    {
        #pragma unroll
        for (int e = 0; e < 2; e++) {
            int chunk = tid + e * 256;
            int row = chunk >> 3, seg = chunk & 7;
            int j = row;
            int sz = (j < N_) ? 16 : 0;
            cp16(smem_u32(&s_dyn[row*36 + seg*4]), Kp + (size_t)(sz ? j : 0) * D_ + seg*8, sz);
            cp16(smem_u32(&s_dyn[V1_OFF + row*36 + seg*4]), V1g + (size_t)row * 512 + seg*8, 16);
            cp16(smem_u32(&s_dyn[V2_OFF + row*36 + seg*4]), V2g + (size_t)row * 512 + seg*8, 16);
        }
        CP_COMMIT();
    }

    for (int t = 0; t < ntiles; t++) {
        const int j0 = t * 64;
        if (t + 1 < ntiles) {
            int buf = (t + 1) & 1;
            int jb = j0 + 64;
            #pragma unroll
            for (int e = 0; e < 2; e++) {
                int chunk = tid + e * 256;
                int row = chunk >> 3, seg = chunk & 7;
                int j = jb + row;
                int sz = (j < N_) ? 16 : 0;
                cp16(smem_u32(&s_dyn[buf*KT_W + row*36 + seg*4]), Kp + (size_t)(sz ? j : 0) * D_ + seg*8, sz);
                cp16(smem_u32(&s_dyn[V1_OFF + buf*KT_W + row*36 + seg*4]), V1g + (size_t)row * 512 + jb + seg*8, 16);
                cp16(smem_u32(&s_dyn[V2_OFF + buf*KT_W + row*36 + seg*4]), V2g + (size_t)row * 512 + jb + seg*8, 16);
            }
            CP_COMMIT();
            CP_WAIT(1);
        } else {
            CP_WAIT(0);
        }
        __syncthreads();

        const uint32_t* Kt = s_dyn + (t & 1) * KT_W;
        const uint32_t* V1 = s_dyn + V1_OFF + (t & 1) * KT_W;
        const uint32_t* V2 = s_dyn + V2_OFF + (t & 1) * KT_W;

        float sacc[8][4];
        #pragma unroll
        for (int nt = 0; nt < 8; nt++)
            #pragma unroll
            for (int e = 0; e < 4; e++) sacc[nt][e] = 0.f;
        #pragma unroll
        for (int ks = 0; ks < 4; ks++) {
            #pragma unroll
            for (int p = 0; p < 4; p++) {
                uint32_t tkt[4];
                ldm4(tkt, smem_u32(&Kt[(p*16 + b_row) * 36 + ks*8 + b_col]));
                mma_f16(sacc[2*p    ], qf[ks], tkt);
                mma_f16(sacc[2*p + 1], qf[ks], tkt + 2);
            }
        }
        if (j0 + 64 > N_) {
            #pragma unroll
            for (int nt = 0; nt < 8; nt++) {
                int cc = j0 + nt*8 + gc*2;
                if (cc     >= N_) { sacc[nt][0] = -1e30f; sacc[nt][2] = -1e30f; }
                if (cc + 1 >= N_) { sacc[nt][1] = -1e30f; sacc[nt][3] = -1e30f; }
            }
        }
        float tm0 = -1e30f, tm1 = -1e30f;
        #pragma unroll
        for (int nt = 0; nt < 8; nt++) {
            tm0 = fmaxf(tm0, fmaxf(sacc[nt][0], sacc[nt][1]));
            tm1 = fmaxf(tm1, fmaxf(sacc[nt][2], sacc[nt][3]));
        }
        tm0 = fmaxf(tm0, __shfl_xor_sync(0xffffffffu, tm0, 1));
        tm0 = fmaxf(tm0, __shfl_xor_sync(0xffffffffu, tm0, 2));
        tm1 = fmaxf(tm1, __shfl_xor_sync(0xffffffffu, tm1, 1));
        tm1 = fmaxf(tm1, __shfl_xor_sync(0xffffffffu, tm1, 2));
        float nm0 = fmaxf(rmax0, tm0), nm1 = fmaxf(rmax1, tm1);
        float sc0 = __expf(rmax0 - nm0), sc1 = __expf(rmax1 - nm1);
        rmax0 = nm0; rmax1 = nm1;
        float ps0 = 0.f, ps1 = 0.f;
        __half2* PQh = (__half2*)PQ;
        #pragma unroll
        for (int nt = 0; nt < 8; nt++) {
            float p00 = __expf(sacc[nt][0] - nm0);
            float p01 = __expf(sacc[nt][1] - nm0);
            float p10 = __expf(sacc[nt][2] - nm1);
            float p11 = __expf(sacc[nt][3] - nm1);
            ps0 += p00 + p01; ps1 += p10 + p11;
            PQh[(rbase + gr    ) * 36 + nt*4 + gc] = __floats2half2_rn(p00, p01);
            PQh[(rbase + gr + 8) * 36 + nt*4 + gc] = __floats2half2_rn(p10, p11);
            acc1[nt][0] *= sc0; acc1[nt][1] *= sc0; acc1[nt][2] *= sc1; acc1[nt][3] *= sc1;
            acc2[nt][0] *= sc0; acc2[nt][1] *= sc0; acc2[nt][2] *= sc1; acc2[nt][3] *= sc1;
        }
        ps0 += __shfl_xor_sync(0xffffffffu, ps0, 1);
        ps0 += __shfl_xor_sync(0xffffffffu, ps0, 2);
        ps1 += __shfl_xor_sync(0xffffffffu, ps1, 1);
        ps1 += __shfl_xor_sync(0xffffffffu, ps1, 2);
        rsum0 = rsum0 * sc0 + ps0;
        rsum1 = rsum1 * sc1 + ps1;
        __syncwarp();

        #pragma unroll
        for (int ks = 0; ks < 4; ks++) {
            uint32_t af[4];
            ldm4(af, smem_u32(&PQ[(rbase + a_row) * 36 + ks*8 + a_col]));
            #pragma unroll
            for (int p = 0; p < 4; p++) {
                uint32_t t1[4], t2[4];
                ldm4(t1, smem_u32(&V1[(p*16 + b_row) * 36 + ks*8 + b_col]));
                ldm4(t2, smem_u32(&V2[(p*16 + b_row) * 36 + ks*8 + b_col]));
                mma_f16(acc1[2*p    ], af, t1);
                mma_f16(acc1[2*p + 1], af, t1 + 2);
                mma_f16(acc2[2*p    ], af, t2);
                mma_f16(acc2[2*p + 1], af, t2 + 2);
            }
        }
        __syncthreads();
    }

    // ---- epilogue (fp16 out) ----
    float inv0 = 1.0f / rsum0, inv1 = 1.0f / rsum1;
    int gi0 = i0 + rbase + gr, gi1 = gi0 + 8;
    if (gi0 < N_) {
        float f = inv0 * g_upd[b * N_ + gi0];
        size_t base = (size_t)(b * N_ + gi0) * DIM_ + h * 64;
        #pragma unroll
        for (int nt = 0; nt < 8; nt++) {
            int d = nt*8 + gc*2;
            __half2 h1 = __floats2half2_rn(acc1[nt][0]*f, acc1[nt][1]*f);
            __half2 h2 = __floats2half2_rn(acc2[nt][0]*f, acc2[nt][1]*f);
            *(uint32_t*)&g_outh[base + d] = *(uint32_t*)&h1;
            *(uint32_t*)&g_mh  [base + d] = *(uint32_t*)&h2;
        }
    }
    if (gi1 < N_) {
        float f = inv1 * g_upd[b * N_ + gi1];
        size_t base = (size_t)(b * N_ + gi1) * DIM_ + h * 64;
        #pragma unroll
        for (int nt = 0; nt < 8; nt++) {
            int d = nt*8 + gc*2;
            __half2 h1 = __floats2half2_rn(acc1[nt][2]*f, acc1[nt][3]*f);
            __half2 h2 = __floats2half2_rn(acc2[nt][2]*f, acc2[nt][3]*f);
            *(uint32_t*)&g_outh[base + d] = *(uint32_t*)&h1;
            *(uint32_t*)&g_mh  [base + d] = *(uint32_t*)&h2;
        }
    }
}

// ---------------- per-(bh,w,d) max over sequence (fp16 input) ----------------
__global__ void reduce_max_k()
{
    int o = blockIdx.x * blockDim.x + threadIdx.x;
    if (o >= B_*H_*3*D_) return;
    int d = o & 63;
    int w = (o >> 6) % 3;
    int h = ((o >> 6) / 3) % H_;
    int b = (o >> 6) / 24;
    const __half* p = g_qkvmh + (size_t)b * N_ * QKV_ + w * DIM_ + h * 64 + d;
    float mx = -1e30f;
    for (int i = 0; i < N_; i++) mx = fmaxf(mx, __half2float(p[(size_t)i * QKV_]));
    g_max[((b * H_ + h) * 3 + w) * 64 + d] = mx;
}

// ---------------- modulate: fp16 in, fp16 q/k + transposed v/vm out ----------------
__global__ void __launch_bounds__(256) modulate_k()
{
    __shared__ __half sv1[64][72];
    __shared__ __half sv2[64][72];
    __shared__ float smax[192];
    const int bh = blockIdx.y, b = bh >> 3, h = bh & 7;
    const int i0 = blockIdx.x * 64;
    const int t = threadIdx.x;
    if (t < 192) smax[t] = g_max[bh * 192 + t];
    __syncthreads();

    const int r = t >> 2, d0 = (t & 3) * 16;
    const int i = i0 + r;

    union H16 { __half h[16]; uint4 u[2]; };
    H16 qo, ko;

    if (i < N_) {
        size_t base = (size_t)(b * N_ + i) * QKV_ + h * 64 + d0;
        H16 qi, ki, vi, qmi, kmi, vmi;
        qi.u[0]  = *(const uint4*)&g_qkvh [base];        qi.u[1]  = *(const uint4*)&g_qkvh [base + 8];
        ki.u[0]  = *(const uint4*)&g_qkvh [base + 512];  ki.u[1]  = *(const uint4*)&g_qkvh [base + 520];
        vi.u[0]  = *(const uint4*)&g_qkvh [base + 1024]; vi.u[1]  = *(const uint4*)&g_qkvh [base + 1032];
        qmi.u[0] = *(const uint4*)&g_qkvmh[base];        qmi.u[1] = *(const uint4*)&g_qkvmh[base + 8];
        kmi.u[0] = *(const uint4*)&g_qkvmh[base + 512];  kmi.u[1] = *(const uint4*)&g_qkvmh[base + 520];
        vmi.u[0] = *(const uint4*)&g_qkvmh[base + 1024]; vmi.u[1] = *(const uint4*)&g_qkvmh[base + 1032];
        #pragma unroll
        for (int j = 0; j < 16; j++) {
            int d = d0 + j;
            float qmn = __half2float(qmi.h[j]) / (1e-6f + smax[d]);
            float kmn = __half2float(kmi.h[j]) / (1e-6f + smax[64 + d]);
            float vmn = __half2float(vmi.h[j]) / (1e-6f + smax[128 + d]);
            qo.h[j] = __float2half_rn(__half2float(qi.h[j]) * qmn * SCALE_);
            ko.h[j] = __float2half_rn(__half2float(ki.h[j]) * kmn);
            sv1[r][d] = __float2half_rn(__half2float(vi.h[j]) * vmn);
            sv2[r][d] = __float2half_rn(vmn);
        }
        size_t ob = (size_t)bh * N_ * 64 + (size_t)i * 64 + d0;
        *(uint4*)&g_qh[ob] = qo.u[0];
        *(uint4*)&g_qh[ob + 8] = qo.u[1];
        *(uint4*)&g_kh[ob] = ko.u[0];
        *(uint4*)&g_kh[ob + 8] = ko.u[1];
    } else {
        #pragma unroll
        for (int e = 0; e < 16; e++) {
            sv1[r][d0 + e] = __float2half_rn(0.f);
            sv2[r][d0 + e] = __float2half_rn(0.f);
        }
    }
    __syncthreads();

    const int drow = t >> 2, is0 = (t & 3) * 16;
    H16 o1, o2;
    #pragma unroll
    for (int e = 0; e < 16; e++) {
        o1.h[e] = sv1[is0 + e][drow];
        o2.h[e] = sv2[is0 + e][drow];
    }
    size_t ob = (size_t)bh * 64 * 512 + (size_t)drow * 512 + i0 + is0;
    *(uint4*)&g_vvT[ob] = o1.u[0];
    *(uint4*)&g_vvT[ob + 8] = o1.u[1];
    *(uint4*)&g_vmT[ob] = o2.u[0];
    *(uint4*)&g_vmT[ob + 8] = o2.u[1];
}

// ---------------- overlap blending (fp16 in/out) ----------------
__global__ void blend_k()
{
    int idx4 = blockIdx.x * blockDim.x + threadIdx.x;
    if (idx4 >= SZ_BND / 4) return;
    size_t idx = (size_t)idx4 * 4;
    int c = idx % DIM_;
    int i = (idx / DIM_) % N_;
    int b = idx / (DIM_ * (size_t)N_);
    float4 o  = ld_h4(&g_outh[idx]);
    float4 mv = ld_h4(&g_mh[idx]);

    if (i >= 1 && i <= NHW_) {
        int p = i - 1, y = p >> 4, x = p & 15;
        float inv = 0.25f * (1.0f - g_upd[b * N_ + i]);
        float4 s1 = make_float4(0,0,0,0), s2 = make_float4(0,0,0,0);
        #pragma unroll
        for (int dy = -1; dy <= 0; dy++)
            #pragma unroll
            for (int dx = -1; dx <= 0; dx++) {
                int rr = y + dy, cc = x + dx;
                if (rr >= 0 && rr < 15 && cc >= 0 && cc < 15) {
                    size_t src = ((size_t)(b * N_ + TAIL0_ + rr * 15 + cc)) * DIM_ + c;
                    float4 a = ld_h4(&g_outh[src]);
                    float4 e = ld_h4(&g_mh[src]);
                    s1.x += a.x; s1.y += a.y; s1.z += a.z; s1.w += a.w;
                    s2.x += e.x; s2.y += e.y; s2.z += e.z; s2.w += e.w;
                }
            }
        o.x += s1.x*inv; o.y += s1.y*inv; o.z += s1.z*inv; o.w += s1.w*inv;
        mv.x += s2.x*inv; mv.y += s2.y*inv; mv.z += s2.z*inv; mv.w += s2.w*inv;
    } else if (i >= TAIL0_) {
        int p = i - TAIL0_, rr = p / 15, cc = p % 15;
        float inv = 0.25f * (1.0f - g_upd[b * N_ + i]);
        float4 s1 = make_float4(0,0,0,0), s2 = make_float4(0,0,0,0);
        #pragma unroll
        for (int dy = 0; dy <= 1; dy++)
            #pragma unroll
            for (int dx = 0; dx <= 1; dx++) {
                size_t src = ((size_t)(b * N_ + 1 + (rr + dy) * 16 + (cc + dx))) * DIM_ + c;
                float4 a = ld_h4(&g_outh[src]);
                float4 e = ld_h4(&g_mh[src]);
                s1.x += a.x; s1.y += a.y; s1.z += a.z; s1.w += a.w;
                s2.x += e.x; s2.y += e.y; s2.z += e.z; s2.w += e.w;
            }
        o.x += s1.x*inv; o.y += s1.y*inv; o.z += s1.z*inv; o.w += s1.w*inv;
        mv.x += s2.x*inv; mv.y += s2.y*inv; mv.z += s2.z*inv; mv.w += s2.w*inv;
    }
    __half2 ol = __floats2half2_rn(o.x, o.y),  oh = __floats2half2_rn(o.z, o.w);
    __half2 ml = __floats2half2_rn(mv.x, mv.y), mh = __floats2half2_rn(mv.z, mv.w);
    uint2 ou, mu;
    ou.x = *(uint32_t*)&ol; ou.y = *(uint32_t*)&oh;
    mu.x = *(uint32_t*)&ml; mu.y = *(uint32_t*)&mh;
    *(uint2*)&g_o2h[idx] = ou;
    *(uint2*)&g_m2h[idx] = mu;
}

// ---------------- channel means (fp16 input) ----------------
__global__ void mm_k()
{
    int row = blockIdx.x * (blockDim.x >> 5) + (threadIdx.x >> 5);
    if (row >= B_ * (N_ - 1)) return;
    int b = row / (N_ - 1), j = row % (N_ - 1);
    int ln = threadIdx.x & 31;
    const __half2* p = (const __half2*)(g_m2h + (size_t)(b * N_ + j + 1) * DIM_);
    float s = 0.f;
    #pragma unroll
    for (int e = 0; e < 8; e++) {
        float2 v = __half22float2(p[ln + e * 32]);
        s += v.x + v.y;
    }
    #pragma unroll
    for (int o = 16; o > 0; o >>= 1) s += __shfl_xor_sync(0xffffffffu, s, o);
    if (ln == 0) g_mm[row] = s * (1.0f / DIM_);
}

// ---------------- inter ----------------
__global__ void inter_k(float* __restrict__ outp)
{
    int idx = blockIdx.x * blockDim.x + threadIdx.x;
    if (idx >= B_ * 256 * 256) return;
    int x = idx & 255, y = (idx >> 8) & 255, b = idx >> 16;
    float v = g_mm[b * (N_ - 1) + (y >> 4) * 16 + (x >> 4)];
    if (y >= 8 && y < 248 && x >= 8 && x < 248) {
        float sh = g_mm[b * (N_ - 1) + 256 + ((y - 8) >> 4) * 15 + ((x - 8) >> 4)];
        v = 0.5f * (v + sh);
    }
    outp[idx] = v;
}

// ---------------- launch ----------------
extern "C" void kernel_launch(void* const* d_in, const int* in_sizes, int n_in,
                              void* d_out, int out_size)
{
    const float* x    = (const float*)d_in[0];
    const float* mask = (const float*)d_in[1];
    const float* Wqkv = (const float*)d_in[2];
    const float* Wout = (const float*)d_in[3];
    const float* bout = (const float*)d_in[4];
    float* out = (float*)d_out;

    __half *p_xh, *p_wqh, *p_wqah, *p_woh, *p_woah, *p_o2h, *p_m2h, *p_qkvh, *p_qkvmh, *p_mkh;
    cudaGetSymbolAddress((void**)&p_xh,    g_xh);
    cudaGetSymbolAddress((void**)&p_mkh,   g_mkh);
    cudaGetSymbolAddress((void**)&p_wqh,   g_wqh);
    cudaGetSymbolAddress((void**)&p_wqah,  g_wqah);
    cudaGetSymbolAddress((void**)&p_woh,   g_woh);
    cudaGetSymbolAddress((void**)&p_woah,  g_woah);
    cudaGetSymbolAddress((void**)&p_o2h,   g_o2h);
    cudaGetSymbolAddress((void**)&p_m2h,   g_m2h);
    cudaGetSymbolAddress((void**)&p_qkvh,  g_qkvh);
    cudaGetSymbolAddress((void**)&p_qkvmh, g_qkvmh);

    const int gemm_smem = 4 * GBUF_W * 4;          // 40960 B
    cudaFuncSetAttribute(hgemm2<false,true >, cudaFuncAttributeMaxDynamicSharedMemorySize, gemm_smem);
    cudaFuncSetAttribute(hgemm2<true ,false>, cudaFuncAttributeMaxDynamicSharedMemorySize, gemm_smem);
    cudaFuncSetAttribute(flash_attn, cudaFuncAttributeMaxDynamicSharedMemorySize, FA_SMEM_WORDS * 4);

    // 0. fp16 copies + fused mask prep
    half_copy1<<<(SZ_BND/4 + 255)/256, 256>>>((const float4*)x, (uint2*)p_xh, SZ_BND/4);
    mask_prep<<<(BN_ + 7) / 8, 256>>>(mask);
    half_copy2<<<(QKV_*DIM_/4 + 255)/256, 256>>>((const float4*)Wqkv, (uint2*)p_wqh, (uint2*)p_wqah, QKV_*DIM_/4);
    half_copy2<<<(DIM_*DIM_/4 + 255)/256, 256>>>((const float4*)Wout, (uint2*)p_woh, (uint2*)p_woah, DIM_*DIM_/4);

    // 1. qkv projections (both tensors in one z-batched launch, fp16 out)
    hgemm2<false,true><<<dim3(QKV_/128, BN_/128, 2), 256, gemm_smem>>>(
        p_xh, p_mkh, p_wqh, p_wqah, nullptr, p_qkvh, p_qkvmh, DIM_, DIM_, DIM_, QKV_);
    // 2. maxima
    reduce_max_k<<<(B_*H_*3*D_ + 255) / 256, 256>>>();
    // 3. modulate
    modulate_k<<<dim3(8, BH_), 256>>>();
    // 4-6. fused attention (fp16 out/m, 2 CTAs/SM)
    flash_attn<<<dim3(4, BH_), 256, FA_SMEM_WORDS * 4>>>();
    // 7. blending (fp16 in, fp16 out)
    blend_k<<<(SZ_BND/4 + 255)/256, 256>>>();
    // 8. channel means (fp16 in)
    mm_k<<<(B_ * (N_ - 1) + 7) / 8, 256>>>();
    // 9. inter
    inter_k<<<(B_ * 65536 + 255) / 256, 256>>>(out + 2 * (size_t)SZ_BND);
    // 10. final projections (both in one z-batched launch, f32 out into d_out)
    hgemm2<true,false><<<dim3(DIM_/128, BN_/128, 2), 256, gemm_smem>>>(
        p_o2h, p_m2h, p_woh, p_woah, bout, out, out + (size_t)SZ_BND, DIM_, DIM_, DIM_, DIM_);
}

// round 17
// speedup vs baseline: 2.7670x; 1.0993x over previous
#include <cuda_runtime.h>
#include <cuda_fp16.h>
#include <cstdint>

// ---------------- problem constants ----------------
#define B_    64
#define N_    482
#define DIM_  512
#define H_    8
#define D_    64
#define QKV_  1536
#define BH_   (B_*H_)          // 512
#define BN_   (B_*N_)          // 30848
#define SZ_BND (BN_*DIM_)      // 15794176
#define NHW_  256
#define NB_   225
#define TAIL0_ 257
#define SCALE_ 0.125f

// ---------------- device scratch ----------------
__device__ float  g_max [B_*H_*3*D_];
__device__ float  g_upd [BN_];
__device__ float  g_mm  [B_*(N_-1)];
// fp16 tensors
__device__ __half g_xh  [SZ_BND];
__device__ __half g_mkh [SZ_BND];
__device__ __half g_wqh [QKV_*DIM_];
__device__ __half g_wqah[QKV_*DIM_];
__device__ __half g_woh [DIM_*DIM_];
__device__ __half g_woah[DIM_*DIM_];
__device__ __half g_qkvh [(size_t)BN_*QKV_];
__device__ __half g_qkvmh[(size_t)BN_*QKV_];
__device__ __half g_qh  [(size_t)BH_*N_*D_];
__device__ __half g_kh  [(size_t)BH_*N_*D_];
__device__ __half g_vvT [(size_t)BH_*64*512];   // [bh][d][j], zero-padded cols
__device__ __half g_vmT [(size_t)BH_*64*512];
__device__ __half g_outh[SZ_BND];
__device__ __half g_mh  [SZ_BND];
__device__ __half g_o2h [SZ_BND];
__device__ __half g_m2h [SZ_BND];

// ---------------- helpers ----------------
__device__ __forceinline__ void mma_f16(float* c, const uint32_t* a, const uint32_t* b) {
    asm volatile("mma.sync.aligned.m16n8k16.row.col.f32.f16.f16.f32 "
        "{%0,%1,%2,%3}, {%4,%5,%6,%7}, {%8,%9}, {%0,%1,%2,%3};"
        : "+f"(c[0]), "+f"(c[1]), "+f"(c[2]), "+f"(c[3])
        : "r"(a[0]), "r"(a[1]), "r"(a[2]), "r"(a[3]), "r"(b[0]), "r"(b[1]));
}
__device__ __forceinline__ void ldm4(uint32_t* r, uint32_t addr) {
    asm volatile("ldmatrix.sync.aligned.m8n8.x4.shared.b16 {%0,%1,%2,%3}, [%4];"
        : "=r"(r[0]), "=r"(r[1]), "=r"(r[2]), "=r"(r[3]) : "r"(addr));
}
__device__ __forceinline__ uint32_t smem_u32(const void* p) {
    return (uint32_t)__cvta_generic_to_shared(p);
}
__device__ __forceinline__ void cp16(uint32_t dst, const void* src, int sz) {
    asm volatile("cp.async.cg.shared.global [%0], [%1], 16, %2;" :: "r"(dst), "l"(src), "r"(sz));
}
#define CP_COMMIT() asm volatile("cp.async.commit_group;")
#define CP_WAIT(n)  asm volatile("cp.async.wait_group %0;" :: "n"(n))
__device__ __forceinline__ float4 ld_h4(const __half* p) {
    uint2 u = *(const uint2*)p;
    __half2 a = *(__half2*)&u.x, b = *(__half2*)&u.y;
    float2 fa = __half22float2(a), fb = __half22float2(b);
    return make_float4(fa.x, fa.y, fb.x, fb.y);
}

extern __shared__ uint32_t s_dyn[];

// ---------------- prep kernels ----------------
__global__ void half_copy1(const float4* __restrict__ src, uint2* __restrict__ dst, int n4)
{
    int i = blockIdx.x * blockDim.x + threadIdx.x;
    if (i >= n4) return;
    float4 v = src[i];
    __half2 lo = __floats2half2_rn(v.x, v.y);
    __half2 hi = __floats2half2_rn(v.z, v.w);
    uint2 r; r.x = *(uint32_t*)&lo; r.y = *(uint32_t*)&hi;
    dst[i] = r;
}
__global__ void half_copy2(const float4* __restrict__ src, uint2* __restrict__ dstp,
                           uint2* __restrict__ dsta, int n4)
{
    int i = blockIdx.x * blockDim.x + threadIdx.x;
    if (i >= n4) return;
    float4 v = src[i];
    __half2 lo = __floats2half2_rn(v.x, v.y);
    __half2 hi = __floats2half2_rn(v.z, v.w);
    uint2 r; r.x = *(uint32_t*)&lo; r.y = *(uint32_t*)&hi;
    dstp[i] = r;
    r.x &= 0x7fff7fffu; r.y &= 0x7fff7fffu;
    dsta[i] = r;
}
// fused: mask -> fp16 copy + updated flag (warp per row, mask read ONCE)
__global__ void mask_prep(const float* __restrict__ mask)
{
    int row = blockIdx.x * (blockDim.x >> 5) + (threadIdx.x >> 5);
    if (row >= BN_) return;
    int ln = threadIdx.x & 31;
    const float4* p = (const float4*)(mask + (size_t)row * DIM_);
    uint2* dst = (uint2*)(g_mkh + (size_t)row * DIM_);
    float s = 0.f;
    #pragma unroll
    for (int e = 0; e < 4; e++) {
        int c4 = ln + e * 32;
        float4 v = p[c4];
        s += v.x + v.y + v.z + v.w;
        __half2 lo = __floats2half2_rn(v.x, v.y);
        __half2 hi = __floats2half2_rn(v.z, v.w);
        uint2 r; r.x = *(uint32_t*)&lo; r.y = *(uint32_t*)&hi;
        dst[c4] = r;
    }
    #pragma unroll
    for (int o = 16; o > 0; o >>= 1) s += __shfl_xor_sync(0xffffffffu, s, o);
    if (ln == 0) {
        int i = row % N_;
        g_upd[row] = (i == 0) ? 1.0f : (s > 0.0f ? 1.0f : 0.0f);
    }
}

// ================= fp16 NT GEMM pair (z-batched), 128x128 tile, K-slab 64 ========
#define GBUF_W 4608   // words per tile buffer: 128 rows * 36 words (72 halfs)
template<bool BIAS0, bool HOUT>
__global__ void __launch_bounds__(256, 2) hgemm2(const __half* __restrict__ A0,
                                                 const __half* __restrict__ A1,
                                                 const __half* __restrict__ B0,
                                                 const __half* __restrict__ B1,
                                                 const float* __restrict__ bias,
                                                 void* __restrict__ C0,
                                                 void* __restrict__ C1,
                                                 int K, int lda, int ldb, int ldc)
{
    const int z = blockIdx.z;
    const __half* A  = z ? A1 : A0;
    const __half* Bm = z ? B1 : B0;
    void* Cv = z ? C1 : C0;
    const bool use_bias = BIAS0 && (z == 0);

    uint32_t* AsB = s_dyn;               // [2][4608]
    uint32_t* BsB = s_dyn + 2 * GBUF_W;  // [2][4608]
    const int tid = threadIdx.x;
    const int bm = blockIdx.y * 128, bn = blockIdx.x * 128;
    const int lane = tid & 31, wid = tid >> 5;
    const int gr = lane >> 2, gc = lane & 3;
    const int wm = (wid & 1) * 64, wn = (wid >> 1) * 32;
    const int a_row = (lane & 7) + ((lane >> 3) & 1) * 8;
    const int a_col = (lane >> 4) * 4;
    const int b_row = (lane & 7) + ((lane >> 4) & 1) * 8;
    const int b_col = ((lane >> 3) & 1) * 4;

    float acc[4][4][4];
    #pragma unroll
    for (int i = 0; i < 4; i++)
        #pragma unroll
        for (int j = 0; j < 4; j++)
            #pragma unroll
            for (int e = 0; e < 4; e++) acc[i][j][e] = 0.f;

    const int nslab = K >> 6;   // 64-k slabs
    // staging: 128 rows * 64 halfs = 1024 chunks of 16B per matrix; 4/thread
    const int srow = tid >> 1;                 // base rows: 2 chunks per row pair
    const int sseg = (tid & 1) * 4;            // chunk cols {0..3} or {4..7}
    {
        #pragma unroll
        for (int e = 0; e < 4; e++) {
            int row = srow + (e >> 1) * 128;   // not used; simple map below
        }
        // simple map: chunk = tid + e*256; row = chunk>>3, seg = chunk&7
        #pragma unroll
        for (int e = 0; e < 4; e++) {
            int chunk = tid + e * 256;
            int row = chunk >> 3, seg = chunk & 7;
            cp16(smem_u32(&AsB[row*36 + seg*4]), A + (size_t)(bm + row) * lda + seg*8, 16);
            cp16(smem_u32(&BsB[row*36 + seg*4]), Bm + (size_t)(bn + row) * ldb + seg*8, 16);
        }
        CP_COMMIT();
    }
    for (int s = 0; s < nslab; s++) {
        if (s + 1 < nslab) {
            uint32_t* As = AsB + ((s+1) & 1) * GBUF_W;
            uint32_t* Bs = BsB + ((s+1) & 1) * GBUF_W;
            int kt = (s + 1) * 64;
            #pragma unroll
            for (int e = 0; e < 4; e++) {
                int chunk = tid + e * 256;
                int row = chunk >> 3, seg = chunk & 7;
                cp16(smem_u32(&As[row*36 + seg*4]), A + (size_t)(bm + row) * lda + kt + seg*8, 16);
                cp16(smem_u32(&Bs[row*36 + seg*4]), Bm + (size_t)(bn + row) * ldb + kt + seg*8, 16);
            }
            CP_COMMIT();
            CP_WAIT(1);
        } else {
            CP_WAIT(0);
        }
        __syncthreads();

        const uint32_t* As = AsB + (s & 1) * GBUF_W;
        const uint32_t* Bs = BsB + (s & 1) * GBUF_W;
        #pragma unroll
        for (int ks = 0; ks < 4; ks++) {          // four k16 steps per 64-k slab
            const int kw = ks * 8;
            uint32_t ah[4][4];
            #pragma unroll
            for (int mt = 0; mt < 4; mt++)
                ldm4(ah[mt], smem_u32(&As[(wm + mt*16 + a_row) * 36 + kw + a_col]));
            #pragma unroll
            for (int p = 0; p < 2; p++) {
                uint32_t t[4];
                ldm4(t, smem_u32(&Bs[(wn + p*16 + b_row) * 36 + kw + b_col]));
                #pragma unroll
                for (int mt = 0; mt < 4; mt++) {
                    mma_f16(acc[mt][2*p    ], ah[mt], t);
                    mma_f16(acc[mt][2*p + 1], ah[mt], t + 2);
                }
            }
        }
        __syncthreads();
    }
    #pragma unroll
    for (int mt = 0; mt < 4; mt++)
        #pragma unroll
        for (int nt = 0; nt < 4; nt++) {
            int m0 = bm + wm + mt * 16 + gr;
            int n0 = bn + wn + nt * 8 + gc * 2;
            float bx = 0.f, by = 0.f;
            if (use_bias) { bx = bias[n0]; by = bias[n0 + 1]; }
            if (HOUT) {
                __half* C = (__half*)Cv;
                __half2 v0 = __floats2half2_rn(acc[mt][nt][0], acc[mt][nt][1]);
                __half2 v1 = __floats2half2_rn(acc[mt][nt][2], acc[mt][nt][3]);
                *(uint32_t*)&C[(size_t)m0 * ldc + n0]       = *(uint32_t*)&v0;
                *(uint32_t*)&C[(size_t)(m0 + 8) * ldc + n0] = *(uint32_t*)&v1;
            } else {
                float* C = (float*)Cv;
                *(float2*)&C[(size_t)m0 * ldc + n0] = make_float2(acc[mt][nt][0] + bx, acc[mt][nt][1] + by);
                *(float2*)&C[(size_t)(m0 + 8) * ldc + n0] = make_float2(acc[mt][nt][2] + bx, acc[mt][nt][3] + by);
            }
        }
}

// ================= fp16 flash attention (ldmatrix, 2 CTAs/SM) =================
#define KT_W    2304     // 64 rows * 36 words (72 halfs)
#define V1_OFF  (2*KT_W)
#define V2_OFF  (4*KT_W)
#define PQ_OFF  (6*KT_W)
#define FA_SMEM_WORDS (PQ_OFF + 128*36)

__global__ void __launch_bounds__(256, 2) flash_attn()
{
    const int bh = blockIdx.y;
    const int b = bh >> 3, h = bh & 7;
    const int i0 = blockIdx.x * 128;
    const __half* Q   = g_qh  + (size_t)bh * N_ * D_;
    const __half* Kp  = g_kh  + (size_t)bh * N_ * D_;
    const __half* V1g = g_vvT + (size_t)bh * 64 * 512;
    const __half* V2g = g_vmT + (size_t)bh * 64 * 512;
    uint32_t* PQ = s_dyn + PQ_OFF;

    const int tid = threadIdx.x;
    const int lane = tid & 31, wid = tid >> 5;
    const int gr = lane >> 2, gc = lane & 3;
    const int rbase = wid * 16;
    const int a_row = (lane & 7) + ((lane >> 3) & 1) * 8;
    const int a_col = (lane >> 4) * 4;
    const int b_row = (lane & 7) + ((lane >> 4) & 1) * 8;
    const int b_col = ((lane >> 3) & 1) * 4;

    {
        #pragma unroll
        for (int e = 0; e < 4; e++) {
            int chunk = tid + e * 256;
            int row = chunk >> 3, seg = chunk & 7;
            int gi = i0 + row;
            uint4 q = make_uint4(0u,0u,0u,0u);
            if (gi < N_) q = *(const uint4*)(Q + (size_t)gi * D_ + seg * 8);
            *(uint4*)&PQ[row * 36 + seg * 4] = q;
        }
    }
    __syncthreads();
    uint32_t qf[4][4];
    #pragma unroll
    for (int ks = 0; ks < 4; ks++)
        ldm4(qf[ks], smem_u32(&PQ[(rbase + a_row) * 36 + ks*8 + a_col]));
    __syncthreads();

    float acc1[8][4], acc2[8][4];
    #pragma unroll
    for (int nt = 0; nt < 8; nt++)
        #pragma unroll
        for (int e = 0; e < 4; e++) { acc1[nt][e] = 0.f; acc2[nt][e] = 0.f; }
    float rmax0 = -1e30f, rmax1 = -1e30f, rsum0 = 0.f, rsum1 = 0.f;

    const int ntiles = (N_ + 63) / 64;   // 8
    {
        #pragma unroll
        for (int e = 0; e < 2; e++) {
            int chunk = tid + e * 256;
            int row = chunk >> 3, seg = chunk & 7;
            int j = row;
            int sz = (j < N_) ? 16 : 0;
            cp16(smem_u32(&s_dyn[row*36 + seg*4]), Kp + (size_t)(sz ? j : 0) * D_ + seg*8, sz);
            cp16(smem_u32(&s_dyn[V1_OFF + row*36 + seg*4]), V1g + (size_t)row * 512 + seg*8, 16);
            cp16(smem_u32(&s_dyn[V2_OFF + row*36 + seg*4]), V2g + (size_t)row * 512 + seg*8, 16);
        }
        CP_COMMIT();
    }

    for (int t = 0; t < ntiles; t++) {
        const int j0 = t * 64;
        if (t + 1 < ntiles) {
            int buf = (t + 1) & 1;
            int jb = j0 + 64;
            #pragma unroll
            for (int e = 0; e < 2; e++) {
                int chunk = tid + e * 256;
                int row = chunk >> 3, seg = chunk & 7;
                int j = jb + row;
                int sz = (j < N_) ? 16 : 0;
                cp16(smem_u32(&s_dyn[buf*KT_W + row*36 + seg*4]), Kp + (size_t)(sz ? j : 0) * D_ + seg*8, sz);
                cp16(smem_u32(&s_dyn[V1_OFF + buf*KT_W + row*36 + seg*4]), V1g + (size_t)row * 512 + jb + seg*8, 16);
                cp16(smem_u32(&s_dyn[V2_OFF + buf*KT_W + row*36 + seg*4]), V2g + (size_t)row * 512 + jb + seg*8, 16);
            }
            CP_COMMIT();
            CP_WAIT(1);
        } else {
            CP_WAIT(0);
        }
        __syncthreads();

        const uint32_t* Kt = s_dyn + (t & 1) * KT_W;
        const uint32_t* V1 = s_dyn + V1_OFF + (t & 1) * KT_W;
        const uint32_t* V2 = s_dyn + V2_OFF + (t & 1) * KT_W;

        float sacc[8][4];
        #pragma unroll
        for (int nt = 0; nt < 8; nt++)
            #pragma unroll
            for (int e = 0; e < 4; e++) sacc[nt][e] = 0.f;
        #pragma unroll
        for (int ks = 0; ks < 4; ks++) {
            #pragma unroll
            for (int p = 0; p < 4; p++) {
                uint32_t tkt[4];
                ldm4(tkt, smem_u32(&Kt[(p*16 + b_row) * 36 + ks*8 + b_col]));
                mma_f16(sacc[2*p    ], qf[ks], tkt);
                mma_f16(sacc[2*p + 1], qf[ks], tkt + 2);
            }
        }
        if (j0 + 64 > N_) {
            #pragma unroll
            for (int nt = 0; nt < 8; nt++) {
                int cc = j0 + nt*8 + gc*2;
                if (cc     >= N_) { sacc[nt][0] = -1e30f; sacc[nt][2] = -1e30f; }
                if (cc + 1 >= N_) { sacc[nt][1] = -1e30f; sacc[nt][3] = -1e30f; }
            }
        }
        float tm0 = -1e30f, tm1 = -1e30f;
        #pragma unroll
        for (int nt = 0; nt < 8; nt++) {
            tm0 = fmaxf(tm0, fmaxf(sacc[nt][0], sacc[nt][1]));
            tm1 = fmaxf(tm1, fmaxf(sacc[nt][2], sacc[nt][3]));
        }
        tm0 = fmaxf(tm0, __shfl_xor_sync(0xffffffffu, tm0, 1));
        tm0 = fmaxf(tm0, __shfl_xor_sync(0xffffffffu, tm0, 2));
        tm1 = fmaxf(tm1, __shfl_xor_sync(0xffffffffu, tm1, 1));
        tm1 = fmaxf(tm1, __shfl_xor_sync(0xffffffffu, tm1, 2));
        float nm0 = fmaxf(rmax0, tm0), nm1 = fmaxf(rmax1, tm1);
        float sc0 = __expf(rmax0 - nm0), sc1 = __expf(rmax1 - nm1);
        rmax0 = nm0; rmax1 = nm1;
        float ps0 = 0.f, ps1 = 0.f;
        __half2* PQh = (__half2*)PQ;
        #pragma unroll
        for (int nt = 0; nt < 8; nt++) {
            float p00 = __expf(sacc[nt][0] - nm0);
            float p01 = __expf(sacc[nt][1] - nm0);
            float p10 = __expf(sacc[nt][2] - nm1);
            float p11 = __expf(sacc[nt][3] - nm1);
            ps0 += p00 + p01; ps1 += p10 + p11;
            PQh[(rbase + gr    ) * 36 + nt*4 + gc] = __floats2half2_rn(p00, p01);
            PQh[(rbase + gr + 8) * 36 + nt*4 + gc] = __floats2half2_rn(p10, p11);
            acc1[nt][0] *= sc0; acc1[nt][1] *= sc0; acc1[nt][2] *= sc1; acc1[nt][3] *= sc1;
            acc2[nt][0] *= sc0; acc2[nt][1] *= sc0; acc2[nt][2] *= sc1; acc2[nt][3] *= sc1;
        }
        ps0 += __shfl_xor_sync(0xffffffffu, ps0, 1);
        ps0 += __shfl_xor_sync(0xffffffffu, ps0, 2);
        ps1 += __shfl_xor_sync(0xffffffffu, ps1, 1);
        ps1 += __shfl_xor_sync(0xffffffffu, ps1, 2);
        rsum0 = rsum0 * sc0 + ps0;
        rsum1 = rsum1 * sc1 + ps1;
        __syncwarp();

        #pragma unroll
        for (int ks = 0; ks < 4; ks++) {
            uint32_t af[4];
            ldm4(af, smem_u32(&PQ[(rbase + a_row) * 36 + ks*8 + a_col]));
            #pragma unroll
            for (int p = 0; p < 4; p++) {
                uint32_t t1[4], t2[4];
                ldm4(t1, smem_u32(&V1[(p*16 + b_row) * 36 + ks*8 + b_col]));
                ldm4(t2, smem_u32(&V2[(p*16 + b_row) * 36 + ks*8 + b_col]));
                mma_f16(acc1[2*p    ], af, t1);
                mma_f16(acc1[2*p + 1], af, t1 + 2);
                mma_f16(acc2[2*p    ], af, t2);
                mma_f16(acc2[2*p + 1], af, t2 + 2);
            }
        }
        __syncthreads();
    }

    // ---- epilogue (fp16 out) ----
    float inv0 = 1.0f / rsum0, inv1 = 1.0f / rsum1;
    int gi0 = i0 + rbase + gr, gi1 = gi0 + 8;
    if (gi0 < N_) {
        float f = inv0 * g_upd[b * N_ + gi0];
        size_t base = (size_t)(b * N_ + gi0) * DIM_ + h * 64;
        #pragma unroll
        for (int nt = 0; nt < 8; nt++) {
            int d = nt*8 + gc*2;
            __half2 h1 = __floats2half2_rn(acc1[nt][0]*f, acc1[nt][1]*f);
            __half2 h2 = __floats2half2_rn(acc2[nt][0]*f, acc2[nt][1]*f);
            *(uint32_t*)&g_outh[base + d] = *(uint32_t*)&h1;
            *(uint32_t*)&g_mh  [base + d] = *(uint32_t*)&h2;
        }
    }
    if (gi1 < N_) {
        float f = inv1 * g_upd[b * N_ + gi1];
        size_t base = (size_t)(b * N_ + gi1) * DIM_ + h * 64;
        #pragma unroll
        for (int nt = 0; nt < 8; nt++) {
            int d = nt*8 + gc*2;
            __half2 h1 = __floats2half2_rn(acc1[nt][2]*f, acc1[nt][3]*f);
            __half2 h2 = __floats2half2_rn(acc2[nt][2]*f, acc2[nt][3]*f);
            *(uint32_t*)&g_outh[base + d] = *(uint32_t*)&h1;
            *(uint32_t*)&g_mh  [base + d] = *(uint32_t*)&h2;
        }
    }
}

// ---------------- per-(bh,w,d) max over sequence (fp16 input) ----------------
__global__ void reduce_max_k()
{
    int o = blockIdx.x * blockDim.x + threadIdx.x;
    if (o >= B_*H_*3*D_) return;
    int d = o & 63;
    int w = (o >> 6) % 3;
    int h = ((o >> 6) / 3) % H_;
    int b = (o >> 6) / 24;
    const __half* p = g_qkvmh + (size_t)b * N_ * QKV_ + w * DIM_ + h * 64 + d;
    float mx = -1e30f;
    for (int i = 0; i < N_; i++) mx = fmaxf(mx, __half2float(p[(size_t)i * QKV_]));
    g_max[((b * H_ + h) * 3 + w) * 64 + d] = mx;
}

// ---------------- modulate: fp16 in, fp16 q/k + transposed v/vm out ----------------
__global__ void __launch_bounds__(256) modulate_k()
{
    __shared__ __half sv1[64][72];
    __shared__ __half sv2[64][72];
    __shared__ float smax[192];
    const int bh = blockIdx.y, b = bh >> 3, h = bh & 7;
    const int i0 = blockIdx.x * 64;
    const int t = threadIdx.x;
    if (t < 192) smax[t] = g_max[bh * 192 + t];
    __syncthreads();

    const int r = t >> 2, d0 = (t & 3) * 16;
    const int i = i0 + r;

    union H16 { __half h[16]; uint4 u[2]; };
    H16 qo, ko;

    if (i < N_) {
        size_t base = (size_t)(b * N_ + i) * QKV_ + h * 64 + d0;
        H16 qi, ki, vi, qmi, kmi, vmi;
        qi.u[0]  = *(const uint4*)&g_qkvh [base];        qi.u[1]  = *(const uint4*)&g_qkvh [base + 8];
        ki.u[0]  = *(const uint4*)&g_qkvh [base + 512];  ki.u[1]  = *(const uint4*)&g_qkvh [base + 520];
        vi.u[0]  = *(const uint4*)&g_qkvh [base + 1024]; vi.u[1]  = *(const uint4*)&g_qkvh [base + 1032];
        qmi.u[0] = *(const uint4*)&g_qkvmh[base];        qmi.u[1] = *(const uint4*)&g_qkvmh[base + 8];
        kmi.u[0] = *(const uint4*)&g_qkvmh[base + 512];  kmi.u[1] = *(const uint4*)&g_qkvmh[base + 520];
        vmi.u[0] = *(const uint4*)&g_qkvmh[base + 1024]; vmi.u[1] = *(const uint4*)&g_qkvmh[base + 1032];
        #pragma unroll
        for (int j = 0; j < 16; j++) {
            int d = d0 + j;
            float qmn = __half2float(qmi.h[j]) / (1e-6f + smax[d]);
            float kmn = __half2float(kmi.h[j]) / (1e-6f + smax[64 + d]);
            float vmn = __half2float(vmi.h[j]) / (1e-6f + smax[128 + d]);
            qo.h[j] = __float2half_rn(__half2float(qi.h[j]) * qmn * SCALE_);
            ko.h[j] = __float2half_rn(__half2float(ki.h[j]) * kmn);
            sv1[r][d] = __float2half_rn(__half2float(vi.h[j]) * vmn);
            sv2[r][d] = __float2half_rn(vmn);
        }
        size_t ob = (size_t)bh * N_ * 64 + (size_t)i * 64 + d0;
        *(uint4*)&g_qh[ob] = qo.u[0];
        *(uint4*)&g_qh[ob + 8] = qo.u[1];
        *(uint4*)&g_kh[ob] = ko.u[0];
        *(uint4*)&g_kh[ob + 8] = ko.u[1];
    } else {
        #pragma unroll
        for (int e = 0; e < 16; e++) {
            sv1[r][d0 + e] = __float2half_rn(0.f);
            sv2[r][d0 + e] = __float2half_rn(0.f);
        }
    }
    __syncthreads();

    const int drow = t >> 2, is0 = (t & 3) * 16;
    H16 o1, o2;
    #pragma unroll
    for (int e = 0; e < 16; e++) {
        o1.h[e] = sv1[is0 + e][drow];
        o2.h[e] = sv2[is0 + e][drow];
    }
    size_t ob = (size_t)bh * 64 * 512 + (size_t)drow * 512 + i0 + is0;
    *(uint4*)&g_vvT[ob] = o1.u[0];
    *(uint4*)&g_vvT[ob + 8] = o1.u[1];
    *(uint4*)&g_vmT[ob] = o2.u[0];
    *(uint4*)&g_vmT[ob + 8] = o2.u[1];
}

// ---------------- overlap blending (fp16 in/out) ----------------
__global__ void blend_k()
{
    int idx4 = blockIdx.x * blockDim.x + threadIdx.x;
    if (idx4 >= SZ_BND / 4) return;
    size_t idx = (size_t)idx4 * 4;
    int c = idx % DIM_;
    int i = (idx / DIM_) % N_;
    int b = idx / (DIM_ * (size_t)N_);
    float4 o  = ld_h4(&g_outh[idx]);
    float4 mv = ld_h4(&g_mh[idx]);

    if (i >= 1 && i <= NHW_) {
        int p = i - 1, y = p >> 4, x = p & 15;
        float inv = 0.25f * (1.0f - g_upd[b * N_ + i]);
        float4 s1 = make_float4(0,0,0,0), s2 = make_float4(0,0,0,0);
        #pragma unroll
        for (int dy = -1; dy <= 0; dy++)
            #pragma unroll
            for (int dx = -1; dx <= 0; dx++) {
                int rr = y + dy, cc = x + dx;
                if (rr >= 0 && rr < 15 && cc >= 0 && cc < 15) {
                    size_t src = ((size_t)(b * N_ + TAIL0_ + rr * 15 + cc)) * DIM_ + c;
                    float4 a = ld_h4(&g_outh[src]);
                    float4 e = ld_h4(&g_mh[src]);
                    s1.x += a.x; s1.y += a.y; s1.z += a.z; s1.w += a.w;
                    s2.x += e.x; s2.y += e.y; s2.z += e.z; s2.w += e.w;
                }
            }
        o.x += s1.x*inv; o.y += s1.y*inv; o.z += s1.z*inv; o.w += s1.w*inv;
        mv.x += s2.x*inv; mv.y += s2.y*inv; mv.z += s2.z*inv; mv.w += s2.w*inv;
    } else if (i >= TAIL0_) {
        int p = i - TAIL0_, rr = p / 15, cc = p % 15;
        float inv = 0.25f * (1.0f - g_upd[b * N_ + i]);
        float4 s1 = make_float4(0,0,0,0), s2 = make_float4(0,0,0,0);
        #pragma unroll
        for (int dy = 0; dy <= 1; dy++)
            #pragma unroll
            for (int dx = 0; dx <= 1; dx++) {
                size_t src = ((size_t)(b * N_ + 1 + (rr + dy) * 16 + (cc + dx))) * DIM_ + c;
                float4 a = ld_h4(&g_outh[src]);
                float4 e = ld_h4(&g_mh[src]);
                s1.x += a.x; s1.y += a.y; s1.z += a.z; s1.w += a.w;
                s2.x += e.x; s2.y += e.y; s2.z += e.z; s2.w += e.w;
            }
        o.x += s1.x*inv; o.y += s1.y*inv; o.z += s1.z*inv; o.w += s1.w*inv;
        mv.x += s2.x*inv; mv.y += s2.y*inv; mv.z += s2.z*inv; mv.w += s2.w*inv;
    }
    __half2 ol = __floats2half2_rn(o.x, o.y),  oh = __floats2half2_rn(o.z, o.w);
    __half2 ml = __floats2half2_rn(mv.x, mv.y), mh = __floats2half2_rn(mv.z, mv.w);
    uint2 ou, mu;
    ou.x = *(uint32_t*)&ol; ou.y = *(uint32_t*)&oh;
    mu.x = *(uint32_t*)&ml; mu.y = *(uint32_t*)&mh;
    *(uint2*)&g_o2h[idx] = ou;
    *(uint2*)&g_m2h[idx] = mu;
}

// ---------------- channel means (fp16 input) ----------------
__global__ void mm_k()
{
    int row = blockIdx.x * (blockDim.x >> 5) + (threadIdx.x >> 5);
    if (row >= B_ * (N_ - 1)) return;
    int b = row / (N_ - 1), j = row % (N_ - 1);
    int ln = threadIdx.x & 31;
    const __half2* p = (const __half2*)(g_m2h + (size_t)(b * N_ + j + 1) * DIM_);
    float s = 0.f;
    #pragma unroll
    for (int e = 0; e < 8; e++) {
        float2 v = __half22float2(p[ln + e * 32]);
        s += v.x + v.y;
    }
    #pragma unroll
    for (int o = 16; o > 0; o >>= 1) s += __shfl_xor_sync(0xffffffffu, s, o);
    if (ln == 0) g_mm[row] = s * (1.0f / DIM_);
}

// ---------------- inter ----------------
__global__ void inter_k(float* __restrict__ outp)
{
    int idx = blockIdx.x * blockDim.x + threadIdx.x;
    if (idx >= B_ * 256 * 256) return;
    int x = idx & 255, y = (idx >> 8) & 255, b = idx >> 16;
    float v = g_mm[b * (N_ - 1) + (y >> 4) * 16 + (x >> 4)];
    if (y >= 8 && y < 248 && x >= 8 && x < 248) {
        float sh = g_mm[b * (N_ - 1) + 256 + ((y - 8) >> 4) * 15 + ((x - 8) >> 4)];
        v = 0.5f * (v + sh);
    }
    outp[idx] = v;
}

// ---------------- launch ----------------
extern "C" void kernel_launch(void* const* d_in, const int* in_sizes, int n_in,
                              void* d_out, int out_size)
{
    const float* x    = (const float*)d_in[0];
    const float* mask = (const float*)d_in[1];
    const float* Wqkv = (const float*)d_in[2];
    const float* Wout = (const float*)d_in[3];
    const float* bout = (const float*)d_in[4];
    float* out = (float*)d_out;

    __half *p_xh, *p_wqh, *p_wqah, *p_woh, *p_woah, *p_o2h, *p_m2h, *p_qkvh, *p_qkvmh, *p_mkh;
    cudaGetSymbolAddress((void**)&p_xh,    g_xh);
    cudaGetSymbolAddress((void**)&p_mkh,   g_mkh);
    cudaGetSymbolAddress((void**)&p_wqh,   g_wqh);
    cudaGetSymbolAddress((void**)&p_wqah,  g_wqah);
    cudaGetSymbolAddress((void**)&p_woh,   g_woh);
    cudaGetSymbolAddress((void**)&p_woah,  g_woah);
    cudaGetSymbolAddress((void**)&p_o2h,   g_o2h);
    cudaGetSymbolAddress((void**)&p_m2h,   g_m2h);
    cudaGetSymbolAddress((void**)&p_qkvh,  g_qkvh);
    cudaGetSymbolAddress((void**)&p_qkvmh, g_qkvmh);

    const int gemm_smem = 4 * GBUF_W * 4;          // 73728 B
    cudaFuncSetAttribute(hgemm2<false,true >, cudaFuncAttributeMaxDynamicSharedMemorySize, gemm_smem);
    cudaFuncSetAttribute(hgemm2<true ,false>, cudaFuncAttributeMaxDynamicSharedMemorySize, gemm_smem);
    cudaFuncSetAttribute(flash_attn, cudaFuncAttributeMaxDynamicSharedMemorySize, FA_SMEM_WORDS * 4);

    // 0. fp16 copies + fused mask prep
    half_copy1<<<(SZ_BND/4 + 255)/256, 256>>>((const float4*)x, (uint2*)p_xh, SZ_BND/4);
    mask_prep<<<(BN_ + 7) / 8, 256>>>(mask);
    half_copy2<<<(QKV_*DIM_/4 + 255)/256, 256>>>((const float4*)Wqkv, (uint2*)p_wqh, (uint2*)p_wqah, QKV_*DIM_/4);
    half_copy2<<<(DIM_*DIM_/4 + 255)/256, 256>>>((const float4*)Wout, (uint2*)p_woh, (uint2*)p_woah, DIM_*DIM_/4);

    // 1. qkv projections (both tensors in one z-batched launch, fp16 out)
    hgemm2<false,true><<<dim3(QKV_/128, BN_/128, 2), 256, gemm_smem>>>(
        p_xh, p_mkh, p_wqh, p_wqah, nullptr, p_qkvh, p_qkvmh, DIM_, DIM_, DIM_, QKV_);
    // 2. maxima
    reduce_max_k<<<(B_*H_*3*D_ + 255) / 256, 256>>>();
    // 3. modulate
    modulate_k<<<dim3(8, BH_), 256>>>();
    // 4-6. fused attention
    flash_attn<<<dim3(4, BH_), 256, FA_SMEM_WORDS * 4>>>();
    // 7. blending
    blend_k<<<(SZ_BND/4 + 255)/256, 256>>>();
    // 8. channel means
    mm_k<<<(B_ * (N_ - 1) + 7) / 8, 256>>>();
    // 9. inter
    inter_k<<<(B_ * 65536 + 255) / 256, 256>>>(out + 2 * (size_t)SZ_BND);
    // 10. final projections (z-batched, f32 out into d_out)
    hgemm2<true,false><<<dim3(DIM_/128, BN_/128, 2), 256, gemm_smem>>>(
        p_o2h, p_m2h, p_woh, p_woah, bout, out, out + (size_t)SZ_BND, DIM_, DIM_, DIM_, DIM_);
}